// round 13
// baseline (speedup 1.0000x reference)
#include <cuda_runtime.h>
#include <cuda_bf16.h>
#include <math.h>
#include <cstdint>
#include <cstddef>

// ---------------- problem constants ----------------
#define BB       2
#define IMG      512
#define PS       16
#define HP       32
#define NTOK     1024
#define CDIM     768
#define NHEADS   12
#define HEADD    64
#define NPTS     4
#define SCALE_F  0.125f
#define EPS_F    1e-6f
#define MROWS    (BB*NTOK)   // 2048

typedef __nv_bfloat16 bf16;

// ---------------- device scratch ----------------
__device__ float g_x   [MROWS*CDIM];
__device__ float g_offs[MROWS*96];

__device__ bf16 g_hh  [MROWS*CDIM],      g_hl  [MROWS*CDIM];
__device__ bf16 g_colh[MROWS*CDIM],      g_coll[MROWS*CDIM];
__device__ bf16 g_qkvh[MROWS*3*CDIM],    g_qkvl[MROWS*3*CDIM];
__device__ bf16 g_aoh [MROWS*CDIM],      g_aol [MROWS*CDIM];
__device__ bf16 g_mlph[MROWS*4*CDIM],    g_mlpl[MROWS*4*CDIM];

// weight bf16 hi/lo (converted each launch)
__device__ bf16 g_pwh[CDIM*CDIM],        g_pwl[CDIM*CDIM];
__device__ bf16 g_qwh[6*3*CDIM*CDIM],    g_qwl[6*3*CDIM*CDIM];
__device__ bf16 g_owh[6*96*CDIM],        g_owl[6*96*CDIM];
__device__ bf16 g_jwh[6*CDIM*CDIM],      g_jwl[6*CDIM*CDIM];
__device__ bf16 g_f1h[6*4*CDIM*CDIM],    g_f1l[6*4*CDIM*CDIM];
__device__ bf16 g_f2h[6*4*CDIM*CDIM],    g_f2l[6*4*CDIM*CDIM];

// ---------------- helpers ----------------
__device__ __forceinline__ float gelu_f(float v) {
    return 0.5f * v * (1.0f + erff(v * 0.7071067811865476f));
}
__device__ __forceinline__ void split_pair(float v, bf16& hi, bf16& lo) {
    hi = __float2bfloat16(v);
    lo = __float2bfloat16(v - __bfloat162float(hi));
}
__device__ __forceinline__ float2 unpack_pair(uint32_t h2, uint32_t l2) {
    __nv_bfloat162 th = *reinterpret_cast<__nv_bfloat162*>(&h2);
    __nv_bfloat162 tl = *reinterpret_cast<__nv_bfloat162*>(&l2);
    return make_float2(__bfloat162float(th.x) + __bfloat162float(tl.x),
                       __bfloat162float(th.y) + __bfloat162float(tl.y));
}
__device__ __forceinline__ uint32_t smem_u32(const void* p) {
    return (uint32_t)__cvta_generic_to_shared(p);
}
__device__ __forceinline__ void cp_async16(uint32_t dst, const void* src, bool pred) {
    int sz = pred ? 16 : 0;
    asm volatile("cp.async.cg.shared.global [%0], [%1], 16, %2;\n"
                 :: "r"(dst), "l"(src), "r"(sz));
}

#define LDSM4(r0, r1, r2, r3, addr) \
    asm volatile("ldmatrix.sync.aligned.m8n8.x4.shared.b16 {%0,%1,%2,%3}, [%4];" \
                 : "=r"(r0), "=r"(r1), "=r"(r2), "=r"(r3) : "r"(addr))

#define LDSM4T(r0, r1, r2, r3, addr) \
    asm volatile("ldmatrix.sync.aligned.m8n8.x4.trans.shared.b16 {%0,%1,%2,%3}, [%4];" \
                 : "=r"(r0), "=r"(r1), "=r"(r2), "=r"(r3) : "r"(addr))

#define MMA16816(c4, a0, a1, a2, a3, b0, b1) \
    asm volatile( \
        "mma.sync.aligned.m16n8k16.row.col.f32.bf16.bf16.f32 " \
        "{%0,%1,%2,%3}, {%4,%5,%6,%7}, {%8,%9}, {%0,%1,%2,%3};\n" \
        : "+f"((c4)[0]), "+f"((c4)[1]), "+f"((c4)[2]), "+f"((c4)[3]) \
        : "r"(a0), "r"(a1), "r"(a2), "r"(a3), "r"(b0), "r"(b1))

// =====================================================================
// bf16 hi/lo 3-product HMMA GEMM.
// Template MTW: m16 tiles per warp (4 -> 128 rows, 2 -> 64 rows).
// Template KSLAB: 32-k slabs per pipeline stage (BK = 32*KSLAB).
// 2-stage cp.async pipeline; ldmatrix.x4 fragment loads.
// epi: 0 bias, 1 gelu(bias), 2 residual (+= Cf). M%TILE_M==0, K%(32*KSLAB)==0.
// =====================================================================
extern __shared__ __align__(16) char smem_raw[];

template<int MTW, int KSLAB>
__global__ __launch_bounds__(256, 4 / MTW)
void mma_gemm_kernel(const bf16* __restrict__ Ah_g, const bf16* __restrict__ Al_g,
                     const bf16* __restrict__ Bh_g, const bf16* __restrict__ Bl_g,
                     float* Cf, bf16* Chi, bf16* Clo,
                     const float* __restrict__ bias,
                     int M, int N, int K, int lda, int ldb, int ldc,
                     long sAb, long sAh2, long sBb, long sBh2, long sCb, long sCh2,
                     int nh, int epi)
{
    constexpr int TILE_M  = MTW * 32;
    constexpr int A_BYTES = TILE_M * 80;
    constexpr int OFF_BH  = 2 * A_BYTES;
    constexpr int B_BYTES = 128 * 80;
    constexpr int SLAB    = 2 * A_BYTES + 2 * B_BYTES;
    constexpr int STAGE   = KSLAB * SLAB;
    constexpr int ACH     = TILE_M * 4;
    constexpr int TOT_CH  = 2 * ACH + 1024;
    constexpr int NIT     = TOT_CH / 256;

    int z  = blockIdx.z;
    int bb = z / nh, hh = z % nh;
    long aoff = (long)bb * sAb + (long)hh * sAh2;
    long boff = (long)bb * sBb + (long)hh * sBh2;
    long coff = (long)bb * sCb + (long)hh * sCh2;
    Ah_g += aoff; Al_g += aoff; Bh_g += boff; Bl_g += boff;
    if (Cf)  Cf  += coff;
    if (Chi) { Chi += coff; Clo += coff; }

    const int m0 = blockIdx.y * TILE_M;
    const int n0 = blockIdx.x * 128;

    const int tid  = threadIdx.x;
    const int warp = tid >> 5;
    const int lane = tid & 31;
    const int grp  = lane >> 2;
    const int tig  = lane & 3;
    const int mbase = (warp >> 2) * (MTW * 16);
    const int nbase = (warp & 3) * 32;

    const uint32_t dynbase = smem_u32(smem_raw);

    float acc[MTW][4][4];
    #pragma unroll
    for (int i = 0; i < MTW; i++)
        #pragma unroll
        for (int j = 0; j < 4; j++)
            #pragma unroll
            for (int r = 0; r < 4; r++) acc[i][j][r] = 0.f;

    const int KT = K / (32 * KSLAB);

    auto load_stage = [&](int s, int kt) {
        #pragma unroll
        for (int sl = 0; sl < KSLAB; sl++) {
            const int k0 = (kt * KSLAB + sl) << 5;
            const uint32_t sb = dynbase + s * STAGE + sl * SLAB;
            #pragma unroll
            for (int i = 0; i < NIT; i++) {
                int idx = tid + i * 256;
                if (idx < 2 * ACH) {
                    int arr = idx / ACH;
                    int rem = idx - arr * ACH;
                    int row = rem >> 2;
                    int c16 = rem & 3;
                    uint32_t dst = sb + arr * A_BYTES + row * 80 + c16 * 16;
                    const bf16* src = (arr ? Al_g : Ah_g)
                                    + (long)(m0 + row) * lda + k0 + c16 * 8;
                    cp_async16(dst, src, true);
                } else {
                    int idxb = idx - 2 * ACH;
                    int arr = idxb >> 9;
                    int rem = idxb & 511;
                    int row = rem >> 2;
                    int c16 = rem & 3;
                    uint32_t dst = sb + OFF_BH + arr * B_BYTES + row * 80 + c16 * 16;
                    int nr = n0 + row;
                    bool p = nr < N;
                    const bf16* src = (arr ? Bl_g : Bh_g)
                                    + (long)(p ? nr : 0) * ldb + k0 + c16 * 8;
                    cp_async16(dst, src, p);
                }
            }
        }
        asm volatile("cp.async.commit_group;\n");
    };

    load_stage(0, 0);

    const int a_row = mbase + (lane & 15);
    const int a_kof = (lane >> 4) << 3;
    const int b_row = nbase + ((lane >> 4) << 3) + (lane & 7);
    const int b_kof = ((lane >> 3) & 1) << 3;

    for (int kt = 0; kt < KT; kt++) {
        const int cur = kt & 1;
        if (kt + 1 < KT) {
            load_stage(cur ^ 1, kt + 1);
            asm volatile("cp.async.wait_group 1;\n");
        } else {
            asm volatile("cp.async.wait_group 0;\n");
        }
        __syncthreads();

        #pragma unroll
        for (int sl = 0; sl < KSLAB; sl++) {
            const uint32_t sA = dynbase + cur * STAGE + sl * SLAB;
            const uint32_t sB = sA + OFF_BH;

            #pragma unroll
            for (int kk = 0; kk < 2; kk++) {
                const int kc = kk * 16;
                uint32_t ah[MTW][4], al[MTW][4], bh[4][2], bl[4][2];

                const uint32_t aaddr = sA + (uint32_t)(a_row * 80 + (kc + a_kof) * 2);
                #pragma unroll
                for (int mt = 0; mt < MTW; mt++) {
                    LDSM4(ah[mt][0], ah[mt][1], ah[mt][2], ah[mt][3],
                          aaddr + mt * (16 * 80));
                    LDSM4(al[mt][0], al[mt][1], al[mt][2], al[mt][3],
                          aaddr + A_BYTES + mt * (16 * 80));
                }
                const uint32_t baddr = sB + (uint32_t)(b_row * 80 + (kc + b_kof) * 2);
                #pragma unroll
                for (int p = 0; p < 2; p++) {
                    LDSM4(bh[2*p][0], bh[2*p][1], bh[2*p+1][0], bh[2*p+1][1],
                          baddr + p * (16 * 80));
                    LDSM4(bl[2*p][0], bl[2*p][1], bl[2*p+1][0], bl[2*p+1][1],
                          baddr + B_BYTES + p * (16 * 80));
                }

                #pragma unroll
                for (int mt = 0; mt < MTW; mt++) {
                    #pragma unroll
                    for (int nt = 0; nt < 4; nt++) {
                        float* c4 = acc[mt][nt];
                        MMA16816(c4, ah[mt][0], ah[mt][1], ah[mt][2], ah[mt][3],
                                 bh[nt][0], bh[nt][1]);
                        MMA16816(c4, ah[mt][0], ah[mt][1], ah[mt][2], ah[mt][3],
                                 bl[nt][0], bl[nt][1]);
                        MMA16816(c4, al[mt][0], al[mt][1], al[mt][2], al[mt][3],
                                 bh[nt][0], bh[nt][1]);
                    }
                }
            }
        }
        __syncthreads();
    }

    // ---- epilogue ----
    #pragma unroll
    for (int mt = 0; mt < MTW; mt++) {
        #pragma unroll
        for (int nt = 0; nt < 4; nt++) {
            int nc = n0 + nbase + nt * 8 + 2 * tig;
            if (nc >= N) continue;
            float* c4 = acc[mt][nt];
            #pragma unroll
            for (int rr = 0; rr < 2; rr++) {
                int m = m0 + mbase + mt * 16 + grp + rr * 8;
                float v0 = c4[rr * 2], v1 = c4[rr * 2 + 1];
                if (bias) { v0 += bias[nc]; v1 += bias[nc + 1]; }
                if (epi == 1) { v0 = gelu_f(v0); v1 = gelu_f(v1); }
                long idx = (long)m * ldc + nc;
                if (epi == 2) {
                    float2 old = *(const float2*)&Cf[idx];
                    v0 += old.x; v1 += old.y;
                }
                if (Cf) *(float2*)&Cf[idx] = make_float2(v0, v1);
                if (Chi) {
                    bf16 h0, l0, h1, l1;
                    split_pair(v0, h0, l0);
                    split_pair(v1, h1, l1);
                    __nv_bfloat162 th = __halves2bfloat162(h0, h1);
                    __nv_bfloat162 tl = __halves2bfloat162(l0, l1);
                    *(uint32_t*)&Chi[idx] = *(uint32_t*)&th;
                    *(uint32_t*)&Clo[idx] = *(uint32_t*)&tl;
                }
            }
        }
    }
}

#define DYN_SMEM_M128K2 (2 * 2 * (2 * 128 * 80 + 2 * 128 * 80))  // 163840
#define DYN_SMEM_M64    (2 * (2 * 64 * 80 + 2 * 128 * 80))       // 61440

// =====================================================================
// Fused flash attention (Round-10 config: K-block 128, 1 CTA/SM).
// =====================================================================
#define FQ_ROWB   144
#define FA_QL     18432
#define FA_ST0    36864
#define FA_ARR    18432
#define FA_STAGE  (4*FA_ARR)
#define FA_SMEM   (FA_ST0 + 2*FA_STAGE)   // 184320

__global__ __launch_bounds__(256, 1)
void flash_attn_kernel(const bf16* __restrict__ qkvh, const bf16* __restrict__ qkvl,
                       bf16* __restrict__ oh, bf16* __restrict__ ol)
{
    const int bh = blockIdx.y;
    const int b  = bh / NHEADS;
    const int h  = bh % NHEADS;
    const int q0 = blockIdx.x * 128;

    const int tid  = threadIdx.x;
    const int warp = tid >> 5;
    const int lane = tid & 31;
    const int qbase = warp * 16;

    const uint32_t dyn = smem_u32(smem_raw);

    const bf16* qh_g = qkvh + ((long)(b * NTOK + q0)) * (3 * CDIM) + h * HEADD;
    const bf16* ql_g = qkvl + ((long)(b * NTOK + q0)) * (3 * CDIM) + h * HEADD;

    #pragma unroll
    for (int i = 0; i < 8; i++) {
        int idx = tid + i * 256;
        int arr = idx >> 10;
        int rem = idx & 1023;
        int row = rem >> 3;
        int c   = rem & 7;
        uint32_t dst = dyn + arr * FA_QL + row * FQ_ROWB + c * 16;
        const bf16* src = (arr ? ql_g : qh_g) + (long)row * (3 * CDIM) + c * 8;
        cp_async16(dst, src, true);
    }

    auto load_kv = [&](int s, int j) {
        const long keybase = (long)(b * NTOK + j * 128);
        const uint32_t sb = dyn + FA_ST0 + s * FA_STAGE;
        #pragma unroll
        for (int i = 0; i < 16; i++) {
            int idx = tid + i * 256;
            int arr = idx >> 10;
            int rem = idx & 1023;
            int row = rem >> 3;
            int c   = rem & 7;
            uint32_t dst = sb + arr * FA_ARR + row * FQ_ROWB + c * 16;
            const bf16* base = ((arr & 1) ? qkvl : qkvh);
            int sect = (arr < 2) ? CDIM : 2 * CDIM;
            const bf16* src = base + (keybase + row) * (3 * CDIM) + sect + h * HEADD + c * 8;
            cp_async16(dst, src, true);
        }
        asm volatile("cp.async.commit_group;\n");
    };

    load_kv(0, 0);

    float o[8][4];
    #pragma unroll
    for (int i = 0; i < 8; i++)
        #pragma unroll
        for (int r = 0; r < 4; r++) o[i][r] = 0.f;
    float m_i[2] = { -1e30f, -1e30f };
    float l_i[2] = { 0.f, 0.f };

    uint32_t qh_f[4][4], ql_f[4][4];
    const int a_row = qbase + (lane & 15);
    const int a_kof = (lane >> 4) << 3;
    const int b_row = ((lane >> 4) << 3) + (lane & 7);
    const int b_kof = ((lane >> 3) & 1) << 3;
    const int v_row = (((lane >> 3) & 1) << 3) + (lane & 7);
    const int v_dof = (lane >> 4) << 3;

    for (int j = 0; j < 8; j++) {
        const int cur = j & 1;
        if (j + 1 < 8) {
            load_kv(cur ^ 1, j + 1);
            asm volatile("cp.async.wait_group 1;\n");
        } else {
            asm volatile("cp.async.wait_group 0;\n");
        }
        __syncthreads();

        if (j == 0) {
            #pragma unroll
            for (int kk = 0; kk < 4; kk++) {
                uint32_t qaddr = dyn + (uint32_t)(a_row * FQ_ROWB + (kk * 16 + a_kof) * 2);
                LDSM4(qh_f[kk][0], qh_f[kk][1], qh_f[kk][2], qh_f[kk][3], qaddr);
                LDSM4(ql_f[kk][0], ql_f[kk][1], ql_f[kk][2], ql_f[kk][3], qaddr + FA_QL);
            }
        }

        const uint32_t kb = dyn + FA_ST0 + cur * FA_STAGE;
        const uint32_t vb = kb + 2 * FA_ARR;

        float s[16][4];
        #pragma unroll
        for (int i = 0; i < 16; i++)
            #pragma unroll
            for (int r = 0; r < 4; r++) s[i][r] = 0.f;

        #pragma unroll
        for (int np = 0; np < 8; np++) {
            #pragma unroll
            for (int kk = 0; kk < 4; kk++) {
                uint32_t kaddr = kb + (uint32_t)((np * 16 + b_row) * FQ_ROWB
                                                 + (kk * 16 + b_kof) * 2);
                uint32_t kh0, kh1, kh2, kh3, kl0, kl1, kl2, kl3;
                LDSM4(kh0, kh1, kh2, kh3, kaddr);
                LDSM4(kl0, kl1, kl2, kl3, kaddr + FA_ARR);
                float* c0 = s[2*np];
                float* c1 = s[2*np+1];
                MMA16816(c0, qh_f[kk][0], qh_f[kk][1], qh_f[kk][2], qh_f[kk][3], kh0, kh1);
                MMA16816(c0, qh_f[kk][0], qh_f[kk][1], qh_f[kk][2], qh_f[kk][3], kl0, kl1);
                MMA16816(c0, ql_f[kk][0], ql_f[kk][1], ql_f[kk][2], ql_f[kk][3], kh0, kh1);
                MMA16816(c1, qh_f[kk][0], qh_f[kk][1], qh_f[kk][2], qh_f[kk][3], kh2, kh3);
                MMA16816(c1, qh_f[kk][0], qh_f[kk][1], qh_f[kk][2], qh_f[kk][3], kl2, kl3);
                MMA16816(c1, ql_f[kk][0], ql_f[kk][1], ql_f[kk][2], ql_f[kk][3], kh2, kh3);
            }
        }

        #pragma unroll
        for (int rr = 0; rr < 2; rr++) {
            float mx = -1e30f;
            #pragma unroll
            for (int nt = 0; nt < 16; nt++)
                mx = fmaxf(mx, fmaxf(s[nt][rr*2], s[nt][rr*2+1]));
            mx = fmaxf(mx, __shfl_xor_sync(~0u, mx, 1));
            mx = fmaxf(mx, __shfl_xor_sync(~0u, mx, 2));
            float m_new = fmaxf(m_i[rr], mx);
            float alpha = expf(SCALE_F * (m_i[rr] - m_new));
            m_i[rr] = m_new;
            l_i[rr] *= alpha;
            float psum = 0.f;
            #pragma unroll
            for (int nt = 0; nt < 16; nt++) {
                float p0 = expf(SCALE_F * (s[nt][rr*2]     - m_new));
                float p1 = expf(SCALE_F * (s[nt][rr*2 + 1] - m_new));
                s[nt][rr*2]     = p0;
                s[nt][rr*2 + 1] = p1;
                psum += p0 + p1;
            }
            l_i[rr] += psum;
            #pragma unroll
            for (int nt = 0; nt < 8; nt++) {
                o[nt][rr*2]     *= alpha;
                o[nt][rr*2 + 1] *= alpha;
            }
        }

        #pragma unroll
        for (int ks = 0; ks < 8; ks++) {
            uint32_t pah[4], pal[4];
            #pragma unroll
            for (int q = 0; q < 4; q++) {
                int nt = 2 * ks + (q >> 1);
                int base = (q & 1) * 2;
                bf16 h0, l0, h1, l1;
                split_pair(s[nt][base],     h0, l0);
                split_pair(s[nt][base + 1], h1, l1);
                __nv_bfloat162 th = __halves2bfloat162(h0, h1);
                __nv_bfloat162 tl = __halves2bfloat162(l0, l1);
                pah[q] = *(uint32_t*)&th;
                pal[q] = *(uint32_t*)&tl;
            }
            #pragma unroll
            for (int np = 0; np < 4; np++) {
                uint32_t vaddr = vb + (uint32_t)((ks * 16 + v_row) * FQ_ROWB
                                                 + (np * 16 + v_dof) * 2);
                uint32_t vh0, vh1, vh2, vh3, vl0, vl1, vl2, vl3;
                LDSM4T(vh0, vh1, vh2, vh3, vaddr);
                LDSM4T(vl0, vl1, vl2, vl3, vaddr + FA_ARR);
                float* c0 = o[2*np];
                float* c1 = o[2*np+1];
                MMA16816(c0, pah[0], pah[1], pah[2], pah[3], vh0, vh1);
                MMA16816(c0, pah[0], pah[1], pah[2], pah[3], vl0, vl1);
                MMA16816(c0, pal[0], pal[1], pal[2], pal[3], vh0, vh1);
                MMA16816(c1, pah[0], pah[1], pah[2], pah[3], vh2, vh3);
                MMA16816(c1, pah[0], pah[1], pah[2], pah[3], vl2, vl3);
                MMA16816(c1, pal[0], pal[1], pal[2], pal[3], vh2, vh3);
            }
        }
        __syncthreads();
    }

    float inv[2];
    #pragma unroll
    for (int rr = 0; rr < 2; rr++) {
        float l = l_i[rr];
        l += __shfl_xor_sync(~0u, l, 1);
        l += __shfl_xor_sync(~0u, l, 2);
        inv[rr] = 1.f / l;
    }

    const int r = lane >> 2;
    const int t = lane & 3;
    #pragma unroll
    for (int nt = 0; nt < 8; nt++) {
        #pragma unroll
        for (int rr = 0; rr < 2; rr++) {
            int qr = q0 + qbase + r + rr * 8;
            float v0 = o[nt][rr*2]     * inv[rr];
            float v1 = o[nt][rr*2 + 1] * inv[rr];
            bf16 h0, l0, h1, l1;
            split_pair(v0, h0, l0);
            split_pair(v1, h1, l1);
            __nv_bfloat162 th = __halves2bfloat162(h0, h1);
            __nv_bfloat162 tl = __halves2bfloat162(l0, l1);
            long idx = ((long)(b * NTOK + qr)) * CDIM + h * HEADD + nt * 8 + 2 * t;
            *(uint32_t*)&oh[idx] = *(uint32_t*)&th;
            *(uint32_t*)&ol[idx] = *(uint32_t*)&tl;
        }
    }
}

// =====================================================================
// f32 -> bf16 hi/lo pair conversion, float4-vectorized
// =====================================================================
__global__ void cvt_pair4_kernel(const float* __restrict__ in,
                                 bf16* __restrict__ hi, bf16* __restrict__ lo, long n4)
{
    long i = (long)blockIdx.x * blockDim.x + threadIdx.x;
    if (i >= n4) return;
    float4 v = ((const float4*)in)[i];
    bf16 h[4], l[4];
    split_pair(v.x, h[0], l[0]); split_pair(v.y, h[1], l[1]);
    split_pair(v.z, h[2], l[2]); split_pair(v.w, h[3], l[3]);
    __nv_bfloat162 h01 = __halves2bfloat162(h[0], h[1]);
    __nv_bfloat162 h23 = __halves2bfloat162(h[2], h[3]);
    __nv_bfloat162 l01 = __halves2bfloat162(l[0], l[1]);
    __nv_bfloat162 l23 = __halves2bfloat162(l[2], l[3]);
    ((uint2*)hi)[i] = make_uint2(*(uint32_t*)&h01, *(uint32_t*)&h23);
    ((uint2*)lo)[i] = make_uint2(*(uint32_t*)&l01, *(uint32_t*)&l23);
}

// =====================================================================
// im2col producing bf16 pairs
// =====================================================================
__global__ void im2col_kernel(const float* __restrict__ x,
                              bf16* __restrict__ ch, bf16* __restrict__ cl)
{
    long idx = (long)blockIdx.x * blockDim.x + threadIdx.x;
    if (idx >= (long)MROWS * CDIM) return;
    int k = (int)(idx % CDIM);
    int m = (int)(idx / CDIM);
    int b  = m >> 10;
    int n  = m & 1023;
    int hp = n >> 5, wp = n & 31;
    int ci = k >> 8;
    int r  = k & 255;
    int ky = r >> 4, kx = r & 15;
    long src = (((long)(b * 3 + ci) * IMG) + hp * PS + ky) * IMG + wp * PS + kx;
    bf16 h, l; split_pair(x[src], h, l);
    ch[idx] = h; cl[idx] = l;
}

// =====================================================================
// LayerNorm producing bf16 pairs
// =====================================================================
__global__ void layernorm_kernel(const float* __restrict__ in,
                                 bf16* __restrict__ oh, bf16* __restrict__ ol,
                                 const float* __restrict__ s, const float* __restrict__ b)
{
    __shared__ float red[8];
    const long row = blockIdx.x;
    const float* r = in + row * CDIM;
    int tid = threadIdx.x, lane = tid & 31, w = tid >> 5;

    float v[3];
    float sum = 0.f;
    #pragma unroll
    for (int j = 0; j < 3; j++) { v[j] = r[tid + j * 256]; sum += v[j]; }
    #pragma unroll
    for (int off = 16; off; off >>= 1) sum += __shfl_xor_sync(~0u, sum, off);
    if (lane == 0) red[w] = sum;
    __syncthreads();
    if (w == 0) {
        float t = (lane < 8) ? red[lane] : 0.f;
        #pragma unroll
        for (int off = 4; off; off >>= 1) t += __shfl_xor_sync(~0u, t, off);
        if (lane == 0) red[0] = t;
    }
    __syncthreads();
    float mu = red[0] * (1.f / CDIM);
    __syncthreads();

    float sq = 0.f;
    #pragma unroll
    for (int j = 0; j < 3; j++) { float d = v[j] - mu; sq += d * d; }
    #pragma unroll
    for (int off = 16; off; off >>= 1) sq += __shfl_xor_sync(~0u, sq, off);
    if (lane == 0) red[w] = sq;
    __syncthreads();
    if (w == 0) {
        float t = (lane < 8) ? red[lane] : 0.f;
        #pragma unroll
        for (int off = 4; off; off >>= 1) t += __shfl_xor_sync(~0u, t, off);
        if (lane == 0) red[0] = t;
    }
    __syncthreads();
    float rstd = rsqrtf(red[0] * (1.f / CDIM) + EPS_F);

    #pragma unroll
    for (int j = 0; j < 3; j++) {
        int c = tid + j * 256;
        float o = (v[j] - mu) * rstd * s[c] + b[c];
        bf16 h, l; split_pair(o, h, l);
        oh[row * CDIM + c] = h; ol[row * CDIM + c] = l;
    }
}

// =====================================================================
// Fused deformable attention: one warp per (b, h, n).
// =====================================================================
__global__ void deform_attn_kernel(const bf16* __restrict__ qkvh,
                                   const bf16* __restrict__ qkvl,
                                   const float* __restrict__ offs,
                                   bf16* __restrict__ oh, bf16* __restrict__ ol)
{
    int gwarp = (blockIdx.x * blockDim.x + threadIdx.x) >> 5;
    int lane  = threadIdx.x & 31;
    if (gwarp >= BB * NHEADS * NTOK) return;
    int n  = gwarp & (NTOK - 1);
    int bh = gwarp >> 10;
    int h  = bh % NHEADS;
    int b  = bh / NHEADS;
    int hp = n >> 5, wp = n & 31;

    const long rowoff = ((long)(b * NTOK + n)) * (3 * CDIM) + h * HEADD + 2 * lane;
    float2 q = unpack_pair(*(const uint32_t*)&qkvh[rowoff],
                           *(const uint32_t*)&qkvl[rowoff]);

    const float* offrow = offs + ((long)(b * NTOK + n)) * 96 + h * NPTS * 2;

    float att[NPTS], sv0[NPTS], sv1[NPTS];

    #pragma unroll
    for (int p = 0; p < NPTS; p++) {
        float ox = offrow[p * 2 + 0];
        float oy = offrow[p * 2 + 1];
        float gx = (wp + 0.5f) * (1.f / HP) + ox * (1.f / HP);
        float gy = (hp + 0.5f) * (1.f / HP) + oy * (1.f / HP);
        float px = (2.f * gx) * (HP * 0.5f) - 0.5f;
        float py = (2.f * gy) * (HP * 0.5f) - 0.5f;
        float x0f = floorf(px), y0f = floorf(py);
        float wx = px - x0f, wy = py - y0f;
        int x0 = (int)x0f, y0 = (int)y0f;
        float cw[4] = { (1.f - wx) * (1.f - wy), wx * (1.f - wy),
                        (1.f - wx) * wy,         wx * wy };

        float k0 = 0.f, k1 = 0.f, v0 = 0.f, v1 = 0.f;
        #pragma unroll
        for (int c = 0; c < 4; c++) {
            int yi = y0 + (c >> 1);
            int xi = x0 + (c & 1);
            if (yi >= 0 && yi < HP && xi >= 0 && xi < HP) {
                long base = ((long)(b * NTOK + yi * HP + xi)) * (3 * CDIM)
                          + CDIM + h * HEADD + 2 * lane;
                float2 kv = unpack_pair(*(const uint32_t*)&qkvh[base],
                                        *(const uint32_t*)&qkvl[base]);
                float2 vv = unpack_pair(*(const uint32_t*)&qkvh[base + CDIM],
                                        *(const uint32_t*)&qkvl[base + CDIM]);
                float wc = cw[c];
                k0 += wc * kv.x;  k1 += wc * kv.y;
                v0 += wc * vv.x;  v1 += wc * vv.y;
            }
        }
        sv0[p] = v0; sv1[p] = v1;
        float d = q.x * k0 + q.y * k1;
        #pragma unroll
        for (int off = 16; off; off >>= 1) d += __shfl_xor_sync(~0u, d, off);
        att[p] = d * SCALE_F;
    }

    float mx = fmaxf(fmaxf(att[0], att[1]), fmaxf(att[2], att[3]));
    float e[NPTS], sum = 0.f;
    #pragma unroll
    for (int p = 0; p < NPTS; p++) { e[p] = expf(att[p] - mx); sum += e[p]; }
    float inv = 1.f / sum;

    float o0 = 0.f, o1 = 0.f;
    #pragma unroll
    for (int p = 0; p < NPTS; p++) {
        float a = e[p] * inv;
        o0 += a * sv0[p];
        o1 += a * sv1[p];
    }
    long base = ((long)(b * NTOK + n)) * CDIM + h * HEADD + 2 * lane;
    bf16 h0, l0, h1, l1;
    split_pair(o0, h0, l0);
    split_pair(o1, h1, l1);
    __nv_bfloat162 th = __halves2bfloat162(h0, h1);
    __nv_bfloat162 tl = __halves2bfloat162(l0, l1);
    *(uint32_t*)&oh[base] = *(uint32_t*)&th;
    *(uint32_t*)&ol[base] = *(uint32_t*)&tl;
}

// =====================================================================
// Output transpose: (B,N,C) -> (B,C,Hp,Wp)
// =====================================================================
__global__ void out_transpose_kernel(const float* __restrict__ x, float* __restrict__ out)
{
    long idx = (long)blockIdx.x * blockDim.x + threadIdx.x;
    if (idx >= (long)MROWS * CDIM) return;
    int n = (int)(idx % NTOK);
    int c = (int)((idx / NTOK) % CDIM);
    int b = (int)(idx / ((long)NTOK * CDIM));
    out[idx] = x[((long)(b * NTOK + n)) * CDIM + c];
}

// =====================================================================
// Host launcher
// =====================================================================
extern "C" void kernel_launch(void* const* d_in, const int* in_sizes, int n_in,
                              void* d_out, int out_size)
{
    const float* x       = (const float*)d_in[0];
    const float* patch_w = (const float*)d_in[1];
    const float* patch_b = (const float*)d_in[2];
    const float* ln1_s   = (const float*)d_in[3];
    const float* ln1_b   = (const float*)d_in[4];
    const float* qkv_w   = (const float*)d_in[5];
    const float* offs_w  = (const float*)d_in[6];
    const float* offs_b  = (const float*)d_in[7];
    const float* proj_w  = (const float*)d_in[8];
    const float* proj_b  = (const float*)d_in[9];
    const float* ln2_s   = (const float*)d_in[10];
    const float* ln2_b   = (const float*)d_in[11];
    const float* fc1_w   = (const float*)d_in[12];
    const float* fc1_b   = (const float*)d_in[13];
    const float* fc2_w   = (const float*)d_in[14];
    const float* fc2_b   = (const float*)d_in[15];

    cudaFuncSetAttribute(mma_gemm_kernel<4,2>,
                         cudaFuncAttributeMaxDynamicSharedMemorySize, DYN_SMEM_M128K2);
    cudaFuncSetAttribute(mma_gemm_kernel<2,1>,
                         cudaFuncAttributeMaxDynamicSharedMemorySize, DYN_SMEM_M64);
    cudaFuncSetAttribute(flash_attn_kernel,
                         cudaFuncAttributeMaxDynamicSharedMemorySize, FA_SMEM);

    float *gx, *goffs;
    bf16 *ghh,*ghl,*gcolh,*gcoll,*gqkvh,*gqkvl,*gaoh,*gaol;
    bf16 *gmlph,*gmlpl;
    bf16 *pwh,*pwl,*qwh,*qwl,*owh,*owl,*jwh,*jwl,*f1h,*f1l,*f2h,*f2l;
    cudaGetSymbolAddress((void**)&gx,    g_x);
    cudaGetSymbolAddress((void**)&goffs, g_offs);
    cudaGetSymbolAddress((void**)&ghh,   g_hh);   cudaGetSymbolAddress((void**)&ghl,   g_hl);
    cudaGetSymbolAddress((void**)&gcolh, g_colh); cudaGetSymbolAddress((void**)&gcoll, g_coll);
    cudaGetSymbolAddress((void**)&gqkvh, g_qkvh); cudaGetSymbolAddress((void**)&gqkvl, g_qkvl);
    cudaGetSymbolAddress((void**)&gaoh,  g_aoh);  cudaGetSymbolAddress((void**)&gaol,  g_aol);
    cudaGetSymbolAddress((void**)&gmlph, g_mlph); cudaGetSymbolAddress((void**)&gmlpl, g_mlpl);
    cudaGetSymbolAddress((void**)&pwh, g_pwh); cudaGetSymbolAddress((void**)&pwl, g_pwl);
    cudaGetSymbolAddress((void**)&qwh, g_qwh); cudaGetSymbolAddress((void**)&qwl, g_qwl);
    cudaGetSymbolAddress((void**)&owh, g_owh); cudaGetSymbolAddress((void**)&owl, g_owl);
    cudaGetSymbolAddress((void**)&jwh, g_jwh); cudaGetSymbolAddress((void**)&jwl, g_jwl);
    cudaGetSymbolAddress((void**)&f1h, g_f1h); cudaGetSymbolAddress((void**)&f1l, g_f1l);
    cudaGetSymbolAddress((void**)&f2h, g_f2h); cudaGetSymbolAddress((void**)&f2l, g_f2l);

    const int M = MROWS;

    // ---- weight conversion (vectorized) ----
    {
        long n1 = (long)CDIM * CDIM / 4;
        cvt_pair4_kernel<<<(int)((n1 + 255) / 256), 256>>>(patch_w, pwh, pwl, n1);
        long n2 = 6L * 3 * CDIM * CDIM / 4;
        cvt_pair4_kernel<<<(int)((n2 + 255) / 256), 256>>>(qkv_w, qwh, qwl, n2);
        long n3 = 6L * 96 * CDIM / 4;
        cvt_pair4_kernel<<<(int)((n3 + 255) / 256), 256>>>(offs_w, owh, owl, n3);
        long n4 = 6L * CDIM * CDIM / 4;
        cvt_pair4_kernel<<<(int)((n4 + 255) / 256), 256>>>(proj_w, jwh, jwl, n4);
        long n5 = 6L * 4 * CDIM * CDIM / 4;
        cvt_pair4_kernel<<<(int)((n5 + 255) / 256), 256>>>(fc1_w, f1h, f1l, n5);
        cvt_pair4_kernel<<<(int)((n5 + 255) / 256), 256>>>(fc2_w, f2h, f2l, n5);
    }

    // ---- patch embed (M64: 192 CTAs) ----
    im2col_kernel<<<(M * CDIM + 255) / 256, 256>>>(x, gcolh, gcoll);
    mma_gemm_kernel<2,1><<<dim3(6, M / 64, 1), 256, DYN_SMEM_M64>>>(
        gcolh, gcoll, pwh, pwl, gx, nullptr, nullptr, patch_b,
        M, CDIM, CDIM, CDIM, CDIM, CDIM,
        0, 0, 0, 0, 0, 0, 1, 0);

    for (int i = 0; i < 6; i++) {
        layernorm_kernel<<<M, 256>>>(gx, ghh, ghl, ln1_s + i * CDIM, ln1_b + i * CDIM);

        // QKV (M128 BK64: 288 CTAs)
        mma_gemm_kernel<4,2><<<dim3(18, M / 128, 1), 256, DYN_SMEM_M128K2>>>(
            ghh, ghl, qwh + (long)i * 2304 * CDIM, qwl + (long)i * 2304 * CDIM,
            nullptr, gqkvh, gqkvl, nullptr,
            M, 2304, CDIM, CDIM, CDIM, 2304,
            0, 0, 0, 0, 0, 0, 1, 0);

        bool sample = ((i + 1) % 3) != 0;
        if (sample) {
            // offsets (M64: 32 CTAs)
            mma_gemm_kernel<2,1><<<dim3(1, M / 64, 1), 256, DYN_SMEM_M64>>>(
                gqkvh, gqkvl, owh + (long)i * 96 * CDIM, owl + (long)i * 96 * CDIM,
                goffs, nullptr, nullptr, offs_b + i * 96,
                M, 96, CDIM, 3 * CDIM, CDIM, 96,
                0, 0, 0, 0, 0, 0, 1, 0);
            deform_attn_kernel<<<(BB * NHEADS * NTOK * 32) / 256, 256>>>(
                gqkvh, gqkvl, goffs, gaoh, gaol);
        } else {
            flash_attn_kernel<<<dim3(NTOK / 128, BB * NHEADS, 1), 256, FA_SMEM>>>(
                gqkvh, gqkvl, gaoh, gaol);
        }

        // proj + residual (M64: 192 CTAs)
        mma_gemm_kernel<2,1><<<dim3(6, M / 64, 1), 256, DYN_SMEM_M64>>>(
            gaoh, gaol, jwh + (long)i * CDIM * CDIM, jwl + (long)i * CDIM * CDIM,
            gx, nullptr, nullptr, proj_b + i * CDIM,
            M, CDIM, CDIM, CDIM, CDIM, CDIM,
            0, 0, 0, 0, 0, 0, 1, 2);

        layernorm_kernel<<<M, 256>>>(gx, ghh, ghl, ln2_s + i * CDIM, ln2_b + i * CDIM);

        // fc1 + gelu (M128 BK64: 384 CTAs)
        mma_gemm_kernel<4,2><<<dim3(24, M / 128, 1), 256, DYN_SMEM_M128K2>>>(
            ghh, ghl, f1h + (long)i * 3072 * CDIM, f1l + (long)i * 3072 * CDIM,
            nullptr, gmlph, gmlpl, fc1_b + i * 3072,
            M, 3072, CDIM, CDIM, CDIM, 3072,
            0, 0, 0, 0, 0, 0, 1, 1);
        // fc2 + residual (M64: 192 CTAs)
        mma_gemm_kernel<2,1><<<dim3(6, M / 64, 1), 256, DYN_SMEM_M64>>>(
            gmlph, gmlpl, f2h + (long)i * CDIM * 3072, f2l + (long)i * CDIM * 3072,
            gx, nullptr, nullptr, fc2_b + i * CDIM,
            M, CDIM, 3072, 3072, 3072, CDIM,
            0, 0, 0, 0, 0, 0, 1, 2);
    }

    out_transpose_kernel<<<(M * CDIM + 255) / 256, 256>>>(gx, (float*)d_out);
}

// round 14
// speedup vs baseline: 1.2831x; 1.2831x over previous
#include <cuda_runtime.h>
#include <cuda_bf16.h>
#include <math.h>
#include <cstdint>
#include <cstddef>

// ---------------- problem constants ----------------
#define BB       2
#define IMG      512
#define PS       16
#define HP       32
#define NTOK     1024
#define CDIM     768
#define NHEADS   12
#define HEADD    64
#define NPTS     4
#define SCALE_F  0.125f
#define EPS_F    1e-6f
#define MROWS    (BB*NTOK)   // 2048

typedef __nv_bfloat16 bf16;

// ---------------- device scratch ----------------
__device__ float g_x   [MROWS*CDIM];
__device__ float g_offs[MROWS*96];

__device__ bf16 g_hh  [MROWS*CDIM],      g_hl  [MROWS*CDIM];
__device__ bf16 g_colh[MROWS*CDIM],      g_coll[MROWS*CDIM];
__device__ bf16 g_qkvh[MROWS*3*CDIM],    g_qkvl[MROWS*3*CDIM];
__device__ bf16 g_aoh [MROWS*CDIM],      g_aol [MROWS*CDIM];
__device__ bf16 g_mlph[MROWS*4*CDIM],    g_mlpl[MROWS*4*CDIM];

// weight bf16 hi/lo (converted each launch)
__device__ bf16 g_pwh[CDIM*CDIM],        g_pwl[CDIM*CDIM];
__device__ bf16 g_qwh[6*3*CDIM*CDIM],    g_qwl[6*3*CDIM*CDIM];
__device__ bf16 g_owh[6*96*CDIM],        g_owl[6*96*CDIM];
__device__ bf16 g_jwh[6*CDIM*CDIM],      g_jwl[6*CDIM*CDIM];
__device__ bf16 g_f1h[6*4*CDIM*CDIM],    g_f1l[6*4*CDIM*CDIM];
__device__ bf16 g_f2h[6*4*CDIM*CDIM],    g_f2l[6*4*CDIM*CDIM];

// ---------------- helpers ----------------
__device__ __forceinline__ float gelu_f(float v) {
    return 0.5f * v * (1.0f + erff(v * 0.7071067811865476f));
}
__device__ __forceinline__ void split_pair(float v, bf16& hi, bf16& lo) {
    hi = __float2bfloat16(v);
    lo = __float2bfloat16(v - __bfloat162float(hi));
}
__device__ __forceinline__ float2 unpack_pair(uint32_t h2, uint32_t l2) {
    __nv_bfloat162 th = *reinterpret_cast<__nv_bfloat162*>(&h2);
    __nv_bfloat162 tl = *reinterpret_cast<__nv_bfloat162*>(&l2);
    return make_float2(__bfloat162float(th.x) + __bfloat162float(tl.x),
                       __bfloat162float(th.y) + __bfloat162float(tl.y));
}
__device__ __forceinline__ uint32_t smem_u32(const void* p) {
    return (uint32_t)__cvta_generic_to_shared(p);
}
__device__ __forceinline__ void cp_async16(uint32_t dst, const void* src, bool pred) {
    int sz = pred ? 16 : 0;
    asm volatile("cp.async.cg.shared.global [%0], [%1], 16, %2;\n"
                 :: "r"(dst), "l"(src), "r"(sz));
}

#define LDSM4(r0, r1, r2, r3, addr) \
    asm volatile("ldmatrix.sync.aligned.m8n8.x4.shared.b16 {%0,%1,%2,%3}, [%4];" \
                 : "=r"(r0), "=r"(r1), "=r"(r2), "=r"(r3) : "r"(addr))

#define LDSM4T(r0, r1, r2, r3, addr) \
    asm volatile("ldmatrix.sync.aligned.m8n8.x4.trans.shared.b16 {%0,%1,%2,%3}, [%4];" \
                 : "=r"(r0), "=r"(r1), "=r"(r2), "=r"(r3) : "r"(addr))

#define MMA16816(c4, a0, a1, a2, a3, b0, b1) \
    asm volatile( \
        "mma.sync.aligned.m16n8k16.row.col.f32.bf16.bf16.f32 " \
        "{%0,%1,%2,%3}, {%4,%5,%6,%7}, {%8,%9}, {%0,%1,%2,%3};\n" \
        : "+f"((c4)[0]), "+f"((c4)[1]), "+f"((c4)[2]), "+f"((c4)[3]) \
        : "r"(a0), "r"(a1), "r"(a2), "r"(a3), "r"(b0), "r"(b1))

// =====================================================================
// bf16 hi/lo 3-product HMMA GEMM (champion config: BK=32, 2-stage)
// =====================================================================
extern __shared__ __align__(16) char smem_raw[];

template<int MTW>
__global__ __launch_bounds__(256, 4 / MTW)
void mma_gemm_kernel(const bf16* __restrict__ Ah_g, const bf16* __restrict__ Al_g,
                     const bf16* __restrict__ Bh_g, const bf16* __restrict__ Bl_g,
                     float* Cf, bf16* Chi, bf16* Clo,
                     const float* __restrict__ bias,
                     int M, int N, int K, int lda, int ldb, int ldc,
                     long sAb, long sAh2, long sBb, long sBh2, long sCb, long sCh2,
                     int nh, int epi)
{
    constexpr int TILE_M  = MTW * 32;
    constexpr int A_BYTES = TILE_M * 80;
    constexpr int OFF_BH  = 2 * A_BYTES;
    constexpr int B_BYTES = 128 * 80;
    constexpr int STAGE   = 2 * A_BYTES + 2 * B_BYTES;
    constexpr int ACH     = TILE_M * 4;
    constexpr int TOT_CH  = 2 * ACH + 1024;
    constexpr int NIT     = TOT_CH / 256;

    int z  = blockIdx.z;
    int bb = z / nh, hh = z % nh;
    long aoff = (long)bb * sAb + (long)hh * sAh2;
    long boff = (long)bb * sBb + (long)hh * sBh2;
    long coff = (long)bb * sCb + (long)hh * sCh2;
    Ah_g += aoff; Al_g += aoff; Bh_g += boff; Bl_g += boff;
    if (Cf)  Cf  += coff;
    if (Chi) { Chi += coff; Clo += coff; }

    const int m0 = blockIdx.y * TILE_M;
    const int n0 = blockIdx.x * 128;

    const int tid  = threadIdx.x;
    const int warp = tid >> 5;
    const int lane = tid & 31;
    const int grp  = lane >> 2;
    const int tig  = lane & 3;
    const int mbase = (warp >> 2) * (MTW * 16);
    const int nbase = (warp & 3) * 32;

    const uint32_t dynbase = smem_u32(smem_raw);

    float acc[MTW][4][4];
    #pragma unroll
    for (int i = 0; i < MTW; i++)
        #pragma unroll
        for (int j = 0; j < 4; j++)
            #pragma unroll
            for (int r = 0; r < 4; r++) acc[i][j][r] = 0.f;

    const int KT = K >> 5;

    auto load_stage = [&](int s, int kt) {
        const int k0 = kt << 5;
        const uint32_t sb = dynbase + s * STAGE;
        #pragma unroll
        for (int i = 0; i < NIT; i++) {
            int idx = tid + i * 256;
            if (idx < 2 * ACH) {
                int arr = idx / ACH;
                int rem = idx - arr * ACH;
                int row = rem >> 2;
                int c16 = rem & 3;
                uint32_t dst = sb + arr * A_BYTES + row * 80 + c16 * 16;
                const bf16* src = (arr ? Al_g : Ah_g)
                                + (long)(m0 + row) * lda + k0 + c16 * 8;
                cp_async16(dst, src, true);
            } else {
                int idxb = idx - 2 * ACH;
                int arr = idxb >> 9;
                int rem = idxb & 511;
                int row = rem >> 2;
                int c16 = rem & 3;
                uint32_t dst = sb + OFF_BH + arr * B_BYTES + row * 80 + c16 * 16;
                int nr = n0 + row;
                bool p = nr < N;
                const bf16* src = (arr ? Bl_g : Bh_g)
                                + (long)(p ? nr : 0) * ldb + k0 + c16 * 8;
                cp_async16(dst, src, p);
            }
        }
        asm volatile("cp.async.commit_group;\n");
    };

    load_stage(0, 0);

    const int a_row = mbase + (lane & 15);
    const int a_kof = (lane >> 4) << 3;
    const int b_row = nbase + ((lane >> 4) << 3) + (lane & 7);
    const int b_kof = ((lane >> 3) & 1) << 3;

    for (int kt = 0; kt < KT; kt++) {
        const int cur = kt & 1;
        if (kt + 1 < KT) {
            load_stage(cur ^ 1, kt + 1);
            asm volatile("cp.async.wait_group 1;\n");
        } else {
            asm volatile("cp.async.wait_group 0;\n");
        }
        __syncthreads();

        const uint32_t sA = dynbase + cur * STAGE;
        const uint32_t sB = sA + OFF_BH;

        #pragma unroll
        for (int kk = 0; kk < 2; kk++) {
            const int kc = kk * 16;
            uint32_t ah[MTW][4], al[MTW][4], bh[4][2], bl[4][2];

            const uint32_t aaddr = sA + (uint32_t)(a_row * 80 + (kc + a_kof) * 2);
            #pragma unroll
            for (int mt = 0; mt < MTW; mt++) {
                LDSM4(ah[mt][0], ah[mt][1], ah[mt][2], ah[mt][3], aaddr + mt * (16 * 80));
                LDSM4(al[mt][0], al[mt][1], al[mt][2], al[mt][3],
                      aaddr + A_BYTES + mt * (16 * 80));
            }
            const uint32_t baddr = sB + (uint32_t)(b_row * 80 + (kc + b_kof) * 2);
            #pragma unroll
            for (int p = 0; p < 2; p++) {
                LDSM4(bh[2*p][0], bh[2*p][1], bh[2*p+1][0], bh[2*p+1][1],
                      baddr + p * (16 * 80));
                LDSM4(bl[2*p][0], bl[2*p][1], bl[2*p+1][0], bl[2*p+1][1],
                      baddr + B_BYTES + p * (16 * 80));
            }

            #pragma unroll
            for (int mt = 0; mt < MTW; mt++) {
                #pragma unroll
                for (int nt = 0; nt < 4; nt++) {
                    float* c4 = acc[mt][nt];
                    MMA16816(c4, ah[mt][0], ah[mt][1], ah[mt][2], ah[mt][3],
                             bh[nt][0], bh[nt][1]);
                    MMA16816(c4, ah[mt][0], ah[mt][1], ah[mt][2], ah[mt][3],
                             bl[nt][0], bl[nt][1]);
                    MMA16816(c4, al[mt][0], al[mt][1], al[mt][2], al[mt][3],
                             bh[nt][0], bh[nt][1]);
                }
            }
        }
        __syncthreads();
    }

    // ---- epilogue ----
    #pragma unroll
    for (int mt = 0; mt < MTW; mt++) {
        #pragma unroll
        for (int nt = 0; nt < 4; nt++) {
            int nc = n0 + nbase + nt * 8 + 2 * tig;
            if (nc >= N) continue;
            float* c4 = acc[mt][nt];
            #pragma unroll
            for (int rr = 0; rr < 2; rr++) {
                int m = m0 + mbase + mt * 16 + grp + rr * 8;
                float v0 = c4[rr * 2], v1 = c4[rr * 2 + 1];
                if (bias) { v0 += bias[nc]; v1 += bias[nc + 1]; }
                if (epi == 1) { v0 = gelu_f(v0); v1 = gelu_f(v1); }
                long idx = (long)m * ldc + nc;
                if (epi == 2) {
                    float2 old = *(const float2*)&Cf[idx];
                    v0 += old.x; v1 += old.y;
                }
                if (Cf) *(float2*)&Cf[idx] = make_float2(v0, v1);
                if (Chi) {
                    bf16 h0, l0, h1, l1;
                    split_pair(v0, h0, l0);
                    split_pair(v1, h1, l1);
                    __nv_bfloat162 th = __halves2bfloat162(h0, h1);
                    __nv_bfloat162 tl = __halves2bfloat162(l0, l1);
                    *(uint32_t*)&Chi[idx] = *(uint32_t*)&th;
                    *(uint32_t*)&Clo[idx] = *(uint32_t*)&tl;
                }
            }
        }
    }
}

#define DYN_SMEM_M128 (2 * (2 * 128 * 80 + 2 * 128 * 80))   // 81920
#define DYN_SMEM_M64  (2 * (2 * 64 * 80 + 2 * 128 * 80))    // 61440

// =====================================================================
// Fused flash attention (champion config: K-block 128, 1 CTA/SM).
// =====================================================================
#define FQ_ROWB   144
#define FA_QL     18432
#define FA_ST0    36864
#define FA_ARR    18432
#define FA_STAGE  (4*FA_ARR)
#define FA_SMEM   (FA_ST0 + 2*FA_STAGE)   // 184320

__global__ __launch_bounds__(256, 1)
void flash_attn_kernel(const bf16* __restrict__ qkvh, const bf16* __restrict__ qkvl,
                       bf16* __restrict__ oh, bf16* __restrict__ ol)
{
    const int bh = blockIdx.y;
    const int b  = bh / NHEADS;
    const int h  = bh % NHEADS;
    const int q0 = blockIdx.x * 128;

    const int tid  = threadIdx.x;
    const int warp = tid >> 5;
    const int lane = tid & 31;
    const int qbase = warp * 16;

    const uint32_t dyn = smem_u32(smem_raw);

    const bf16* qh_g = qkvh + ((long)(b * NTOK + q0)) * (3 * CDIM) + h * HEADD;
    const bf16* ql_g = qkvl + ((long)(b * NTOK + q0)) * (3 * CDIM) + h * HEADD;

    #pragma unroll
    for (int i = 0; i < 8; i++) {
        int idx = tid + i * 256;
        int arr = idx >> 10;
        int rem = idx & 1023;
        int row = rem >> 3;
        int c   = rem & 7;
        uint32_t dst = dyn + arr * FA_QL + row * FQ_ROWB + c * 16;
        const bf16* src = (arr ? ql_g : qh_g) + (long)row * (3 * CDIM) + c * 8;
        cp_async16(dst, src, true);
    }

    auto load_kv = [&](int s, int j) {
        const long keybase = (long)(b * NTOK + j * 128);
        const uint32_t sb = dyn + FA_ST0 + s * FA_STAGE;
        #pragma unroll
        for (int i = 0; i < 16; i++) {
            int idx = tid + i * 256;
            int arr = idx >> 10;
            int rem = idx & 1023;
            int row = rem >> 3;
            int c   = rem & 7;
            uint32_t dst = sb + arr * FA_ARR + row * FQ_ROWB + c * 16;
            const bf16* base = ((arr & 1) ? qkvl : qkvh);
            int sect = (arr < 2) ? CDIM : 2 * CDIM;
            const bf16* src = base + (keybase + row) * (3 * CDIM) + sect + h * HEADD + c * 8;
            cp_async16(dst, src, true);
        }
        asm volatile("cp.async.commit_group;\n");
    };

    load_kv(0, 0);

    float o[8][4];
    #pragma unroll
    for (int i = 0; i < 8; i++)
        #pragma unroll
        for (int r = 0; r < 4; r++) o[i][r] = 0.f;
    float m_i[2] = { -1e30f, -1e30f };
    float l_i[2] = { 0.f, 0.f };

    uint32_t qh_f[4][4], ql_f[4][4];
    const int a_row = qbase + (lane & 15);
    const int a_kof = (lane >> 4) << 3;
    const int b_row = ((lane >> 4) << 3) + (lane & 7);
    const int b_kof = ((lane >> 3) & 1) << 3;
    const int v_row = (((lane >> 3) & 1) << 3) + (lane & 7);
    const int v_dof = (lane >> 4) << 3;

    for (int j = 0; j < 8; j++) {
        const int cur = j & 1;
        if (j + 1 < 8) {
            load_kv(cur ^ 1, j + 1);
            asm volatile("cp.async.wait_group 1;\n");
        } else {
            asm volatile("cp.async.wait_group 0;\n");
        }
        __syncthreads();

        if (j == 0) {
            #pragma unroll
            for (int kk = 0; kk < 4; kk++) {
                uint32_t qaddr = dyn + (uint32_t)(a_row * FQ_ROWB + (kk * 16 + a_kof) * 2);
                LDSM4(qh_f[kk][0], qh_f[kk][1], qh_f[kk][2], qh_f[kk][3], qaddr);
                LDSM4(ql_f[kk][0], ql_f[kk][1], ql_f[kk][2], ql_f[kk][3], qaddr + FA_QL);
            }
        }

        const uint32_t kb = dyn + FA_ST0 + cur * FA_STAGE;
        const uint32_t vb = kb + 2 * FA_ARR;

        float s[16][4];
        #pragma unroll
        for (int i = 0; i < 16; i++)
            #pragma unroll
            for (int r = 0; r < 4; r++) s[i][r] = 0.f;

        #pragma unroll
        for (int np = 0; np < 8; np++) {
            #pragma unroll
            for (int kk = 0; kk < 4; kk++) {
                uint32_t kaddr = kb + (uint32_t)((np * 16 + b_row) * FQ_ROWB
                                                 + (kk * 16 + b_kof) * 2);
                uint32_t kh0, kh1, kh2, kh3, kl0, kl1, kl2, kl3;
                LDSM4(kh0, kh1, kh2, kh3, kaddr);
                LDSM4(kl0, kl1, kl2, kl3, kaddr + FA_ARR);
                float* c0 = s[2*np];
                float* c1 = s[2*np+1];
                MMA16816(c0, qh_f[kk][0], qh_f[kk][1], qh_f[kk][2], qh_f[kk][3], kh0, kh1);
                MMA16816(c0, qh_f[kk][0], qh_f[kk][1], qh_f[kk][2], qh_f[kk][3], kl0, kl1);
                MMA16816(c0, ql_f[kk][0], ql_f[kk][1], ql_f[kk][2], ql_f[kk][3], kh0, kh1);
                MMA16816(c1, qh_f[kk][0], qh_f[kk][1], qh_f[kk][2], qh_f[kk][3], kh2, kh3);
                MMA16816(c1, qh_f[kk][0], qh_f[kk][1], qh_f[kk][2], qh_f[kk][3], kl2, kl3);
                MMA16816(c1, ql_f[kk][0], ql_f[kk][1], ql_f[kk][2], ql_f[kk][3], kh2, kh3);
            }
        }

        #pragma unroll
        for (int rr = 0; rr < 2; rr++) {
            float mx = -1e30f;
            #pragma unroll
            for (int nt = 0; nt < 16; nt++)
                mx = fmaxf(mx, fmaxf(s[nt][rr*2], s[nt][rr*2+1]));
            mx = fmaxf(mx, __shfl_xor_sync(~0u, mx, 1));
            mx = fmaxf(mx, __shfl_xor_sync(~0u, mx, 2));
            float m_new = fmaxf(m_i[rr], mx);
            float alpha = __expf(SCALE_F * (m_i[rr] - m_new));
            m_i[rr] = m_new;
            l_i[rr] *= alpha;
            float psum = 0.f;
            #pragma unroll
            for (int nt = 0; nt < 16; nt++) {
                float p0 = __expf(SCALE_F * (s[nt][rr*2]     - m_new));
                float p1 = __expf(SCALE_F * (s[nt][rr*2 + 1] - m_new));
                s[nt][rr*2]     = p0;
                s[nt][rr*2 + 1] = p1;
                psum += p0 + p1;
            }
            l_i[rr] += psum;
            #pragma unroll
            for (int nt = 0; nt < 8; nt++) {
                o[nt][rr*2]     *= alpha;
                o[nt][rr*2 + 1] *= alpha;
            }
        }

        #pragma unroll
        for (int ks = 0; ks < 8; ks++) {
            uint32_t pah[4], pal[4];
            #pragma unroll
            for (int q = 0; q < 4; q++) {
                int nt = 2 * ks + (q >> 1);
                int base = (q & 1) * 2;
                bf16 h0, l0, h1, l1;
                split_pair(s[nt][base],     h0, l0);
                split_pair(s[nt][base + 1], h1, l1);
                __nv_bfloat162 th = __halves2bfloat162(h0, h1);
                __nv_bfloat162 tl = __halves2bfloat162(l0, l1);
                pah[q] = *(uint32_t*)&th;
                pal[q] = *(uint32_t*)&tl;
            }
            #pragma unroll
            for (int np = 0; np < 4; np++) {
                uint32_t vaddr = vb + (uint32_t)((ks * 16 + v_row) * FQ_ROWB
                                                 + (np * 16 + v_dof) * 2);
                uint32_t vh0, vh1, vh2, vh3, vl0, vl1, vl2, vl3;
                LDSM4T(vh0, vh1, vh2, vh3, vaddr);
                LDSM4T(vl0, vl1, vl2, vl3, vaddr + FA_ARR);
                float* c0 = o[2*np];
                float* c1 = o[2*np+1];
                MMA16816(c0, pah[0], pah[1], pah[2], pah[3], vh0, vh1);
                MMA16816(c0, pah[0], pah[1], pah[2], pah[3], vl0, vl1);
                MMA16816(c0, pal[0], pal[1], pal[2], pal[3], vh0, vh1);
                MMA16816(c1, pah[0], pah[1], pah[2], pah[3], vh2, vh3);
                MMA16816(c1, pah[0], pah[1], pah[2], pah[3], vl2, vl3);
                MMA16816(c1, pal[0], pal[1], pal[2], pal[3], vh2, vh3);
            }
        }
        __syncthreads();
    }

    float inv[2];
    #pragma unroll
    for (int rr = 0; rr < 2; rr++) {
        float l = l_i[rr];
        l += __shfl_xor_sync(~0u, l, 1);
        l += __shfl_xor_sync(~0u, l, 2);
        inv[rr] = 1.f / l;
    }

    const int r = lane >> 2;
    const int t = lane & 3;
    #pragma unroll
    for (int nt = 0; nt < 8; nt++) {
        #pragma unroll
        for (int rr = 0; rr < 2; rr++) {
            int qr = q0 + qbase + r + rr * 8;
            float v0 = o[nt][rr*2]     * inv[rr];
            float v1 = o[nt][rr*2 + 1] * inv[rr];
            bf16 h0, l0, h1, l1;
            split_pair(v0, h0, l0);
            split_pair(v1, h1, l1);
            __nv_bfloat162 th = __halves2bfloat162(h0, h1);
            __nv_bfloat162 tl = __halves2bfloat162(l0, l1);
            long idx = ((long)(b * NTOK + qr)) * CDIM + h * HEADD + nt * 8 + 2 * t;
            *(uint32_t*)&oh[idx] = *(uint32_t*)&th;
            *(uint32_t*)&ol[idx] = *(uint32_t*)&tl;
        }
    }
}

// =====================================================================
// f32 -> bf16 hi/lo pair conversion, float4-vectorized
// =====================================================================
__global__ void cvt_pair4_kernel(const float* __restrict__ in,
                                 bf16* __restrict__ hi, bf16* __restrict__ lo, long n4)
{
    long i = (long)blockIdx.x * blockDim.x + threadIdx.x;
    if (i >= n4) return;
    float4 v = ((const float4*)in)[i];
    bf16 h[4], l[4];
    split_pair(v.x, h[0], l[0]); split_pair(v.y, h[1], l[1]);
    split_pair(v.z, h[2], l[2]); split_pair(v.w, h[3], l[3]);
    __nv_bfloat162 h01 = __halves2bfloat162(h[0], h[1]);
    __nv_bfloat162 h23 = __halves2bfloat162(h[2], h[3]);
    __nv_bfloat162 l01 = __halves2bfloat162(l[0], l[1]);
    __nv_bfloat162 l23 = __halves2bfloat162(l[2], l[3]);
    ((uint2*)hi)[i] = make_uint2(*(uint32_t*)&h01, *(uint32_t*)&h23);
    ((uint2*)lo)[i] = make_uint2(*(uint32_t*)&l01, *(uint32_t*)&l23);
}

// =====================================================================
// im2col producing bf16 pairs
// =====================================================================
__global__ void im2col_kernel(const float* __restrict__ x,
                              bf16* __restrict__ ch, bf16* __restrict__ cl)
{
    long idx = (long)blockIdx.x * blockDim.x + threadIdx.x;
    if (idx >= (long)MROWS * CDIM) return;
    int k = (int)(idx % CDIM);
    int m = (int)(idx / CDIM);
    int b  = m >> 10;
    int n  = m & 1023;
    int hp = n >> 5, wp = n & 31;
    int ci = k >> 8;
    int r  = k & 255;
    int ky = r >> 4, kx = r & 15;
    long src = (((long)(b * 3 + ci) * IMG) + hp * PS + ky) * IMG + wp * PS + kx;
    bf16 h, l; split_pair(x[src], h, l);
    ch[idx] = h; cl[idx] = l;
}

// =====================================================================
// LayerNorm producing bf16 pairs
// =====================================================================
__global__ void layernorm_kernel(const float* __restrict__ in,
                                 bf16* __restrict__ oh, bf16* __restrict__ ol,
                                 const float* __restrict__ s, const float* __restrict__ b)
{
    __shared__ float red[8];
    const long row = blockIdx.x;
    const float* r = in + row * CDIM;
    int tid = threadIdx.x, lane = tid & 31, w = tid >> 5;

    float v[3];
    float sum = 0.f;
    #pragma unroll
    for (int j = 0; j < 3; j++) { v[j] = r[tid + j * 256]; sum += v[j]; }
    #pragma unroll
    for (int off = 16; off; off >>= 1) sum += __shfl_xor_sync(~0u, sum, off);
    if (lane == 0) red[w] = sum;
    __syncthreads();
    if (w == 0) {
        float t = (lane < 8) ? red[lane] : 0.f;
        #pragma unroll
        for (int off = 4; off; off >>= 1) t += __shfl_xor_sync(~0u, t, off);
        if (lane == 0) red[0] = t;
    }
    __syncthreads();
    float mu = red[0] * (1.f / CDIM);
    __syncthreads();

    float sq = 0.f;
    #pragma unroll
    for (int j = 0; j < 3; j++) { float d = v[j] - mu; sq += d * d; }
    #pragma unroll
    for (int off = 16; off; off >>= 1) sq += __shfl_xor_sync(~0u, sq, off);
    if (lane == 0) red[w] = sq;
    __syncthreads();
    if (w == 0) {
        float t = (lane < 8) ? red[lane] : 0.f;
        #pragma unroll
        for (int off = 4; off; off >>= 1) t += __shfl_xor_sync(~0u, t, off);
        if (lane == 0) red[0] = t;
    }
    __syncthreads();
    float rstd = rsqrtf(red[0] * (1.f / CDIM) + EPS_F);

    #pragma unroll
    for (int j = 0; j < 3; j++) {
        int c = tid + j * 256;
        float o = (v[j] - mu) * rstd * s[c] + b[c];
        bf16 h, l; split_pair(o, h, l);
        oh[row * CDIM + c] = h; ol[row * CDIM + c] = l;
    }
}

// =====================================================================
// Fused deformable attention: one warp per (b, h, n).
// =====================================================================
__global__ void deform_attn_kernel(const bf16* __restrict__ qkvh,
                                   const bf16* __restrict__ qkvl,
                                   const float* __restrict__ offs,
                                   bf16* __restrict__ oh, bf16* __restrict__ ol)
{
    int gwarp = (blockIdx.x * blockDim.x + threadIdx.x) >> 5;
    int lane  = threadIdx.x & 31;
    if (gwarp >= BB * NHEADS * NTOK) return;
    int n  = gwarp & (NTOK - 1);
    int bh = gwarp >> 10;
    int h  = bh % NHEADS;
    int b  = bh / NHEADS;
    int hp = n >> 5, wp = n & 31;

    const long rowoff = ((long)(b * NTOK + n)) * (3 * CDIM) + h * HEADD + 2 * lane;
    float2 q = unpack_pair(*(const uint32_t*)&qkvh[rowoff],
                           *(const uint32_t*)&qkvl[rowoff]);

    const float* offrow = offs + ((long)(b * NTOK + n)) * 96 + h * NPTS * 2;

    float att[NPTS], sv0[NPTS], sv1[NPTS];

    #pragma unroll
    for (int p = 0; p < NPTS; p++) {
        float ox = offrow[p * 2 + 0];
        float oy = offrow[p * 2 + 1];
        float gx = (wp + 0.5f) * (1.f / HP) + ox * (1.f / HP);
        float gy = (hp + 0.5f) * (1.f / HP) + oy * (1.f / HP);
        float px = (2.f * gx) * (HP * 0.5f) - 0.5f;
        float py = (2.f * gy) * (HP * 0.5f) - 0.5f;
        float x0f = floorf(px), y0f = floorf(py);
        float wx = px - x0f, wy = py - y0f;
        int x0 = (int)x0f, y0 = (int)y0f;
        float cw[4] = { (1.f - wx) * (1.f - wy), wx * (1.f - wy),
                        (1.f - wx) * wy,         wx * wy };

        float k0 = 0.f, k1 = 0.f, v0 = 0.f, v1 = 0.f;
        #pragma unroll
        for (int c = 0; c < 4; c++) {
            int yi = y0 + (c >> 1);
            int xi = x0 + (c & 1);
            if (yi >= 0 && yi < HP && xi >= 0 && xi < HP) {
                long base = ((long)(b * NTOK + yi * HP + xi)) * (3 * CDIM)
                          + CDIM + h * HEADD + 2 * lane;
                float2 kv = unpack_pair(*(const uint32_t*)&qkvh[base],
                                        *(const uint32_t*)&qkvl[base]);
                float2 vv = unpack_pair(*(const uint32_t*)&qkvh[base + CDIM],
                                        *(const uint32_t*)&qkvl[base + CDIM]);
                float wc = cw[c];
                k0 += wc * kv.x;  k1 += wc * kv.y;
                v0 += wc * vv.x;  v1 += wc * vv.y;
            }
        }
        sv0[p] = v0; sv1[p] = v1;
        float d = q.x * k0 + q.y * k1;
        #pragma unroll
        for (int off = 16; off; off >>= 1) d += __shfl_xor_sync(~0u, d, off);
        att[p] = d * SCALE_F;
    }

    float mx = fmaxf(fmaxf(att[0], att[1]), fmaxf(att[2], att[3]));
    float e[NPTS], sum = 0.f;
    #pragma unroll
    for (int p = 0; p < NPTS; p++) { e[p] = __expf(att[p] - mx); sum += e[p]; }
    float inv = 1.f / sum;

    float o0 = 0.f, o1 = 0.f;
    #pragma unroll
    for (int p = 0; p < NPTS; p++) {
        float a = e[p] * inv;
        o0 += a * sv0[p];
        o1 += a * sv1[p];
    }
    long base = ((long)(b * NTOK + n)) * CDIM + h * HEADD + 2 * lane;
    bf16 h0, l0, h1, l1;
    split_pair(o0, h0, l0);
    split_pair(o1, h1, l1);
    __nv_bfloat162 th = __halves2bfloat162(h0, h1);
    __nv_bfloat162 tl = __halves2bfloat162(l0, l1);
    *(uint32_t*)&oh[base] = *(uint32_t*)&th;
    *(uint32_t*)&ol[base] = *(uint32_t*)&tl;
}

// =====================================================================
// Output transpose: (B,N,C) -> (B,C,Hp,Wp)
// =====================================================================
__global__ void out_transpose_kernel(const float* __restrict__ x, float* __restrict__ out)
{
    long idx = (long)blockIdx.x * blockDim.x + threadIdx.x;
    if (idx >= (long)MROWS * CDIM) return;
    int n = (int)(idx % NTOK);
    int c = (int)((idx / NTOK) % CDIM);
    int b = (int)(idx / ((long)NTOK * CDIM));
    out[idx] = x[((long)(b * NTOK + n)) * CDIM + c];
}

// =====================================================================
// Host launcher
// =====================================================================
extern "C" void kernel_launch(void* const* d_in, const int* in_sizes, int n_in,
                              void* d_out, int out_size)
{
    const float* x       = (const float*)d_in[0];
    const float* patch_w = (const float*)d_in[1];
    const float* patch_b = (const float*)d_in[2];
    const float* ln1_s   = (const float*)d_in[3];
    const float* ln1_b   = (const float*)d_in[4];
    const float* qkv_w   = (const float*)d_in[5];
    const float* offs_w  = (const float*)d_in[6];
    const float* offs_b  = (const float*)d_in[7];
    const float* proj_w  = (const float*)d_in[8];
    const float* proj_b  = (const float*)d_in[9];
    const float* ln2_s   = (const float*)d_in[10];
    const float* ln2_b   = (const float*)d_in[11];
    const float* fc1_w   = (const float*)d_in[12];
    const float* fc1_b   = (const float*)d_in[13];
    const float* fc2_w   = (const float*)d_in[14];
    const float* fc2_b   = (const float*)d_in[15];

    cudaFuncSetAttribute(mma_gemm_kernel<4>,
                         cudaFuncAttributeMaxDynamicSharedMemorySize, DYN_SMEM_M128);
    cudaFuncSetAttribute(mma_gemm_kernel<2>,
                         cudaFuncAttributeMaxDynamicSharedMemorySize, DYN_SMEM_M64);
    cudaFuncSetAttribute(flash_attn_kernel,
                         cudaFuncAttributeMaxDynamicSharedMemorySize, FA_SMEM);

    float *gx, *goffs;
    bf16 *ghh,*ghl,*gcolh,*gcoll,*gqkvh,*gqkvl,*gaoh,*gaol;
    bf16 *gmlph,*gmlpl;
    bf16 *pwh,*pwl,*qwh,*qwl,*owh,*owl,*jwh,*jwl,*f1h,*f1l,*f2h,*f2l;
    cudaGetSymbolAddress((void**)&gx,    g_x);
    cudaGetSymbolAddress((void**)&goffs, g_offs);
    cudaGetSymbolAddress((void**)&ghh,   g_hh);   cudaGetSymbolAddress((void**)&ghl,   g_hl);
    cudaGetSymbolAddress((void**)&gcolh, g_colh); cudaGetSymbolAddress((void**)&gcoll, g_coll);
    cudaGetSymbolAddress((void**)&gqkvh, g_qkvh); cudaGetSymbolAddress((void**)&gqkvl, g_qkvl);
    cudaGetSymbolAddress((void**)&gaoh,  g_aoh);  cudaGetSymbolAddress((void**)&gaol,  g_aol);
    cudaGetSymbolAddress((void**)&gmlph, g_mlph); cudaGetSymbolAddress((void**)&gmlpl, g_mlpl);
    cudaGetSymbolAddress((void**)&pwh, g_pwh); cudaGetSymbolAddress((void**)&pwl, g_pwl);
    cudaGetSymbolAddress((void**)&qwh, g_qwh); cudaGetSymbolAddress((void**)&qwl, g_qwl);
    cudaGetSymbolAddress((void**)&owh, g_owh); cudaGetSymbolAddress((void**)&owl, g_owl);
    cudaGetSymbolAddress((void**)&jwh, g_jwh); cudaGetSymbolAddress((void**)&jwl, g_jwl);
    cudaGetSymbolAddress((void**)&f1h, g_f1h); cudaGetSymbolAddress((void**)&f1l, g_f1l);
    cudaGetSymbolAddress((void**)&f2h, g_f2h); cudaGetSymbolAddress((void**)&f2l, g_f2l);

    const int M = MROWS;

    // ---- weight conversion (vectorized) ----
    {
        long n1 = (long)CDIM * CDIM / 4;
        cvt_pair4_kernel<<<(int)((n1 + 255) / 256), 256>>>(patch_w, pwh, pwl, n1);
        long n2 = 6L * 3 * CDIM * CDIM / 4;
        cvt_pair4_kernel<<<(int)((n2 + 255) / 256), 256>>>(qkv_w, qwh, qwl, n2);
        long n3 = 6L * 96 * CDIM / 4;
        cvt_pair4_kernel<<<(int)((n3 + 255) / 256), 256>>>(offs_w, owh, owl, n3);
        long n4 = 6L * CDIM * CDIM / 4;
        cvt_pair4_kernel<<<(int)((n4 + 255) / 256), 256>>>(proj_w, jwh, jwl, n4);
        long n5 = 6L * 4 * CDIM * CDIM / 4;
        cvt_pair4_kernel<<<(int)((n5 + 255) / 256), 256>>>(fc1_w, f1h, f1l, n5);
        cvt_pair4_kernel<<<(int)((n5 + 255) / 256), 256>>>(fc2_w, f2h, f2l, n5);
    }

    // ---- patch embed (M64: 192 CTAs) ----
    im2col_kernel<<<(M * CDIM + 255) / 256, 256>>>(x, gcolh, gcoll);
    mma_gemm_kernel<2><<<dim3(6, M / 64, 1), 256, DYN_SMEM_M64>>>(
        gcolh, gcoll, pwh, pwl, gx, nullptr, nullptr, patch_b,
        M, CDIM, CDIM, CDIM, CDIM, CDIM,
        0, 0, 0, 0, 0, 0, 1, 0);

    for (int i = 0; i < 6; i++) {
        layernorm_kernel<<<M, 256>>>(gx, ghh, ghl, ln1_s + i * CDIM, ln1_b + i * CDIM);

        // QKV (M128: 288 CTAs)
        mma_gemm_kernel<4><<<dim3(18, M / 128, 1), 256, DYN_SMEM_M128>>>(
            ghh, ghl, qwh + (long)i * 2304 * CDIM, qwl + (long)i * 2304 * CDIM,
            nullptr, gqkvh, gqkvl, nullptr,
            M, 2304, CDIM, CDIM, CDIM, 2304,
            0, 0, 0, 0, 0, 0, 1, 0);

        bool sample = ((i + 1) % 3) != 0;
        if (sample) {
            // offsets (M64: 32 CTAs)
            mma_gemm_kernel<2><<<dim3(1, M / 64, 1), 256, DYN_SMEM_M64>>>(
                gqkvh, gqkvl, owh + (long)i * 96 * CDIM, owl + (long)i * 96 * CDIM,
                goffs, nullptr, nullptr, offs_b + i * 96,
                M, 96, CDIM, 3 * CDIM, CDIM, 96,
                0, 0, 0, 0, 0, 0, 1, 0);
            deform_attn_kernel<<<(BB * NHEADS * NTOK * 32) / 256, 256>>>(
                gqkvh, gqkvl, goffs, gaoh, gaol);
        } else {
            flash_attn_kernel<<<dim3(NTOK / 128, BB * NHEADS, 1), 256, FA_SMEM>>>(
                gqkvh, gqkvl, gaoh, gaol);
        }

        // proj + residual (M64: 192 CTAs)
        mma_gemm_kernel<2><<<dim3(6, M / 64, 1), 256, DYN_SMEM_M64>>>(
            gaoh, gaol, jwh + (long)i * CDIM * CDIM, jwl + (long)i * CDIM * CDIM,
            gx, nullptr, nullptr, proj_b + i * CDIM,
            M, CDIM, CDIM, CDIM, CDIM, CDIM,
            0, 0, 0, 0, 0, 0, 1, 2);

        layernorm_kernel<<<M, 256>>>(gx, ghh, ghl, ln2_s + i * CDIM, ln2_b + i * CDIM);

        // fc1 + gelu (M128: 384 CTAs)
        mma_gemm_kernel<4><<<dim3(24, M / 128, 1), 256, DYN_SMEM_M128>>>(
            ghh, ghl, f1h + (long)i * 3072 * CDIM, f1l + (long)i * 3072 * CDIM,
            nullptr, gmlph, gmlpl, fc1_b + i * 3072,
            M, 3072, CDIM, CDIM, CDIM, 3072,
            0, 0, 0, 0, 0, 0, 1, 1);
        // fc2 + residual (M64: 192 CTAs)
        mma_gemm_kernel<2><<<dim3(6, M / 64, 1), 256, DYN_SMEM_M64>>>(
            gmlph, gmlpl, f2h + (long)i * CDIM * 3072, f2l + (long)i * CDIM * 3072,
            gx, nullptr, nullptr, fc2_b + i * CDIM,
            M, CDIM, 3072, 3072, 3072, CDIM,
            0, 0, 0, 0, 0, 0, 1, 2);
    }

    out_transpose_kernel<<<(M * CDIM + 255) / 256, 256>>>(gx, (float*)d_out);
}

// round 15
// speedup vs baseline: 1.3054x; 1.0173x over previous
#include <cuda_runtime.h>
#include <cuda_bf16.h>
#include <math.h>
#include <cstdint>
#include <cstddef>

// ---------------- problem constants ----------------
#define BB       2
#define IMG      512
#define PS       16
#define HP       32
#define NTOK     1024
#define CDIM     768
#define NHEADS   12
#define HEADD    64
#define NPTS     4
#define SCALE_F  0.125f
#define EPS_F    1e-6f
#define MROWS    (BB*NTOK)   // 2048
#define KSPLIT   4           // offsets GEMM K-split factor

typedef __nv_bfloat16 bf16;

// ---------------- device scratch ----------------
__device__ float g_x    [MROWS*CDIM];
__device__ float g_offs4[KSPLIT*MROWS*96];

__device__ bf16 g_hh  [MROWS*CDIM],      g_hl  [MROWS*CDIM];
__device__ bf16 g_colh[MROWS*CDIM],      g_coll[MROWS*CDIM];
__device__ bf16 g_qkvh[MROWS*3*CDIM],    g_qkvl[MROWS*3*CDIM];
__device__ bf16 g_aoh [MROWS*CDIM],      g_aol [MROWS*CDIM];
__device__ bf16 g_mlph[MROWS*4*CDIM],    g_mlpl[MROWS*4*CDIM];

// weight bf16 hi/lo (converted each launch)
__device__ bf16 g_pwh[CDIM*CDIM],        g_pwl[CDIM*CDIM];
__device__ bf16 g_qwh[6*3*CDIM*CDIM],    g_qwl[6*3*CDIM*CDIM];
__device__ bf16 g_owh[6*96*CDIM],        g_owl[6*96*CDIM];
__device__ bf16 g_jwh[6*CDIM*CDIM],      g_jwl[6*CDIM*CDIM];
__device__ bf16 g_f1h[6*4*CDIM*CDIM],    g_f1l[6*4*CDIM*CDIM];
__device__ bf16 g_f2h[6*4*CDIM*CDIM],    g_f2l[6*4*CDIM*CDIM];

// ---------------- helpers ----------------
__device__ __forceinline__ float gelu_f(float v) {
    return 0.5f * v * (1.0f + erff(v * 0.7071067811865476f));
}
__device__ __forceinline__ void split_pair(float v, bf16& hi, bf16& lo) {
    hi = __float2bfloat16(v);
    lo = __float2bfloat16(v - __bfloat162float(hi));
}
__device__ __forceinline__ float2 unpack_pair(uint32_t h2, uint32_t l2) {
    __nv_bfloat162 th = *reinterpret_cast<__nv_bfloat162*>(&h2);
    __nv_bfloat162 tl = *reinterpret_cast<__nv_bfloat162*>(&l2);
    return make_float2(__bfloat162float(th.x) + __bfloat162float(tl.x),
                       __bfloat162float(th.y) + __bfloat162float(tl.y));
}
__device__ __forceinline__ uint32_t smem_u32(const void* p) {
    return (uint32_t)__cvta_generic_to_shared(p);
}
__device__ __forceinline__ void cp_async16(uint32_t dst, const void* src, bool pred) {
    int sz = pred ? 16 : 0;
    asm volatile("cp.async.cg.shared.global [%0], [%1], 16, %2;\n"
                 :: "r"(dst), "l"(src), "r"(sz));
}

#define LDSM4(r0, r1, r2, r3, addr) \
    asm volatile("ldmatrix.sync.aligned.m8n8.x4.shared.b16 {%0,%1,%2,%3}, [%4];" \
                 : "=r"(r0), "=r"(r1), "=r"(r2), "=r"(r3) : "r"(addr))

#define LDSM4T(r0, r1, r2, r3, addr) \
    asm volatile("ldmatrix.sync.aligned.m8n8.x4.trans.shared.b16 {%0,%1,%2,%3}, [%4];" \
                 : "=r"(r0), "=r"(r1), "=r"(r2), "=r"(r3) : "r"(addr))

#define MMA16816(c4, a0, a1, a2, a3, b0, b1) \
    asm volatile( \
        "mma.sync.aligned.m16n8k16.row.col.f32.bf16.bf16.f32 " \
        "{%0,%1,%2,%3}, {%4,%5,%6,%7}, {%8,%9}, {%0,%1,%2,%3};\n" \
        : "+f"((c4)[0]), "+f"((c4)[1]), "+f"((c4)[2]), "+f"((c4)[3]) \
        : "r"(a0), "r"(a1), "r"(a2), "r"(a3), "r"(b0), "r"(b1))

// =====================================================================
// bf16 hi/lo 3-product HMMA GEMM (champion config: BK=32, 2-stage)
// =====================================================================
extern __shared__ __align__(16) char smem_raw[];

template<int MTW>
__global__ __launch_bounds__(256, 4 / MTW)
void mma_gemm_kernel(const bf16* __restrict__ Ah_g, const bf16* __restrict__ Al_g,
                     const bf16* __restrict__ Bh_g, const bf16* __restrict__ Bl_g,
                     float* Cf, bf16* Chi, bf16* Clo,
                     const float* __restrict__ bias,
                     int M, int N, int K, int lda, int ldb, int ldc,
                     long sAb, long sAh2, long sBb, long sBh2, long sCb, long sCh2,
                     int nh, int epi)
{
    constexpr int TILE_M  = MTW * 32;
    constexpr int A_BYTES = TILE_M * 80;
    constexpr int OFF_BH  = 2 * A_BYTES;
    constexpr int B_BYTES = 128 * 80;
    constexpr int STAGE   = 2 * A_BYTES + 2 * B_BYTES;
    constexpr int ACH     = TILE_M * 4;
    constexpr int TOT_CH  = 2 * ACH + 1024;
    constexpr int NIT     = TOT_CH / 256;

    int z  = blockIdx.z;
    int bb = z / nh, hh = z % nh;
    long aoff = (long)bb * sAb + (long)hh * sAh2;
    long boff = (long)bb * sBb + (long)hh * sBh2;
    long coff = (long)bb * sCb + (long)hh * sCh2;
    Ah_g += aoff; Al_g += aoff; Bh_g += boff; Bl_g += boff;
    if (Cf)  Cf  += coff;
    if (Chi) { Chi += coff; Clo += coff; }

    const int m0 = blockIdx.y * TILE_M;
    const int n0 = blockIdx.x * 128;

    const int tid  = threadIdx.x;
    const int warp = tid >> 5;
    const int lane = tid & 31;
    const int grp  = lane >> 2;
    const int tig  = lane & 3;
    const int mbase = (warp >> 2) * (MTW * 16);
    const int nbase = (warp & 3) * 32;

    const uint32_t dynbase = smem_u32(smem_raw);

    float acc[MTW][4][4];
    #pragma unroll
    for (int i = 0; i < MTW; i++)
        #pragma unroll
        for (int j = 0; j < 4; j++)
            #pragma unroll
            for (int r = 0; r < 4; r++) acc[i][j][r] = 0.f;

    const int KT = K >> 5;

    auto load_stage = [&](int s, int kt) {
        const int k0 = kt << 5;
        const uint32_t sb = dynbase + s * STAGE;
        #pragma unroll
        for (int i = 0; i < NIT; i++) {
            int idx = tid + i * 256;
            if (idx < 2 * ACH) {
                int arr = idx / ACH;
                int rem = idx - arr * ACH;
                int row = rem >> 2;
                int c16 = rem & 3;
                uint32_t dst = sb + arr * A_BYTES + row * 80 + c16 * 16;
                const bf16* src = (arr ? Al_g : Ah_g)
                                + (long)(m0 + row) * lda + k0 + c16 * 8;
                cp_async16(dst, src, true);
            } else {
                int idxb = idx - 2 * ACH;
                int arr = idxb >> 9;
                int rem = idxb & 511;
                int row = rem >> 2;
                int c16 = rem & 3;
                uint32_t dst = sb + OFF_BH + arr * B_BYTES + row * 80 + c16 * 16;
                int nr = n0 + row;
                bool p = nr < N;
                const bf16* src = (arr ? Bl_g : Bh_g)
                                + (long)(p ? nr : 0) * ldb + k0 + c16 * 8;
                cp_async16(dst, src, p);
            }
        }
        asm volatile("cp.async.commit_group;\n");
    };

    load_stage(0, 0);

    const int a_row = mbase + (lane & 15);
    const int a_kof = (lane >> 4) << 3;
    const int b_row = nbase + ((lane >> 4) << 3) + (lane & 7);
    const int b_kof = ((lane >> 3) & 1) << 3;

    for (int kt = 0; kt < KT; kt++) {
        const int cur = kt & 1;
        if (kt + 1 < KT) {
            load_stage(cur ^ 1, kt + 1);
            asm volatile("cp.async.wait_group 1;\n");
        } else {
            asm volatile("cp.async.wait_group 0;\n");
        }
        __syncthreads();

        const uint32_t sA = dynbase + cur * STAGE;
        const uint32_t sB = sA + OFF_BH;

        #pragma unroll
        for (int kk = 0; kk < 2; kk++) {
            const int kc = kk * 16;
            uint32_t ah[MTW][4], al[MTW][4], bh[4][2], bl[4][2];

            const uint32_t aaddr = sA + (uint32_t)(a_row * 80 + (kc + a_kof) * 2);
            #pragma unroll
            for (int mt = 0; mt < MTW; mt++) {
                LDSM4(ah[mt][0], ah[mt][1], ah[mt][2], ah[mt][3], aaddr + mt * (16 * 80));
                LDSM4(al[mt][0], al[mt][1], al[mt][2], al[mt][3],
                      aaddr + A_BYTES + mt * (16 * 80));
            }
            const uint32_t baddr = sB + (uint32_t)(b_row * 80 + (kc + b_kof) * 2);
            #pragma unroll
            for (int p = 0; p < 2; p++) {
                LDSM4(bh[2*p][0], bh[2*p][1], bh[2*p+1][0], bh[2*p+1][1],
                      baddr + p * (16 * 80));
                LDSM4(bl[2*p][0], bl[2*p][1], bl[2*p+1][0], bl[2*p+1][1],
                      baddr + B_BYTES + p * (16 * 80));
            }

            #pragma unroll
            for (int mt = 0; mt < MTW; mt++) {
                #pragma unroll
                for (int nt = 0; nt < 4; nt++) {
                    float* c4 = acc[mt][nt];
                    MMA16816(c4, ah[mt][0], ah[mt][1], ah[mt][2], ah[mt][3],
                             bh[nt][0], bh[nt][1]);
                    MMA16816(c4, ah[mt][0], ah[mt][1], ah[mt][2], ah[mt][3],
                             bl[nt][0], bl[nt][1]);
                    MMA16816(c4, al[mt][0], al[mt][1], al[mt][2], al[mt][3],
                             bh[nt][0], bh[nt][1]);
                }
            }
        }
        __syncthreads();
    }

    // ---- epilogue ----
    #pragma unroll
    for (int mt = 0; mt < MTW; mt++) {
        #pragma unroll
        for (int nt = 0; nt < 4; nt++) {
            int nc = n0 + nbase + nt * 8 + 2 * tig;
            if (nc >= N) continue;
            float* c4 = acc[mt][nt];
            #pragma unroll
            for (int rr = 0; rr < 2; rr++) {
                int m = m0 + mbase + mt * 16 + grp + rr * 8;
                float v0 = c4[rr * 2], v1 = c4[rr * 2 + 1];
                if (bias) { v0 += bias[nc]; v1 += bias[nc + 1]; }
                if (epi == 1) { v0 = gelu_f(v0); v1 = gelu_f(v1); }
                long idx = (long)m * ldc + nc;
                if (epi == 2) {
                    float2 old = *(const float2*)&Cf[idx];
                    v0 += old.x; v1 += old.y;
                }
                if (Cf) *(float2*)&Cf[idx] = make_float2(v0, v1);
                if (Chi) {
                    bf16 h0, l0, h1, l1;
                    split_pair(v0, h0, l0);
                    split_pair(v1, h1, l1);
                    __nv_bfloat162 th = __halves2bfloat162(h0, h1);
                    __nv_bfloat162 tl = __halves2bfloat162(l0, l1);
                    *(uint32_t*)&Chi[idx] = *(uint32_t*)&th;
                    *(uint32_t*)&Clo[idx] = *(uint32_t*)&tl;
                }
            }
        }
    }
}

#define DYN_SMEM_M128 (2 * (2 * 128 * 80 + 2 * 128 * 80))   // 81920
#define DYN_SMEM_M64  (2 * (2 * 64 * 80 + 2 * 128 * 80))    // 61440

// =====================================================================
// Fused flash attention (champion config: K-block 128, 1 CTA/SM).
// =====================================================================
#define FQ_ROWB   144
#define FA_QL     18432
#define FA_ST0    36864
#define FA_ARR    18432
#define FA_STAGE  (4*FA_ARR)
#define FA_SMEM   (FA_ST0 + 2*FA_STAGE)   // 184320

__global__ __launch_bounds__(256, 1)
void flash_attn_kernel(const bf16* __restrict__ qkvh, const bf16* __restrict__ qkvl,
                       bf16* __restrict__ oh, bf16* __restrict__ ol)
{
    const int bh = blockIdx.y;
    const int b  = bh / NHEADS;
    const int h  = bh % NHEADS;
    const int q0 = blockIdx.x * 128;

    const int tid  = threadIdx.x;
    const int warp = tid >> 5;
    const int lane = tid & 31;
    const int qbase = warp * 16;

    const uint32_t dyn = smem_u32(smem_raw);

    const bf16* qh_g = qkvh + ((long)(b * NTOK + q0)) * (3 * CDIM) + h * HEADD;
    const bf16* ql_g = qkvl + ((long)(b * NTOK + q0)) * (3 * CDIM) + h * HEADD;

    #pragma unroll
    for (int i = 0; i < 8; i++) {
        int idx = tid + i * 256;
        int arr = idx >> 10;
        int rem = idx & 1023;
        int row = rem >> 3;
        int c   = rem & 7;
        uint32_t dst = dyn + arr * FA_QL + row * FQ_ROWB + c * 16;
        const bf16* src = (arr ? ql_g : qh_g) + (long)row * (3 * CDIM) + c * 8;
        cp_async16(dst, src, true);
    }

    auto load_kv = [&](int s, int j) {
        const long keybase = (long)(b * NTOK + j * 128);
        const uint32_t sb = dyn + FA_ST0 + s * FA_STAGE;
        #pragma unroll
        for (int i = 0; i < 16; i++) {
            int idx = tid + i * 256;
            int arr = idx >> 10;
            int rem = idx & 1023;
            int row = rem >> 3;
            int c   = rem & 7;
            uint32_t dst = sb + arr * FA_ARR + row * FQ_ROWB + c * 16;
            const bf16* base = ((arr & 1) ? qkvl : qkvh);
            int sect = (arr < 2) ? CDIM : 2 * CDIM;
            const bf16* src = base + (keybase + row) * (3 * CDIM) + sect + h * HEADD + c * 8;
            cp_async16(dst, src, true);
        }
        asm volatile("cp.async.commit_group;\n");
    };

    load_kv(0, 0);

    float o[8][4];
    #pragma unroll
    for (int i = 0; i < 8; i++)
        #pragma unroll
        for (int r = 0; r < 4; r++) o[i][r] = 0.f;
    float m_i[2] = { -1e30f, -1e30f };
    float l_i[2] = { 0.f, 0.f };

    uint32_t qh_f[4][4], ql_f[4][4];
    const int a_row = qbase + (lane & 15);
    const int a_kof = (lane >> 4) << 3;
    const int b_row = ((lane >> 4) << 3) + (lane & 7);
    const int b_kof = ((lane >> 3) & 1) << 3;
    const int v_row = (((lane >> 3) & 1) << 3) + (lane & 7);
    const int v_dof = (lane >> 4) << 3;

    for (int j = 0; j < 8; j++) {
        const int cur = j & 1;
        if (j + 1 < 8) {
            load_kv(cur ^ 1, j + 1);
            asm volatile("cp.async.wait_group 1;\n");
        } else {
            asm volatile("cp.async.wait_group 0;\n");
        }
        __syncthreads();

        if (j == 0) {
            #pragma unroll
            for (int kk = 0; kk < 4; kk++) {
                uint32_t qaddr = dyn + (uint32_t)(a_row * FQ_ROWB + (kk * 16 + a_kof) * 2);
                LDSM4(qh_f[kk][0], qh_f[kk][1], qh_f[kk][2], qh_f[kk][3], qaddr);
                LDSM4(ql_f[kk][0], ql_f[kk][1], ql_f[kk][2], ql_f[kk][3], qaddr + FA_QL);
            }
        }

        const uint32_t kb = dyn + FA_ST0 + cur * FA_STAGE;
        const uint32_t vb = kb + 2 * FA_ARR;

        float s[16][4];
        #pragma unroll
        for (int i = 0; i < 16; i++)
            #pragma unroll
            for (int r = 0; r < 4; r++) s[i][r] = 0.f;

        #pragma unroll
        for (int np = 0; np < 8; np++) {
            #pragma unroll
            for (int kk = 0; kk < 4; kk++) {
                uint32_t kaddr = kb + (uint32_t)((np * 16 + b_row) * FQ_ROWB
                                                 + (kk * 16 + b_kof) * 2);
                uint32_t kh0, kh1, kh2, kh3, kl0, kl1, kl2, kl3;
                LDSM4(kh0, kh1, kh2, kh3, kaddr);
                LDSM4(kl0, kl1, kl2, kl3, kaddr + FA_ARR);
                float* c0 = s[2*np];
                float* c1 = s[2*np+1];
                MMA16816(c0, qh_f[kk][0], qh_f[kk][1], qh_f[kk][2], qh_f[kk][3], kh0, kh1);
                MMA16816(c0, qh_f[kk][0], qh_f[kk][1], qh_f[kk][2], qh_f[kk][3], kl0, kl1);
                MMA16816(c0, ql_f[kk][0], ql_f[kk][1], ql_f[kk][2], ql_f[kk][3], kh0, kh1);
                MMA16816(c1, qh_f[kk][0], qh_f[kk][1], qh_f[kk][2], qh_f[kk][3], kh2, kh3);
                MMA16816(c1, qh_f[kk][0], qh_f[kk][1], qh_f[kk][2], qh_f[kk][3], kl2, kl3);
                MMA16816(c1, ql_f[kk][0], ql_f[kk][1], ql_f[kk][2], ql_f[kk][3], kh2, kh3);
            }
        }

        #pragma unroll
        for (int rr = 0; rr < 2; rr++) {
            float mx = -1e30f;
            #pragma unroll
            for (int nt = 0; nt < 16; nt++)
                mx = fmaxf(mx, fmaxf(s[nt][rr*2], s[nt][rr*2+1]));
            mx = fmaxf(mx, __shfl_xor_sync(~0u, mx, 1));
            mx = fmaxf(mx, __shfl_xor_sync(~0u, mx, 2));
            float m_new = fmaxf(m_i[rr], mx);
            float alpha = __expf(SCALE_F * (m_i[rr] - m_new));
            m_i[rr] = m_new;
            l_i[rr] *= alpha;
            float psum = 0.f;
            #pragma unroll
            for (int nt = 0; nt < 16; nt++) {
                float p0 = __expf(SCALE_F * (s[nt][rr*2]     - m_new));
                float p1 = __expf(SCALE_F * (s[nt][rr*2 + 1] - m_new));
                s[nt][rr*2]     = p0;
                s[nt][rr*2 + 1] = p1;
                psum += p0 + p1;
            }
            l_i[rr] += psum;
            #pragma unroll
            for (int nt = 0; nt < 8; nt++) {
                o[nt][rr*2]     *= alpha;
                o[nt][rr*2 + 1] *= alpha;
            }
        }

        #pragma unroll
        for (int ks = 0; ks < 8; ks++) {
            uint32_t pah[4], pal[4];
            #pragma unroll
            for (int q = 0; q < 4; q++) {
                int nt = 2 * ks + (q >> 1);
                int base = (q & 1) * 2;
                bf16 h0, l0, h1, l1;
                split_pair(s[nt][base],     h0, l0);
                split_pair(s[nt][base + 1], h1, l1);
                __nv_bfloat162 th = __halves2bfloat162(h0, h1);
                __nv_bfloat162 tl = __halves2bfloat162(l0, l1);
                pah[q] = *(uint32_t*)&th;
                pal[q] = *(uint32_t*)&tl;
            }
            #pragma unroll
            for (int np = 0; np < 4; np++) {
                uint32_t vaddr = vb + (uint32_t)((ks * 16 + v_row) * FQ_ROWB
                                                 + (np * 16 + v_dof) * 2);
                uint32_t vh0, vh1, vh2, vh3, vl0, vl1, vl2, vl3;
                LDSM4T(vh0, vh1, vh2, vh3, vaddr);
                LDSM4T(vl0, vl1, vl2, vl3, vaddr + FA_ARR);
                float* c0 = o[2*np];
                float* c1 = o[2*np+1];
                MMA16816(c0, pah[0], pah[1], pah[2], pah[3], vh0, vh1);
                MMA16816(c0, pah[0], pah[1], pah[2], pah[3], vl0, vl1);
                MMA16816(c0, pal[0], pal[1], pal[2], pal[3], vh0, vh1);
                MMA16816(c1, pah[0], pah[1], pah[2], pah[3], vh2, vh3);
                MMA16816(c1, pah[0], pah[1], pah[2], pah[3], vl2, vl3);
                MMA16816(c1, pal[0], pal[1], pal[2], pal[3], vh2, vh3);
            }
        }
        __syncthreads();
    }

    float inv[2];
    #pragma unroll
    for (int rr = 0; rr < 2; rr++) {
        float l = l_i[rr];
        l += __shfl_xor_sync(~0u, l, 1);
        l += __shfl_xor_sync(~0u, l, 2);
        inv[rr] = 1.f / l;
    }

    const int r = lane >> 2;
    const int t = lane & 3;
    #pragma unroll
    for (int nt = 0; nt < 8; nt++) {
        #pragma unroll
        for (int rr = 0; rr < 2; rr++) {
            int qr = q0 + qbase + r + rr * 8;
            float v0 = o[nt][rr*2]     * inv[rr];
            float v1 = o[nt][rr*2 + 1] * inv[rr];
            bf16 h0, l0, h1, l1;
            split_pair(v0, h0, l0);
            split_pair(v1, h1, l1);
            __nv_bfloat162 th = __halves2bfloat162(h0, h1);
            __nv_bfloat162 tl = __halves2bfloat162(l0, l1);
            long idx = ((long)(b * NTOK + qr)) * CDIM + h * HEADD + nt * 8 + 2 * t;
            *(uint32_t*)&oh[idx] = *(uint32_t*)&th;
            *(uint32_t*)&ol[idx] = *(uint32_t*)&tl;
        }
    }
}

// =====================================================================
// f32 -> bf16 hi/lo pair conversion, float4-vectorized
// =====================================================================
__global__ void cvt_pair4_kernel(const float* __restrict__ in,
                                 bf16* __restrict__ hi, bf16* __restrict__ lo, long n4)
{
    long i = (long)blockIdx.x * blockDim.x + threadIdx.x;
    if (i >= n4) return;
    float4 v = ((const float4*)in)[i];
    bf16 h[4], l[4];
    split_pair(v.x, h[0], l[0]); split_pair(v.y, h[1], l[1]);
    split_pair(v.z, h[2], l[2]); split_pair(v.w, h[3], l[3]);
    __nv_bfloat162 h01 = __halves2bfloat162(h[0], h[1]);
    __nv_bfloat162 h23 = __halves2bfloat162(h[2], h[3]);
    __nv_bfloat162 l01 = __halves2bfloat162(l[0], l[1]);
    __nv_bfloat162 l23 = __halves2bfloat162(l[2], l[3]);
    ((uint2*)hi)[i] = make_uint2(*(uint32_t*)&h01, *(uint32_t*)&h23);
    ((uint2*)lo)[i] = make_uint2(*(uint32_t*)&l01, *(uint32_t*)&l23);
}

// =====================================================================
// im2col producing bf16 pairs
// =====================================================================
__global__ void im2col_kernel(const float* __restrict__ x,
                              bf16* __restrict__ ch, bf16* __restrict__ cl)
{
    long idx = (long)blockIdx.x * blockDim.x + threadIdx.x;
    if (idx >= (long)MROWS * CDIM) return;
    int k = (int)(idx % CDIM);
    int m = (int)(idx / CDIM);
    int b  = m >> 10;
    int n  = m & 1023;
    int hp = n >> 5, wp = n & 31;
    int ci = k >> 8;
    int r  = k & 255;
    int ky = r >> 4, kx = r & 15;
    long src = (((long)(b * 3 + ci) * IMG) + hp * PS + ky) * IMG + wp * PS + kx;
    bf16 h, l; split_pair(x[src], h, l);
    ch[idx] = h; cl[idx] = l;
}

// =====================================================================
// LayerNorm producing bf16 pairs
// =====================================================================
__global__ void layernorm_kernel(const float* __restrict__ in,
                                 bf16* __restrict__ oh, bf16* __restrict__ ol,
                                 const float* __restrict__ s, const float* __restrict__ b)
{
    __shared__ float red[8];
    const long row = blockIdx.x;
    const float* r = in + row * CDIM;
    int tid = threadIdx.x, lane = tid & 31, w = tid >> 5;

    float v[3];
    float sum = 0.f;
    #pragma unroll
    for (int j = 0; j < 3; j++) { v[j] = r[tid + j * 256]; sum += v[j]; }
    #pragma unroll
    for (int off = 16; off; off >>= 1) sum += __shfl_xor_sync(~0u, sum, off);
    if (lane == 0) red[w] = sum;
    __syncthreads();
    if (w == 0) {
        float t = (lane < 8) ? red[lane] : 0.f;
        #pragma unroll
        for (int off = 4; off; off >>= 1) t += __shfl_xor_sync(~0u, t, off);
        if (lane == 0) red[0] = t;
    }
    __syncthreads();
    float mu = red[0] * (1.f / CDIM);
    __syncthreads();

    float sq = 0.f;
    #pragma unroll
    for (int j = 0; j < 3; j++) { float d = v[j] - mu; sq += d * d; }
    #pragma unroll
    for (int off = 16; off; off >>= 1) sq += __shfl_xor_sync(~0u, sq, off);
    if (lane == 0) red[w] = sq;
    __syncthreads();
    if (w == 0) {
        float t = (lane < 8) ? red[lane] : 0.f;
        #pragma unroll
        for (int off = 4; off; off >>= 1) t += __shfl_xor_sync(~0u, t, off);
        if (lane == 0) red[0] = t;
    }
    __syncthreads();
    float rstd = rsqrtf(red[0] * (1.f / CDIM) + EPS_F);

    #pragma unroll
    for (int j = 0; j < 3; j++) {
        int c = tid + j * 256;
        float o = (v[j] - mu) * rstd * s[c] + b[c];
        bf16 h, l; split_pair(o, h, l);
        oh[row * CDIM + c] = h; ol[row * CDIM + c] = l;
    }
}

// =====================================================================
// Fused deformable attention: one warp per (b, h, n).
// offs4 holds KSPLIT partial sums; bias added here.
// =====================================================================
__global__ void deform_attn_kernel(const bf16* __restrict__ qkvh,
                                   const bf16* __restrict__ qkvl,
                                   const float* __restrict__ offs4,
                                   const float* __restrict__ offs_b,
                                   bf16* __restrict__ oh, bf16* __restrict__ ol)
{
    int gwarp = (blockIdx.x * blockDim.x + threadIdx.x) >> 5;
    int lane  = threadIdx.x & 31;
    if (gwarp >= BB * NHEADS * NTOK) return;
    int n  = gwarp & (NTOK - 1);
    int bh = gwarp >> 10;
    int h  = bh % NHEADS;
    int b  = bh / NHEADS;
    int hp = n >> 5, wp = n & 31;

    const long rowoff = ((long)(b * NTOK + n)) * (3 * CDIM) + h * HEADD + 2 * lane;
    float2 q = unpack_pair(*(const uint32_t*)&qkvh[rowoff],
                           *(const uint32_t*)&qkvl[rowoff]);

    const long offbase = ((long)(b * NTOK + n)) * 96 + h * NPTS * 2;
    const long CH = (long)MROWS * 96;

    float att[NPTS], sv0[NPTS], sv1[NPTS];

    #pragma unroll
    for (int p = 0; p < NPTS; p++) {
        long oidx = offbase + p * 2;
        float ox = offs4[oidx]            + offs4[oidx + CH]
                 + offs4[oidx + 2 * CH]   + offs4[oidx + 3 * CH]
                 + offs_b[h * NPTS * 2 + p * 2];
        float oy = offs4[oidx + 1]        + offs4[oidx + 1 + CH]
                 + offs4[oidx + 1 + 2*CH] + offs4[oidx + 1 + 3*CH]
                 + offs_b[h * NPTS * 2 + p * 2 + 1];
        float gx = (wp + 0.5f) * (1.f / HP) + ox * (1.f / HP);
        float gy = (hp + 0.5f) * (1.f / HP) + oy * (1.f / HP);
        float px = (2.f * gx) * (HP * 0.5f) - 0.5f;
        float py = (2.f * gy) * (HP * 0.5f) - 0.5f;
        float x0f = floorf(px), y0f = floorf(py);
        float wx = px - x0f, wy = py - y0f;
        int x0 = (int)x0f, y0 = (int)y0f;
        float cw[4] = { (1.f - wx) * (1.f - wy), wx * (1.f - wy),
                        (1.f - wx) * wy,         wx * wy };

        float k0 = 0.f, k1 = 0.f, v0 = 0.f, v1 = 0.f;
        #pragma unroll
        for (int c = 0; c < 4; c++) {
            int yi = y0 + (c >> 1);
            int xi = x0 + (c & 1);
            if (yi >= 0 && yi < HP && xi >= 0 && xi < HP) {
                long base = ((long)(b * NTOK + yi * HP + xi)) * (3 * CDIM)
                          + CDIM + h * HEADD + 2 * lane;
                float2 kv = unpack_pair(*(const uint32_t*)&qkvh[base],
                                        *(const uint32_t*)&qkvl[base]);
                float2 vv = unpack_pair(*(const uint32_t*)&qkvh[base + CDIM],
                                        *(const uint32_t*)&qkvl[base + CDIM]);
                float wc = cw[c];
                k0 += wc * kv.x;  k1 += wc * kv.y;
                v0 += wc * vv.x;  v1 += wc * vv.y;
            }
        }
        sv0[p] = v0; sv1[p] = v1;
        float d = q.x * k0 + q.y * k1;
        #pragma unroll
        for (int off = 16; off; off >>= 1) d += __shfl_xor_sync(~0u, d, off);
        att[p] = d * SCALE_F;
    }

    float mx = fmaxf(fmaxf(att[0], att[1]), fmaxf(att[2], att[3]));
    float e[NPTS], sum = 0.f;
    #pragma unroll
    for (int p = 0; p < NPTS; p++) { e[p] = __expf(att[p] - mx); sum += e[p]; }
    float inv = 1.f / sum;

    float o0 = 0.f, o1 = 0.f;
    #pragma unroll
    for (int p = 0; p < NPTS; p++) {
        float a = e[p] * inv;
        o0 += a * sv0[p];
        o1 += a * sv1[p];
    }
    long base = ((long)(b * NTOK + n)) * CDIM + h * HEADD + 2 * lane;
    bf16 h0, l0, h1, l1;
    split_pair(o0, h0, l0);
    split_pair(o1, h1, l1);
    __nv_bfloat162 th = __halves2bfloat162(h0, h1);
    __nv_bfloat162 tl = __halves2bfloat162(l0, l1);
    *(uint32_t*)&oh[base] = *(uint32_t*)&th;
    *(uint32_t*)&ol[base] = *(uint32_t*)&tl;
}

// =====================================================================
// Output transpose: (B,N,C) -> (B,C,Hp,Wp)
// =====================================================================
__global__ void out_transpose_kernel(const float* __restrict__ x, float* __restrict__ out)
{
    long idx = (long)blockIdx.x * blockDim.x + threadIdx.x;
    if (idx >= (long)MROWS * CDIM) return;
    int n = (int)(idx % NTOK);
    int c = (int)((idx / NTOK) % CDIM);
    int b = (int)(idx / ((long)NTOK * CDIM));
    out[idx] = x[((long)(b * NTOK + n)) * CDIM + c];
}

// =====================================================================
// Host launcher
// =====================================================================
extern "C" void kernel_launch(void* const* d_in, const int* in_sizes, int n_in,
                              void* d_out, int out_size)
{
    const float* x       = (const float*)d_in[0];
    const float* patch_w = (const float*)d_in[1];
    const float* patch_b = (const float*)d_in[2];
    const float* ln1_s   = (const float*)d_in[3];
    const float* ln1_b   = (const float*)d_in[4];
    const float* qkv_w   = (const float*)d_in[5];
    const float* offs_w  = (const float*)d_in[6];
    const float* offs_b  = (const float*)d_in[7];
    const float* proj_w  = (const float*)d_in[8];
    const float* proj_b  = (const float*)d_in[9];
    const float* ln2_s   = (const float*)d_in[10];
    const float* ln2_b   = (const float*)d_in[11];
    const float* fc1_w   = (const float*)d_in[12];
    const float* fc1_b   = (const float*)d_in[13];
    const float* fc2_w   = (const float*)d_in[14];
    const float* fc2_b   = (const float*)d_in[15];

    cudaFuncSetAttribute(mma_gemm_kernel<4>,
                         cudaFuncAttributeMaxDynamicSharedMemorySize, DYN_SMEM_M128);
    cudaFuncSetAttribute(mma_gemm_kernel<2>,
                         cudaFuncAttributeMaxDynamicSharedMemorySize, DYN_SMEM_M64);
    cudaFuncSetAttribute(flash_attn_kernel,
                         cudaFuncAttributeMaxDynamicSharedMemorySize, FA_SMEM);

    float *gx, *goffs4;
    bf16 *ghh,*ghl,*gcolh,*gcoll,*gqkvh,*gqkvl,*gaoh,*gaol;
    bf16 *gmlph,*gmlpl;
    bf16 *pwh,*pwl,*qwh,*qwl,*owh,*owl,*jwh,*jwl,*f1h,*f1l,*f2h,*f2l;
    cudaGetSymbolAddress((void**)&gx,     g_x);
    cudaGetSymbolAddress((void**)&goffs4, g_offs4);
    cudaGetSymbolAddress((void**)&ghh,   g_hh);   cudaGetSymbolAddress((void**)&ghl,   g_hl);
    cudaGetSymbolAddress((void**)&gcolh, g_colh); cudaGetSymbolAddress((void**)&gcoll, g_coll);
    cudaGetSymbolAddress((void**)&gqkvh, g_qkvh); cudaGetSymbolAddress((void**)&gqkvl, g_qkvl);
    cudaGetSymbolAddress((void**)&gaoh,  g_aoh);  cudaGetSymbolAddress((void**)&gaol,  g_aol);
    cudaGetSymbolAddress((void**)&gmlph, g_mlph); cudaGetSymbolAddress((void**)&gmlpl, g_mlpl);
    cudaGetSymbolAddress((void**)&pwh, g_pwh); cudaGetSymbolAddress((void**)&pwl, g_pwl);
    cudaGetSymbolAddress((void**)&qwh, g_qwh); cudaGetSymbolAddress((void**)&qwl, g_qwl);
    cudaGetSymbolAddress((void**)&owh, g_owh); cudaGetSymbolAddress((void**)&owl, g_owl);
    cudaGetSymbolAddress((void**)&jwh, g_jwh); cudaGetSymbolAddress((void**)&jwl, g_jwl);
    cudaGetSymbolAddress((void**)&f1h, g_f1h); cudaGetSymbolAddress((void**)&f1l, g_f1l);
    cudaGetSymbolAddress((void**)&f2h, g_f2h); cudaGetSymbolAddress((void**)&f2l, g_f2l);

    const int M = MROWS;

    // ---- weight conversion (vectorized) ----
    {
        long n1 = (long)CDIM * CDIM / 4;
        cvt_pair4_kernel<<<(int)((n1 + 255) / 256), 256>>>(patch_w, pwh, pwl, n1);
        long n2 = 6L * 3 * CDIM * CDIM / 4;
        cvt_pair4_kernel<<<(int)((n2 + 255) / 256), 256>>>(qkv_w, qwh, qwl, n2);
        long n3 = 6L * 96 * CDIM / 4;
        cvt_pair4_kernel<<<(int)((n3 + 255) / 256), 256>>>(offs_w, owh, owl, n3);
        long n4 = 6L * CDIM * CDIM / 4;
        cvt_pair4_kernel<<<(int)((n4 + 255) / 256), 256>>>(proj_w, jwh, jwl, n4);
        long n5 = 6L * 4 * CDIM * CDIM / 4;
        cvt_pair4_kernel<<<(int)((n5 + 255) / 256), 256>>>(fc1_w, f1h, f1l, n5);
        cvt_pair4_kernel<<<(int)((n5 + 255) / 256), 256>>>(fc2_w, f2h, f2l, n5);
    }

    // ---- patch embed (M64: 192 CTAs) ----
    im2col_kernel<<<(M * CDIM + 255) / 256, 256>>>(x, gcolh, gcoll);
    mma_gemm_kernel<2><<<dim3(6, M / 64, 1), 256, DYN_SMEM_M64>>>(
        gcolh, gcoll, pwh, pwl, gx, nullptr, nullptr, patch_b,
        M, CDIM, CDIM, CDIM, CDIM, CDIM,
        0, 0, 0, 0, 0, 0, 1, 0);

    for (int i = 0; i < 6; i++) {
        layernorm_kernel<<<M, 256>>>(gx, ghh, ghl, ln1_s + i * CDIM, ln1_b + i * CDIM);

        // QKV (M128: 288 CTAs)
        mma_gemm_kernel<4><<<dim3(18, M / 128, 1), 256, DYN_SMEM_M128>>>(
            ghh, ghl, qwh + (long)i * 2304 * CDIM, qwl + (long)i * 2304 * CDIM,
            nullptr, gqkvh, gqkvl, nullptr,
            M, 2304, CDIM, CDIM, CDIM, 2304,
            0, 0, 0, 0, 0, 0, 1, 0);

        bool sample = ((i + 1) % 3) != 0;
        if (sample) {
            // offsets: K-split x4 (128 CTAs), partial sums into goffs4
            mma_gemm_kernel<2><<<dim3(1, M / 64, KSPLIT), 256, DYN_SMEM_M64>>>(
                gqkvh, gqkvl, owh + (long)i * 96 * CDIM, owl + (long)i * 96 * CDIM,
                goffs4, nullptr, nullptr, nullptr,
                M, 96, CDIM / KSPLIT, 3 * CDIM, CDIM, 96,
                0, CDIM / KSPLIT,
                0, CDIM / KSPLIT,
                0, (long)MROWS * 96,
                KSPLIT, 0);
            deform_attn_kernel<<<(BB * NHEADS * NTOK * 32) / 256, 256>>>(
                gqkvh, gqkvl, goffs4, offs_b + i * 96, gaoh, gaol);
        } else {
            flash_attn_kernel<<<dim3(NTOK / 128, BB * NHEADS, 1), 256, FA_SMEM>>>(
                gqkvh, gqkvl, gaoh, gaol);
        }

        // proj + residual (M64: 192 CTAs)
        mma_gemm_kernel<2><<<dim3(6, M / 64, 1), 256, DYN_SMEM_M64>>>(
            gaoh, gaol, jwh + (long)i * CDIM * CDIM, jwl + (long)i * CDIM * CDIM,
            gx, nullptr, nullptr, proj_b + i * CDIM,
            M, CDIM, CDIM, CDIM, CDIM, CDIM,
            0, 0, 0, 0, 0, 0, 1, 2);

        layernorm_kernel<<<M, 256>>>(gx, ghh, ghl, ln2_s + i * CDIM, ln2_b + i * CDIM);

        // fc1 + gelu (M128: 384 CTAs)
        mma_gemm_kernel<4><<<dim3(24, M / 128, 1), 256, DYN_SMEM_M128>>>(
            ghh, ghl, f1h + (long)i * 3072 * CDIM, f1l + (long)i * 3072 * CDIM,
            nullptr, gmlph, gmlpl, fc1_b + i * 3072,
            M, 3072, CDIM, CDIM, CDIM, 3072,
            0, 0, 0, 0, 0, 0, 1, 1);
        // fc2 + residual (M64: 192 CTAs)
        mma_gemm_kernel<2><<<dim3(6, M / 64, 1), 256, DYN_SMEM_M64>>>(
            gmlph, gmlpl, f2h + (long)i * CDIM * 3072, f2l + (long)i * CDIM * 3072,
            gx, nullptr, nullptr, fc2_b + i * CDIM,
            M, CDIM, 3072, 3072, 3072, CDIM,
            0, 0, 0, 0, 0, 0, 1, 2);
    }

    out_transpose_kernel<<<(M * CDIM + 255) / 256, 256>>>(gx, (float*)d_out);
}

// round 16
// speedup vs baseline: 1.3992x; 1.0719x over previous
#include <cuda_runtime.h>
#include <cuda_bf16.h>
#include <math.h>
#include <cstdint>
#include <cstddef>

// ---------------- problem constants ----------------
#define BB       2
#define IMG      512
#define PS       16
#define HP       32
#define NTOK     1024
#define CDIM     768
#define NHEADS   12
#define HEADD    64
#define NPTS     4
#define SCALE_F  0.125f
#define EPS_F    1e-6f
#define MROWS    (BB*NTOK)   // 2048
#define KSPLIT   4           // offsets GEMM K-split factor

typedef __nv_bfloat16 bf16;

// ---------------- device scratch ----------------
__device__ float g_x    [MROWS*CDIM];
__device__ float g_offs4[KSPLIT*MROWS*96];
__device__ float g_f2p  [2*MROWS*CDIM];      // fc2 K-split partials

__device__ bf16 g_hh  [MROWS*CDIM],      g_hl  [MROWS*CDIM];
__device__ bf16 g_colh[MROWS*CDIM],      g_coll[MROWS*CDIM];
__device__ bf16 g_qkvh[MROWS*3*CDIM],    g_qkvl[MROWS*3*CDIM];
__device__ bf16 g_aoh [MROWS*CDIM],      g_aol [MROWS*CDIM];
__device__ bf16 g_mlph[MROWS*4*CDIM],    g_mlpl[MROWS*4*CDIM];

// weight bf16 hi/lo (converted each launch)
__device__ bf16 g_pwh[CDIM*CDIM],        g_pwl[CDIM*CDIM];
__device__ bf16 g_qwh[6*3*CDIM*CDIM],    g_qwl[6*3*CDIM*CDIM];
__device__ bf16 g_owh[6*96*CDIM],        g_owl[6*96*CDIM];
__device__ bf16 g_jwh[6*CDIM*CDIM],      g_jwl[6*CDIM*CDIM];
__device__ bf16 g_f1h[6*4*CDIM*CDIM],    g_f1l[6*4*CDIM*CDIM];
__device__ bf16 g_f2h[6*4*CDIM*CDIM],    g_f2l[6*4*CDIM*CDIM];

// ---------------- helpers ----------------
__device__ __forceinline__ float gelu_f(float v) {
    return 0.5f * v * (1.0f + erff(v * 0.7071067811865476f));
}
__device__ __forceinline__ void split_pair(float v, bf16& hi, bf16& lo) {
    hi = __float2bfloat16(v);
    lo = __float2bfloat16(v - __bfloat162float(hi));
}
__device__ __forceinline__ float2 unpack_pair(uint32_t h2, uint32_t l2) {
    __nv_bfloat162 th = *reinterpret_cast<__nv_bfloat162*>(&h2);
    __nv_bfloat162 tl = *reinterpret_cast<__nv_bfloat162*>(&l2);
    return make_float2(__bfloat162float(th.x) + __bfloat162float(tl.x),
                       __bfloat162float(th.y) + __bfloat162float(tl.y));
}
__device__ __forceinline__ uint32_t smem_u32(const void* p) {
    return (uint32_t)__cvta_generic_to_shared(p);
}
__device__ __forceinline__ void cp_async16(uint32_t dst, const void* src, bool pred) {
    int sz = pred ? 16 : 0;
    asm volatile("cp.async.cg.shared.global [%0], [%1], 16, %2;\n"
                 :: "r"(dst), "l"(src), "r"(sz));
}

#define LDSM4(r0, r1, r2, r3, addr) \
    asm volatile("ldmatrix.sync.aligned.m8n8.x4.shared.b16 {%0,%1,%2,%3}, [%4];" \
                 : "=r"(r0), "=r"(r1), "=r"(r2), "=r"(r3) : "r"(addr))

#define LDSM4T(r0, r1, r2, r3, addr) \
    asm volatile("ldmatrix.sync.aligned.m8n8.x4.trans.shared.b16 {%0,%1,%2,%3}, [%4];" \
                 : "=r"(r0), "=r"(r1), "=r"(r2), "=r"(r3) : "r"(addr))

#define MMA16816(c4, a0, a1, a2, a3, b0, b1) \
    asm volatile( \
        "mma.sync.aligned.m16n8k16.row.col.f32.bf16.bf16.f32 " \
        "{%0,%1,%2,%3}, {%4,%5,%6,%7}, {%8,%9}, {%0,%1,%2,%3};\n" \
        : "+f"((c4)[0]), "+f"((c4)[1]), "+f"((c4)[2]), "+f"((c4)[3]) \
        : "r"(a0), "r"(a1), "r"(a2), "r"(a3), "r"(b0), "r"(b1))

// =====================================================================
// bf16 hi/lo 3-product HMMA GEMM (champion config: BK=32, 2-stage)
// bias is applied only by batch-index hh==0 (K-split safe).
// =====================================================================
extern __shared__ __align__(16) char smem_raw[];

template<int MTW>
__global__ __launch_bounds__(256, 4 / MTW)
void mma_gemm_kernel(const bf16* __restrict__ Ah_g, const bf16* __restrict__ Al_g,
                     const bf16* __restrict__ Bh_g, const bf16* __restrict__ Bl_g,
                     float* Cf, bf16* Chi, bf16* Clo,
                     const float* __restrict__ bias,
                     int M, int N, int K, int lda, int ldb, int ldc,
                     long sAb, long sAh2, long sBb, long sBh2, long sCb, long sCh2,
                     int nh, int epi)
{
    constexpr int TILE_M  = MTW * 32;
    constexpr int A_BYTES = TILE_M * 80;
    constexpr int OFF_BH  = 2 * A_BYTES;
    constexpr int B_BYTES = 128 * 80;
    constexpr int STAGE   = 2 * A_BYTES + 2 * B_BYTES;
    constexpr int ACH     = TILE_M * 4;
    constexpr int TOT_CH  = 2 * ACH + 1024;
    constexpr int NIT     = TOT_CH / 256;

    int z  = blockIdx.z;
    int bb = z / nh, hh = z % nh;
    long aoff = (long)bb * sAb + (long)hh * sAh2;
    long boff = (long)bb * sBb + (long)hh * sBh2;
    long coff = (long)bb * sCb + (long)hh * sCh2;
    Ah_g += aoff; Al_g += aoff; Bh_g += boff; Bl_g += boff;
    if (Cf)  Cf  += coff;
    if (Chi) { Chi += coff; Clo += coff; }
    if (hh != 0) bias = nullptr;

    const int m0 = blockIdx.y * TILE_M;
    const int n0 = blockIdx.x * 128;

    const int tid  = threadIdx.x;
    const int warp = tid >> 5;
    const int lane = tid & 31;
    const int grp  = lane >> 2;
    const int tig  = lane & 3;
    const int mbase = (warp >> 2) * (MTW * 16);
    const int nbase = (warp & 3) * 32;

    const uint32_t dynbase = smem_u32(smem_raw);

    float acc[MTW][4][4];
    #pragma unroll
    for (int i = 0; i < MTW; i++)
        #pragma unroll
        for (int j = 0; j < 4; j++)
            #pragma unroll
            for (int r = 0; r < 4; r++) acc[i][j][r] = 0.f;

    const int KT = K >> 5;

    auto load_stage = [&](int s, int kt) {
        const int k0 = kt << 5;
        const uint32_t sb = dynbase + s * STAGE;
        #pragma unroll
        for (int i = 0; i < NIT; i++) {
            int idx = tid + i * 256;
            if (idx < 2 * ACH) {
                int arr = idx / ACH;
                int rem = idx - arr * ACH;
                int row = rem >> 2;
                int c16 = rem & 3;
                uint32_t dst = sb + arr * A_BYTES + row * 80 + c16 * 16;
                const bf16* src = (arr ? Al_g : Ah_g)
                                + (long)(m0 + row) * lda + k0 + c16 * 8;
                cp_async16(dst, src, true);
            } else {
                int idxb = idx - 2 * ACH;
                int arr = idxb >> 9;
                int rem = idxb & 511;
                int row = rem >> 2;
                int c16 = rem & 3;
                uint32_t dst = sb + OFF_BH + arr * B_BYTES + row * 80 + c16 * 16;
                int nr = n0 + row;
                bool p = nr < N;
                const bf16* src = (arr ? Bl_g : Bh_g)
                                + (long)(p ? nr : 0) * ldb + k0 + c16 * 8;
                cp_async16(dst, src, p);
            }
        }
        asm volatile("cp.async.commit_group;\n");
    };

    load_stage(0, 0);

    const int a_row = mbase + (lane & 15);
    const int a_kof = (lane >> 4) << 3;
    const int b_row = nbase + ((lane >> 4) << 3) + (lane & 7);
    const int b_kof = ((lane >> 3) & 1) << 3;

    for (int kt = 0; kt < KT; kt++) {
        const int cur = kt & 1;
        if (kt + 1 < KT) {
            load_stage(cur ^ 1, kt + 1);
            asm volatile("cp.async.wait_group 1;\n");
        } else {
            asm volatile("cp.async.wait_group 0;\n");
        }
        __syncthreads();

        const uint32_t sA = dynbase + cur * STAGE;
        const uint32_t sB = sA + OFF_BH;

        #pragma unroll
        for (int kk = 0; kk < 2; kk++) {
            const int kc = kk * 16;
            uint32_t ah[MTW][4], al[MTW][4], bh[4][2], bl[4][2];

            const uint32_t aaddr = sA + (uint32_t)(a_row * 80 + (kc + a_kof) * 2);
            #pragma unroll
            for (int mt = 0; mt < MTW; mt++) {
                LDSM4(ah[mt][0], ah[mt][1], ah[mt][2], ah[mt][3], aaddr + mt * (16 * 80));
                LDSM4(al[mt][0], al[mt][1], al[mt][2], al[mt][3],
                      aaddr + A_BYTES + mt * (16 * 80));
            }
            const uint32_t baddr = sB + (uint32_t)(b_row * 80 + (kc + b_kof) * 2);
            #pragma unroll
            for (int p = 0; p < 2; p++) {
                LDSM4(bh[2*p][0], bh[2*p][1], bh[2*p+1][0], bh[2*p+1][1],
                      baddr + p * (16 * 80));
                LDSM4(bl[2*p][0], bl[2*p][1], bl[2*p+1][0], bl[2*p+1][1],
                      baddr + B_BYTES + p * (16 * 80));
            }

            #pragma unroll
            for (int mt = 0; mt < MTW; mt++) {
                #pragma unroll
                for (int nt = 0; nt < 4; nt++) {
                    float* c4 = acc[mt][nt];
                    MMA16816(c4, ah[mt][0], ah[mt][1], ah[mt][2], ah[mt][3],
                             bh[nt][0], bh[nt][1]);
                    MMA16816(c4, ah[mt][0], ah[mt][1], ah[mt][2], ah[mt][3],
                             bl[nt][0], bl[nt][1]);
                    MMA16816(c4, al[mt][0], al[mt][1], al[mt][2], al[mt][3],
                             bh[nt][0], bh[nt][1]);
                }
            }
        }
        __syncthreads();
    }

    // ---- epilogue ----
    #pragma unroll
    for (int mt = 0; mt < MTW; mt++) {
        #pragma unroll
        for (int nt = 0; nt < 4; nt++) {
            int nc = n0 + nbase + nt * 8 + 2 * tig;
            if (nc >= N) continue;
            float* c4 = acc[mt][nt];
            #pragma unroll
            for (int rr = 0; rr < 2; rr++) {
                int m = m0 + mbase + mt * 16 + grp + rr * 8;
                float v0 = c4[rr * 2], v1 = c4[rr * 2 + 1];
                if (bias) { v0 += bias[nc]; v1 += bias[nc + 1]; }
                if (epi == 1) { v0 = gelu_f(v0); v1 = gelu_f(v1); }
                long idx = (long)m * ldc + nc;
                if (epi == 2) {
                    float2 old = *(const float2*)&Cf[idx];
                    v0 += old.x; v1 += old.y;
                }
                if (Cf) *(float2*)&Cf[idx] = make_float2(v0, v1);
                if (Chi) {
                    bf16 h0, l0, h1, l1;
                    split_pair(v0, h0, l0);
                    split_pair(v1, h1, l1);
                    __nv_bfloat162 th = __halves2bfloat162(h0, h1);
                    __nv_bfloat162 tl = __halves2bfloat162(l0, l1);
                    *(uint32_t*)&Chi[idx] = *(uint32_t*)&th;
                    *(uint32_t*)&Clo[idx] = *(uint32_t*)&tl;
                }
            }
        }
    }
}

#define DYN_SMEM_M128 (2 * (2 * 128 * 80 + 2 * 128 * 80))   // 81920
#define DYN_SMEM_M64  (2 * (2 * 64 * 80 + 2 * 128 * 80))    // 61440

// =====================================================================
// Fused flash attention (champion config: K-block 128, 1 CTA/SM).
// =====================================================================
#define FQ_ROWB   144
#define FA_QL     18432
#define FA_ST0    36864
#define FA_ARR    18432
#define FA_STAGE  (4*FA_ARR)
#define FA_SMEM   (FA_ST0 + 2*FA_STAGE)   // 184320

__global__ __launch_bounds__(256, 1)
void flash_attn_kernel(const bf16* __restrict__ qkvh, const bf16* __restrict__ qkvl,
                       bf16* __restrict__ oh, bf16* __restrict__ ol)
{
    const int bh = blockIdx.y;
    const int b  = bh / NHEADS;
    const int h  = bh % NHEADS;
    const int q0 = blockIdx.x * 128;

    const int tid  = threadIdx.x;
    const int warp = tid >> 5;
    const int lane = tid & 31;
    const int qbase = warp * 16;

    const uint32_t dyn = smem_u32(smem_raw);

    const bf16* qh_g = qkvh + ((long)(b * NTOK + q0)) * (3 * CDIM) + h * HEADD;
    const bf16* ql_g = qkvl + ((long)(b * NTOK + q0)) * (3 * CDIM) + h * HEADD;

    #pragma unroll
    for (int i = 0; i < 8; i++) {
        int idx = tid + i * 256;
        int arr = idx >> 10;
        int rem = idx & 1023;
        int row = rem >> 3;
        int c   = rem & 7;
        uint32_t dst = dyn + arr * FA_QL + row * FQ_ROWB + c * 16;
        const bf16* src = (arr ? ql_g : qh_g) + (long)row * (3 * CDIM) + c * 8;
        cp_async16(dst, src, true);
    }

    auto load_kv = [&](int s, int j) {
        const long keybase = (long)(b * NTOK + j * 128);
        const uint32_t sb = dyn + FA_ST0 + s * FA_STAGE;
        #pragma unroll
        for (int i = 0; i < 16; i++) {
            int idx = tid + i * 256;
            int arr = idx >> 10;
            int rem = idx & 1023;
            int row = rem >> 3;
            int c   = rem & 7;
            uint32_t dst = sb + arr * FA_ARR + row * FQ_ROWB + c * 16;
            const bf16* base = ((arr & 1) ? qkvl : qkvh);
            int sect = (arr < 2) ? CDIM : 2 * CDIM;
            const bf16* src = base + (keybase + row) * (3 * CDIM) + sect + h * HEADD + c * 8;
            cp_async16(dst, src, true);
        }
        asm volatile("cp.async.commit_group;\n");
    };

    load_kv(0, 0);

    float o[8][4];
    #pragma unroll
    for (int i = 0; i < 8; i++)
        #pragma unroll
        for (int r = 0; r < 4; r++) o[i][r] = 0.f;
    float m_i[2] = { -1e30f, -1e30f };
    float l_i[2] = { 0.f, 0.f };

    uint32_t qh_f[4][4], ql_f[4][4];
    const int a_row = qbase + (lane & 15);
    const int a_kof = (lane >> 4) << 3;
    const int b_row = ((lane >> 4) << 3) + (lane & 7);
    const int b_kof = ((lane >> 3) & 1) << 3;
    const int v_row = (((lane >> 3) & 1) << 3) + (lane & 7);
    const int v_dof = (lane >> 4) << 3;

    for (int j = 0; j < 8; j++) {
        const int cur = j & 1;
        if (j + 1 < 8) {
            load_kv(cur ^ 1, j + 1);
            asm volatile("cp.async.wait_group 1;\n");
        } else {
            asm volatile("cp.async.wait_group 0;\n");
        }
        __syncthreads();

        if (j == 0) {
            #pragma unroll
            for (int kk = 0; kk < 4; kk++) {
                uint32_t qaddr = dyn + (uint32_t)(a_row * FQ_ROWB + (kk * 16 + a_kof) * 2);
                LDSM4(qh_f[kk][0], qh_f[kk][1], qh_f[kk][2], qh_f[kk][3], qaddr);
                LDSM4(ql_f[kk][0], ql_f[kk][1], ql_f[kk][2], ql_f[kk][3], qaddr + FA_QL);
            }
        }

        const uint32_t kb = dyn + FA_ST0 + cur * FA_STAGE;
        const uint32_t vb = kb + 2 * FA_ARR;

        float s[16][4];
        #pragma unroll
        for (int i = 0; i < 16; i++)
            #pragma unroll
            for (int r = 0; r < 4; r++) s[i][r] = 0.f;

        #pragma unroll
        for (int np = 0; np < 8; np++) {
            #pragma unroll
            for (int kk = 0; kk < 4; kk++) {
                uint32_t kaddr = kb + (uint32_t)((np * 16 + b_row) * FQ_ROWB
                                                 + (kk * 16 + b_kof) * 2);
                uint32_t kh0, kh1, kh2, kh3, kl0, kl1, kl2, kl3;
                LDSM4(kh0, kh1, kh2, kh3, kaddr);
                LDSM4(kl0, kl1, kl2, kl3, kaddr + FA_ARR);
                float* c0 = s[2*np];
                float* c1 = s[2*np+1];
                MMA16816(c0, qh_f[kk][0], qh_f[kk][1], qh_f[kk][2], qh_f[kk][3], kh0, kh1);
                MMA16816(c0, qh_f[kk][0], qh_f[kk][1], qh_f[kk][2], qh_f[kk][3], kl0, kl1);
                MMA16816(c0, ql_f[kk][0], ql_f[kk][1], ql_f[kk][2], ql_f[kk][3], kh0, kh1);
                MMA16816(c1, qh_f[kk][0], qh_f[kk][1], qh_f[kk][2], qh_f[kk][3], kh2, kh3);
                MMA16816(c1, qh_f[kk][0], qh_f[kk][1], qh_f[kk][2], qh_f[kk][3], kl2, kl3);
                MMA16816(c1, ql_f[kk][0], ql_f[kk][1], ql_f[kk][2], ql_f[kk][3], kh2, kh3);
            }
        }

        #pragma unroll
        for (int rr = 0; rr < 2; rr++) {
            float mx = -1e30f;
            #pragma unroll
            for (int nt = 0; nt < 16; nt++)
                mx = fmaxf(mx, fmaxf(s[nt][rr*2], s[nt][rr*2+1]));
            mx = fmaxf(mx, __shfl_xor_sync(~0u, mx, 1));
            mx = fmaxf(mx, __shfl_xor_sync(~0u, mx, 2));
            float m_new = fmaxf(m_i[rr], mx);
            float alpha = __expf(SCALE_F * (m_i[rr] - m_new));
            m_i[rr] = m_new;
            l_i[rr] *= alpha;
            float psum = 0.f;
            #pragma unroll
            for (int nt = 0; nt < 16; nt++) {
                float p0 = __expf(SCALE_F * (s[nt][rr*2]     - m_new));
                float p1 = __expf(SCALE_F * (s[nt][rr*2 + 1] - m_new));
                s[nt][rr*2]     = p0;
                s[nt][rr*2 + 1] = p1;
                psum += p0 + p1;
            }
            l_i[rr] += psum;
            #pragma unroll
            for (int nt = 0; nt < 8; nt++) {
                o[nt][rr*2]     *= alpha;
                o[nt][rr*2 + 1] *= alpha;
            }
        }

        #pragma unroll
        for (int ks = 0; ks < 8; ks++) {
            uint32_t pah[4], pal[4];
            #pragma unroll
            for (int q = 0; q < 4; q++) {
                int nt = 2 * ks + (q >> 1);
                int base = (q & 1) * 2;
                bf16 h0, l0, h1, l1;
                split_pair(s[nt][base],     h0, l0);
                split_pair(s[nt][base + 1], h1, l1);
                __nv_bfloat162 th = __halves2bfloat162(h0, h1);
                __nv_bfloat162 tl = __halves2bfloat162(l0, l1);
                pah[q] = *(uint32_t*)&th;
                pal[q] = *(uint32_t*)&tl;
            }
            #pragma unroll
            for (int np = 0; np < 4; np++) {
                uint32_t vaddr = vb + (uint32_t)((ks * 16 + v_row) * FQ_ROWB
                                                 + (np * 16 + v_dof) * 2);
                uint32_t vh0, vh1, vh2, vh3, vl0, vl1, vl2, vl3;
                LDSM4T(vh0, vh1, vh2, vh3, vaddr);
                LDSM4T(vl0, vl1, vl2, vl3, vaddr + FA_ARR);
                float* c0 = o[2*np];
                float* c1 = o[2*np+1];
                MMA16816(c0, pah[0], pah[1], pah[2], pah[3], vh0, vh1);
                MMA16816(c0, pah[0], pah[1], pah[2], pah[3], vl0, vl1);
                MMA16816(c0, pal[0], pal[1], pal[2], pal[3], vh0, vh1);
                MMA16816(c1, pah[0], pah[1], pah[2], pah[3], vh2, vh3);
                MMA16816(c1, pah[0], pah[1], pah[2], pah[3], vl2, vl3);
                MMA16816(c1, pal[0], pal[1], pal[2], pal[3], vh2, vh3);
            }
        }
        __syncthreads();
    }

    float inv[2];
    #pragma unroll
    for (int rr = 0; rr < 2; rr++) {
        float l = l_i[rr];
        l += __shfl_xor_sync(~0u, l, 1);
        l += __shfl_xor_sync(~0u, l, 2);
        inv[rr] = 1.f / l;
    }

    const int r = lane >> 2;
    const int t = lane & 3;
    #pragma unroll
    for (int nt = 0; nt < 8; nt++) {
        #pragma unroll
        for (int rr = 0; rr < 2; rr++) {
            int qr = q0 + qbase + r + rr * 8;
            float v0 = o[nt][rr*2]     * inv[rr];
            float v1 = o[nt][rr*2 + 1] * inv[rr];
            bf16 h0, l0, h1, l1;
            split_pair(v0, h0, l0);
            split_pair(v1, h1, l1);
            __nv_bfloat162 th = __halves2bfloat162(h0, h1);
            __nv_bfloat162 tl = __halves2bfloat162(l0, l1);
            long idx = ((long)(b * NTOK + qr)) * CDIM + h * HEADD + nt * 8 + 2 * t;
            *(uint32_t*)&oh[idx] = *(uint32_t*)&th;
            *(uint32_t*)&ol[idx] = *(uint32_t*)&tl;
        }
    }
}

// =====================================================================
// f32 -> bf16 hi/lo pair conversion, float4-vectorized
// =====================================================================
__global__ void cvt_pair4_kernel(const float* __restrict__ in,
                                 bf16* __restrict__ hi, bf16* __restrict__ lo, long n4)
{
    long i = (long)blockIdx.x * blockDim.x + threadIdx.x;
    if (i >= n4) return;
    float4 v = ((const float4*)in)[i];
    bf16 h[4], l[4];
    split_pair(v.x, h[0], l[0]); split_pair(v.y, h[1], l[1]);
    split_pair(v.z, h[2], l[2]); split_pair(v.w, h[3], l[3]);
    __nv_bfloat162 h01 = __halves2bfloat162(h[0], h[1]);
    __nv_bfloat162 h23 = __halves2bfloat162(h[2], h[3]);
    __nv_bfloat162 l01 = __halves2bfloat162(l[0], l[1]);
    __nv_bfloat162 l23 = __halves2bfloat162(l[2], l[3]);
    ((uint2*)hi)[i] = make_uint2(*(uint32_t*)&h01, *(uint32_t*)&h23);
    ((uint2*)lo)[i] = make_uint2(*(uint32_t*)&l01, *(uint32_t*)&l23);
}

// =====================================================================
// im2col producing bf16 pairs
// =====================================================================
__global__ void im2col_kernel(const float* __restrict__ x,
                              bf16* __restrict__ ch, bf16* __restrict__ cl)
{
    long idx = (long)blockIdx.x * blockDim.x + threadIdx.x;
    if (idx >= (long)MROWS * CDIM) return;
    int k = (int)(idx % CDIM);
    int m = (int)(idx / CDIM);
    int b  = m >> 10;
    int n  = m & 1023;
    int hp = n >> 5, wp = n & 31;
    int ci = k >> 8;
    int r  = k & 255;
    int ky = r >> 4, kx = r & 15;
    long src = (((long)(b * 3 + ci) * IMG) + hp * PS + ky) * IMG + wp * PS + kx;
    bf16 h, l; split_pair(x[src], h, l);
    ch[idx] = h; cl[idx] = l;
}

// =====================================================================
// LayerNorm producing bf16 pairs.
// COMBINE variant: in = gx + p0 + p1 (fc2 partials), writes gx back.
// =====================================================================
template<bool COMBINE>
__global__ void layernorm_kernel(float* __restrict__ gx,
                                 const float* __restrict__ p0,
                                 const float* __restrict__ p1,
                                 bf16* __restrict__ oh, bf16* __restrict__ ol,
                                 const float* __restrict__ s, const float* __restrict__ b)
{
    __shared__ float red[8];
    const long row = blockIdx.x;
    int tid = threadIdx.x, lane = tid & 31, w = tid >> 5;

    float v[3];
    float sum = 0.f;
    #pragma unroll
    for (int j = 0; j < 3; j++) {
        long idx = row * CDIM + tid + j * 256;
        float t = gx[idx];
        if (COMBINE) {
            t += p0[idx] + p1[idx];
            gx[idx] = t;
        }
        v[j] = t; sum += t;
    }
    #pragma unroll
    for (int off = 16; off; off >>= 1) sum += __shfl_xor_sync(~0u, sum, off);
    if (lane == 0) red[w] = sum;
    __syncthreads();
    if (w == 0) {
        float t = (lane < 8) ? red[lane] : 0.f;
        #pragma unroll
        for (int off = 4; off; off >>= 1) t += __shfl_xor_sync(~0u, t, off);
        if (lane == 0) red[0] = t;
    }
    __syncthreads();
    float mu = red[0] * (1.f / CDIM);
    __syncthreads();

    float sq = 0.f;
    #pragma unroll
    for (int j = 0; j < 3; j++) { float d = v[j] - mu; sq += d * d; }
    #pragma unroll
    for (int off = 16; off; off >>= 1) sq += __shfl_xor_sync(~0u, sq, off);
    if (lane == 0) red[w] = sq;
    __syncthreads();
    if (w == 0) {
        float t = (lane < 8) ? red[lane] : 0.f;
        #pragma unroll
        for (int off = 4; off; off >>= 1) t += __shfl_xor_sync(~0u, t, off);
        if (lane == 0) red[0] = t;
    }
    __syncthreads();
    float rstd = rsqrtf(red[0] * (1.f / CDIM) + EPS_F);

    #pragma unroll
    for (int j = 0; j < 3; j++) {
        int c = tid + j * 256;
        float o = (v[j] - mu) * rstd * s[c] + b[c];
        bf16 h, l; split_pair(o, h, l);
        oh[row * CDIM + c] = h; ol[row * CDIM + c] = l;
    }
}

// =====================================================================
// Fused deformable attention: one warp per (b, h, n).
// =====================================================================
__global__ void deform_attn_kernel(const bf16* __restrict__ qkvh,
                                   const bf16* __restrict__ qkvl,
                                   const float* __restrict__ offs4,
                                   const float* __restrict__ offs_b,
                                   bf16* __restrict__ oh, bf16* __restrict__ ol)
{
    int gwarp = (blockIdx.x * blockDim.x + threadIdx.x) >> 5;
    int lane  = threadIdx.x & 31;
    if (gwarp >= BB * NHEADS * NTOK) return;
    int n  = gwarp & (NTOK - 1);
    int bh = gwarp >> 10;
    int h  = bh % NHEADS;
    int b  = bh / NHEADS;
    int hp = n >> 5, wp = n & 31;

    const long rowoff = ((long)(b * NTOK + n)) * (3 * CDIM) + h * HEADD + 2 * lane;
    float2 q = unpack_pair(*(const uint32_t*)&qkvh[rowoff],
                           *(const uint32_t*)&qkvl[rowoff]);

    const long offbase = ((long)(b * NTOK + n)) * 96 + h * NPTS * 2;
    const long CH = (long)MROWS * 96;

    float att[NPTS], sv0[NPTS], sv1[NPTS];

    #pragma unroll
    for (int p = 0; p < NPTS; p++) {
        long oidx = offbase + p * 2;
        float ox = offs4[oidx]            + offs4[oidx + CH]
                 + offs4[oidx + 2 * CH]   + offs4[oidx + 3 * CH]
                 + offs_b[h * NPTS * 2 + p * 2];
        float oy = offs4[oidx + 1]        + offs4[oidx + 1 + CH]
                 + offs4[oidx + 1 + 2*CH] + offs4[oidx + 1 + 3*CH]
                 + offs_b[h * NPTS * 2 + p * 2 + 1];
        float gx = (wp + 0.5f) * (1.f / HP) + ox * (1.f / HP);
        float gy = (hp + 0.5f) * (1.f / HP) + oy * (1.f / HP);
        float px = (2.f * gx) * (HP * 0.5f) - 0.5f;
        float py = (2.f * gy) * (HP * 0.5f) - 0.5f;
        float x0f = floorf(px), y0f = floorf(py);
        float wx = px - x0f, wy = py - y0f;
        int x0 = (int)x0f, y0 = (int)y0f;
        float cw[4] = { (1.f - wx) * (1.f - wy), wx * (1.f - wy),
                        (1.f - wx) * wy,         wx * wy };

        float k0 = 0.f, k1 = 0.f, v0 = 0.f, v1 = 0.f;
        #pragma unroll
        for (int c = 0; c < 4; c++) {
            int yi = y0 + (c >> 1);
            int xi = x0 + (c & 1);
            if (yi >= 0 && yi < HP && xi >= 0 && xi < HP) {
                long base = ((long)(b * NTOK + yi * HP + xi)) * (3 * CDIM)
                          + CDIM + h * HEADD + 2 * lane;
                float2 kv = unpack_pair(*(const uint32_t*)&qkvh[base],
                                        *(const uint32_t*)&qkvl[base]);
                float2 vv = unpack_pair(*(const uint32_t*)&qkvh[base + CDIM],
                                        *(const uint32_t*)&qkvl[base + CDIM]);
                float wc = cw[c];
                k0 += wc * kv.x;  k1 += wc * kv.y;
                v0 += wc * vv.x;  v1 += wc * vv.y;
            }
        }
        sv0[p] = v0; sv1[p] = v1;
        float d = q.x * k0 + q.y * k1;
        #pragma unroll
        for (int off = 16; off; off >>= 1) d += __shfl_xor_sync(~0u, d, off);
        att[p] = d * SCALE_F;
    }

    float mx = fmaxf(fmaxf(att[0], att[1]), fmaxf(att[2], att[3]));
    float e[NPTS], sum = 0.f;
    #pragma unroll
    for (int p = 0; p < NPTS; p++) { e[p] = __expf(att[p] - mx); sum += e[p]; }
    float inv = 1.f / sum;

    float o0 = 0.f, o1 = 0.f;
    #pragma unroll
    for (int p = 0; p < NPTS; p++) {
        float a = e[p] * inv;
        o0 += a * sv0[p];
        o1 += a * sv1[p];
    }
    long base = ((long)(b * NTOK + n)) * CDIM + h * HEADD + 2 * lane;
    bf16 h0, l0, h1, l1;
    split_pair(o0, h0, l0);
    split_pair(o1, h1, l1);
    __nv_bfloat162 th = __halves2bfloat162(h0, h1);
    __nv_bfloat162 tl = __halves2bfloat162(l0, l1);
    *(uint32_t*)&oh[base] = *(uint32_t*)&th;
    *(uint32_t*)&ol[base] = *(uint32_t*)&tl;
}

// =====================================================================
// Output transpose with fc2-partial combine: (B,N,C) -> (B,C,Hp,Wp)
// =====================================================================
__global__ void out_transpose_combine_kernel(const float* __restrict__ x,
                                             const float* __restrict__ p0,
                                             const float* __restrict__ p1,
                                             float* __restrict__ out)
{
    long idx = (long)blockIdx.x * blockDim.x + threadIdx.x;
    if (idx >= (long)MROWS * CDIM) return;
    int n = (int)(idx % NTOK);
    int c = (int)((idx / NTOK) % CDIM);
    int b = (int)(idx / ((long)NTOK * CDIM));
    long src = ((long)(b * NTOK + n)) * CDIM + c;
    out[idx] = x[src] + p0[src] + p1[src];
}

// =====================================================================
// Host launcher
// =====================================================================
extern "C" void kernel_launch(void* const* d_in, const int* in_sizes, int n_in,
                              void* d_out, int out_size)
{
    const float* x       = (const float*)d_in[0];
    const float* patch_w = (const float*)d_in[1];
    const float* patch_b = (const float*)d_in[2];
    const float* ln1_s   = (const float*)d_in[3];
    const float* ln1_b   = (const float*)d_in[4];
    const float* qkv_w   = (const float*)d_in[5];
    const float* offs_w  = (const float*)d_in[6];
    const float* offs_b  = (const float*)d_in[7];
    const float* proj_w  = (const float*)d_in[8];
    const float* proj_b  = (const float*)d_in[9];
    const float* ln2_s   = (const float*)d_in[10];
    const float* ln2_b   = (const float*)d_in[11];
    const float* fc1_w   = (const float*)d_in[12];
    const float* fc1_b   = (const float*)d_in[13];
    const float* fc2_w   = (const float*)d_in[14];
    const float* fc2_b   = (const float*)d_in[15];

    cudaFuncSetAttribute(mma_gemm_kernel<4>,
                         cudaFuncAttributeMaxDynamicSharedMemorySize, DYN_SMEM_M128);
    cudaFuncSetAttribute(mma_gemm_kernel<2>,
                         cudaFuncAttributeMaxDynamicSharedMemorySize, DYN_SMEM_M64);
    cudaFuncSetAttribute(flash_attn_kernel,
                         cudaFuncAttributeMaxDynamicSharedMemorySize, FA_SMEM);

    float *gx, *goffs4, *gf2p;
    bf16 *ghh,*ghl,*gcolh,*gcoll,*gqkvh,*gqkvl,*gaoh,*gaol;
    bf16 *gmlph,*gmlpl;
    bf16 *pwh,*pwl,*qwh,*qwl,*owh,*owl,*jwh,*jwl,*f1h,*f1l,*f2h,*f2l;
    cudaGetSymbolAddress((void**)&gx,     g_x);
    cudaGetSymbolAddress((void**)&goffs4, g_offs4);
    cudaGetSymbolAddress((void**)&gf2p,   g_f2p);
    cudaGetSymbolAddress((void**)&ghh,   g_hh);   cudaGetSymbolAddress((void**)&ghl,   g_hl);
    cudaGetSymbolAddress((void**)&gcolh, g_colh); cudaGetSymbolAddress((void**)&gcoll, g_coll);
    cudaGetSymbolAddress((void**)&gqkvh, g_qkvh); cudaGetSymbolAddress((void**)&gqkvl, g_qkvl);
    cudaGetSymbolAddress((void**)&gaoh,  g_aoh);  cudaGetSymbolAddress((void**)&gaol,  g_aol);
    cudaGetSymbolAddress((void**)&gmlph, g_mlph); cudaGetSymbolAddress((void**)&gmlpl, g_mlpl);
    cudaGetSymbolAddress((void**)&pwh, g_pwh); cudaGetSymbolAddress((void**)&pwl, g_pwl);
    cudaGetSymbolAddress((void**)&qwh, g_qwh); cudaGetSymbolAddress((void**)&qwl, g_qwl);
    cudaGetSymbolAddress((void**)&owh, g_owh); cudaGetSymbolAddress((void**)&owl, g_owl);
    cudaGetSymbolAddress((void**)&jwh, g_jwh); cudaGetSymbolAddress((void**)&jwl, g_jwl);
    cudaGetSymbolAddress((void**)&f1h, g_f1h); cudaGetSymbolAddress((void**)&f1l, g_f1l);
    cudaGetSymbolAddress((void**)&f2h, g_f2h); cudaGetSymbolAddress((void**)&f2l, g_f2l);

    const int M = MROWS;
    float* gf2p1 = gf2p + (long)MROWS * CDIM;

    // ---- weight conversion (vectorized) ----
    {
        long n1 = (long)CDIM * CDIM / 4;
        cvt_pair4_kernel<<<(int)((n1 + 255) / 256), 256>>>(patch_w, pwh, pwl, n1);
        long n2 = 6L * 3 * CDIM * CDIM / 4;
        cvt_pair4_kernel<<<(int)((n2 + 255) / 256), 256>>>(qkv_w, qwh, qwl, n2);
        long n3 = 6L * 96 * CDIM / 4;
        cvt_pair4_kernel<<<(int)((n3 + 255) / 256), 256>>>(offs_w, owh, owl, n3);
        long n4 = 6L * CDIM * CDIM / 4;
        cvt_pair4_kernel<<<(int)((n4 + 255) / 256), 256>>>(proj_w, jwh, jwl, n4);
        long n5 = 6L * 4 * CDIM * CDIM / 4;
        cvt_pair4_kernel<<<(int)((n5 + 255) / 256), 256>>>(fc1_w, f1h, f1l, n5);
        cvt_pair4_kernel<<<(int)((n5 + 255) / 256), 256>>>(fc2_w, f2h, f2l, n5);
    }

    // ---- patch embed (M64: 192 CTAs) ----
    im2col_kernel<<<(M * CDIM + 255) / 256, 256>>>(x, gcolh, gcoll);
    mma_gemm_kernel<2><<<dim3(6, M / 64, 1), 256, DYN_SMEM_M64>>>(
        gcolh, gcoll, pwh, pwl, gx, nullptr, nullptr, patch_b,
        M, CDIM, CDIM, CDIM, CDIM, CDIM,
        0, 0, 0, 0, 0, 0, 1, 0);

    for (int i = 0; i < 6; i++) {
        // LN1: layer 0 reads plain gx; layers >=1 fold in fc2 partials and update gx
        if (i == 0)
            layernorm_kernel<false><<<M, 256>>>(gx, nullptr, nullptr, ghh, ghl,
                                                ln1_s + i * CDIM, ln1_b + i * CDIM);
        else
            layernorm_kernel<true><<<M, 256>>>(gx, gf2p, gf2p1, ghh, ghl,
                                               ln1_s + i * CDIM, ln1_b + i * CDIM);

        // QKV (M128: 288 CTAs)
        mma_gemm_kernel<4><<<dim3(18, M / 128, 1), 256, DYN_SMEM_M128>>>(
            ghh, ghl, qwh + (long)i * 2304 * CDIM, qwl + (long)i * 2304 * CDIM,
            nullptr, gqkvh, gqkvl, nullptr,
            M, 2304, CDIM, CDIM, CDIM, 2304,
            0, 0, 0, 0, 0, 0, 1, 0);

        bool sample = ((i + 1) % 3) != 0;
        if (sample) {
            // offsets: K-split x4 (128 CTAs)
            mma_gemm_kernel<2><<<dim3(1, M / 64, KSPLIT), 256, DYN_SMEM_M64>>>(
                gqkvh, gqkvl, owh + (long)i * 96 * CDIM, owl + (long)i * 96 * CDIM,
                goffs4, nullptr, nullptr, nullptr,
                M, 96, CDIM / KSPLIT, 3 * CDIM, CDIM, 96,
                0, CDIM / KSPLIT,
                0, CDIM / KSPLIT,
                0, (long)MROWS * 96,
                KSPLIT, 0);
            deform_attn_kernel<<<(BB * NHEADS * NTOK * 32) / 256, 256>>>(
                gqkvh, gqkvl, goffs4, offs_b + i * 96, gaoh, gaol);
        } else {
            flash_attn_kernel<<<dim3(NTOK / 128, BB * NHEADS, 1), 256, FA_SMEM>>>(
                gqkvh, gqkvl, gaoh, gaol);
        }

        // proj + residual (M64: 192 CTAs)
        mma_gemm_kernel<2><<<dim3(6, M / 64, 1), 256, DYN_SMEM_M64>>>(
            gaoh, gaol, jwh + (long)i * CDIM * CDIM, jwl + (long)i * CDIM * CDIM,
            gx, nullptr, nullptr, proj_b + i * CDIM,
            M, CDIM, CDIM, CDIM, CDIM, CDIM,
            0, 0, 0, 0, 0, 0, 1, 2);

        layernorm_kernel<false><<<M, 256>>>(gx, nullptr, nullptr, ghh, ghl,
                                            ln2_s + i * CDIM, ln2_b + i * CDIM);

        // fc1 + gelu (M128: 384 CTAs)
        mma_gemm_kernel<4><<<dim3(24, M / 128, 1), 256, DYN_SMEM_M128>>>(
            ghh, ghl, f1h + (long)i * 3072 * CDIM, f1l + (long)i * 3072 * CDIM,
            nullptr, gmlph, gmlpl, fc1_b + i * 3072,
            M, 3072, CDIM, CDIM, CDIM, 3072,
            0, 0, 0, 0, 0, 0, 1, 1);

        // fc2: K-split x2 (384 CTAs) into partials; bias on chunk 0;
        // combined into gx by next LN1 (or final transpose for layer 5)
        mma_gemm_kernel<2><<<dim3(6, M / 64, 2), 256, DYN_SMEM_M64>>>(
            gmlph, gmlpl, f2h + (long)i * CDIM * 3072, f2l + (long)i * CDIM * 3072,
            gf2p, nullptr, nullptr, fc2_b + i * CDIM,
            M, CDIM, 3072 / 2, 3072, 3072, CDIM,
            0, 3072 / 2,
            0, 3072 / 2,
            0, (long)MROWS * CDIM,
            2, 0);
    }

    out_transpose_combine_kernel<<<(M * CDIM + 255) / 256, 256>>>(
        gx, gf2p, gf2p1, (float*)d_out);
}

// round 17
// speedup vs baseline: 1.4316x; 1.0231x over previous
#include <cuda_runtime.h>
#include <cuda_bf16.h>
#include <math.h>
#include <cstdint>
#include <cstddef>

// ---------------- problem constants ----------------
#define BB       2
#define IMG      512
#define PS       16
#define HP       32
#define NTOK     1024
#define CDIM     768
#define NHEADS   12
#define HEADD    64
#define NPTS     4
#define SCALE_F  0.125f
#define EPS_F    1e-6f
#define MROWS    (BB*NTOK)   // 2048
#define KSPLIT   4           // offsets GEMM K-split factor

typedef __nv_bfloat16 bf16;

// ---------------- device scratch ----------------
__device__ float g_x    [MROWS*CDIM];
__device__ float g_offs4[KSPLIT*MROWS*96];
__device__ float g_f2p  [2*MROWS*CDIM];      // K-split partials (proj & fc2, time-shared)

__device__ bf16 g_hh  [MROWS*CDIM],      g_hl  [MROWS*CDIM];
__device__ bf16 g_colh[MROWS*CDIM],      g_coll[MROWS*CDIM];
__device__ bf16 g_qkvh[MROWS*3*CDIM],    g_qkvl[MROWS*3*CDIM];
__device__ bf16 g_aoh [MROWS*CDIM],      g_aol [MROWS*CDIM];
__device__ bf16 g_mlph[MROWS*4*CDIM],    g_mlpl[MROWS*4*CDIM];

// weight bf16 hi/lo (converted each launch)
__device__ bf16 g_pwh[CDIM*CDIM],        g_pwl[CDIM*CDIM];
__device__ bf16 g_qwh[6*3*CDIM*CDIM],    g_qwl[6*3*CDIM*CDIM];
__device__ bf16 g_owh[6*96*CDIM],        g_owl[6*96*CDIM];
__device__ bf16 g_jwh[6*CDIM*CDIM],      g_jwl[6*CDIM*CDIM];
__device__ bf16 g_f1h[6*4*CDIM*CDIM],    g_f1l[6*4*CDIM*CDIM];
__device__ bf16 g_f2h[6*4*CDIM*CDIM],    g_f2l[6*4*CDIM*CDIM];

// ---------------- helpers ----------------
__device__ __forceinline__ float gelu_f(float v) {
    return 0.5f * v * (1.0f + erff(v * 0.7071067811865476f));
}
__device__ __forceinline__ void split_pair(float v, bf16& hi, bf16& lo) {
    hi = __float2bfloat16(v);
    lo = __float2bfloat16(v - __bfloat162float(hi));
}
__device__ __forceinline__ float2 unpack_pair(uint32_t h2, uint32_t l2) {
    __nv_bfloat162 th = *reinterpret_cast<__nv_bfloat162*>(&h2);
    __nv_bfloat162 tl = *reinterpret_cast<__nv_bfloat162*>(&l2);
    return make_float2(__bfloat162float(th.x) + __bfloat162float(tl.x),
                       __bfloat162float(th.y) + __bfloat162float(tl.y));
}
__device__ __forceinline__ uint32_t smem_u32(const void* p) {
    return (uint32_t)__cvta_generic_to_shared(p);
}
__device__ __forceinline__ void cp_async16(uint32_t dst, const void* src, bool pred) {
    int sz = pred ? 16 : 0;
    asm volatile("cp.async.cg.shared.global [%0], [%1], 16, %2;\n"
                 :: "r"(dst), "l"(src), "r"(sz));
}

#define LDSM4(r0, r1, r2, r3, addr) \
    asm volatile("ldmatrix.sync.aligned.m8n8.x4.shared.b16 {%0,%1,%2,%3}, [%4];" \
                 : "=r"(r0), "=r"(r1), "=r"(r2), "=r"(r3) : "r"(addr))

#define LDSM4T(r0, r1, r2, r3, addr) \
    asm volatile("ldmatrix.sync.aligned.m8n8.x4.trans.shared.b16 {%0,%1,%2,%3}, [%4];" \
                 : "=r"(r0), "=r"(r1), "=r"(r2), "=r"(r3) : "r"(addr))

#define MMA16816(c4, a0, a1, a2, a3, b0, b1) \
    asm volatile( \
        "mma.sync.aligned.m16n8k16.row.col.f32.bf16.bf16.f32 " \
        "{%0,%1,%2,%3}, {%4,%5,%6,%7}, {%8,%9}, {%0,%1,%2,%3};\n" \
        : "+f"((c4)[0]), "+f"((c4)[1]), "+f"((c4)[2]), "+f"((c4)[3]) \
        : "r"(a0), "r"(a1), "r"(a2), "r"(a3), "r"(b0), "r"(b1))

// =====================================================================
// bf16 hi/lo 3-product HMMA GEMM (champion config: BK=32, 2-stage)
// bias is applied only by batch-index hh==0 (K-split safe).
// =====================================================================
extern __shared__ __align__(16) char smem_raw[];

template<int MTW>
__global__ __launch_bounds__(256, 4 / MTW)
void mma_gemm_kernel(const bf16* __restrict__ Ah_g, const bf16* __restrict__ Al_g,
                     const bf16* __restrict__ Bh_g, const bf16* __restrict__ Bl_g,
                     float* Cf, bf16* Chi, bf16* Clo,
                     const float* __restrict__ bias,
                     int M, int N, int K, int lda, int ldb, int ldc,
                     long sAb, long sAh2, long sBb, long sBh2, long sCb, long sCh2,
                     int nh, int epi)
{
    constexpr int TILE_M  = MTW * 32;
    constexpr int A_BYTES = TILE_M * 80;
    constexpr int OFF_BH  = 2 * A_BYTES;
    constexpr int B_BYTES = 128 * 80;
    constexpr int STAGE   = 2 * A_BYTES + 2 * B_BYTES;
    constexpr int ACH     = TILE_M * 4;
    constexpr int TOT_CH  = 2 * ACH + 1024;
    constexpr int NIT     = TOT_CH / 256;

    int z  = blockIdx.z;
    int bb = z / nh, hh = z % nh;
    long aoff = (long)bb * sAb + (long)hh * sAh2;
    long boff = (long)bb * sBb + (long)hh * sBh2;
    long coff = (long)bb * sCb + (long)hh * sCh2;
    Ah_g += aoff; Al_g += aoff; Bh_g += boff; Bl_g += boff;
    if (Cf)  Cf  += coff;
    if (Chi) { Chi += coff; Clo += coff; }
    if (hh != 0) bias = nullptr;

    const int m0 = blockIdx.y * TILE_M;
    const int n0 = blockIdx.x * 128;

    const int tid  = threadIdx.x;
    const int warp = tid >> 5;
    const int lane = tid & 31;
    const int grp  = lane >> 2;
    const int tig  = lane & 3;
    const int mbase = (warp >> 2) * (MTW * 16);
    const int nbase = (warp & 3) * 32;

    const uint32_t dynbase = smem_u32(smem_raw);

    float acc[MTW][4][4];
    #pragma unroll
    for (int i = 0; i < MTW; i++)
        #pragma unroll
        for (int j = 0; j < 4; j++)
            #pragma unroll
            for (int r = 0; r < 4; r++) acc[i][j][r] = 0.f;

    const int KT = K >> 5;

    auto load_stage = [&](int s, int kt) {
        const int k0 = kt << 5;
        const uint32_t sb = dynbase + s * STAGE;
        #pragma unroll
        for (int i = 0; i < NIT; i++) {
            int idx = tid + i * 256;
            if (idx < 2 * ACH) {
                int arr = idx / ACH;
                int rem = idx - arr * ACH;
                int row = rem >> 2;
                int c16 = rem & 3;
                uint32_t dst = sb + arr * A_BYTES + row * 80 + c16 * 16;
                const bf16* src = (arr ? Al_g : Ah_g)
                                + (long)(m0 + row) * lda + k0 + c16 * 8;
                cp_async16(dst, src, true);
            } else {
                int idxb = idx - 2 * ACH;
                int arr = idxb >> 9;
                int rem = idxb & 511;
                int row = rem >> 2;
                int c16 = rem & 3;
                uint32_t dst = sb + OFF_BH + arr * B_BYTES + row * 80 + c16 * 16;
                int nr = n0 + row;
                bool p = nr < N;
                const bf16* src = (arr ? Bl_g : Bh_g)
                                + (long)(p ? nr : 0) * ldb + k0 + c16 * 8;
                cp_async16(dst, src, p);
            }
        }
        asm volatile("cp.async.commit_group;\n");
    };

    load_stage(0, 0);

    const int a_row = mbase + (lane & 15);
    const int a_kof = (lane >> 4) << 3;
    const int b_row = nbase + ((lane >> 4) << 3) + (lane & 7);
    const int b_kof = ((lane >> 3) & 1) << 3;

    for (int kt = 0; kt < KT; kt++) {
        const int cur = kt & 1;
        if (kt + 1 < KT) {
            load_stage(cur ^ 1, kt + 1);
            asm volatile("cp.async.wait_group 1;\n");
        } else {
            asm volatile("cp.async.wait_group 0;\n");
        }
        __syncthreads();

        const uint32_t sA = dynbase + cur * STAGE;
        const uint32_t sB = sA + OFF_BH;

        #pragma unroll
        for (int kk = 0; kk < 2; kk++) {
            const int kc = kk * 16;
            uint32_t ah[MTW][4], al[MTW][4], bh[4][2], bl[4][2];

            const uint32_t aaddr = sA + (uint32_t)(a_row * 80 + (kc + a_kof) * 2);
            #pragma unroll
            for (int mt = 0; mt < MTW; mt++) {
                LDSM4(ah[mt][0], ah[mt][1], ah[mt][2], ah[mt][3], aaddr + mt * (16 * 80));
                LDSM4(al[mt][0], al[mt][1], al[mt][2], al[mt][3],
                      aaddr + A_BYTES + mt * (16 * 80));
            }
            const uint32_t baddr = sB + (uint32_t)(b_row * 80 + (kc + b_kof) * 2);
            #pragma unroll
            for (int p = 0; p < 2; p++) {
                LDSM4(bh[2*p][0], bh[2*p][1], bh[2*p+1][0], bh[2*p+1][1],
                      baddr + p * (16 * 80));
                LDSM4(bl[2*p][0], bl[2*p][1], bl[2*p+1][0], bl[2*p+1][1],
                      baddr + B_BYTES + p * (16 * 80));
            }

            #pragma unroll
            for (int mt = 0; mt < MTW; mt++) {
                #pragma unroll
                for (int nt = 0; nt < 4; nt++) {
                    float* c4 = acc[mt][nt];
                    MMA16816(c4, ah[mt][0], ah[mt][1], ah[mt][2], ah[mt][3],
                             bh[nt][0], bh[nt][1]);
                    MMA16816(c4, ah[mt][0], ah[mt][1], ah[mt][2], ah[mt][3],
                             bl[nt][0], bl[nt][1]);
                    MMA16816(c4, al[mt][0], al[mt][1], al[mt][2], al[mt][3],
                             bh[nt][0], bh[nt][1]);
                }
            }
        }
        __syncthreads();
    }

    // ---- epilogue ----
    #pragma unroll
    for (int mt = 0; mt < MTW; mt++) {
        #pragma unroll
        for (int nt = 0; nt < 4; nt++) {
            int nc = n0 + nbase + nt * 8 + 2 * tig;
            if (nc >= N) continue;
            float* c4 = acc[mt][nt];
            #pragma unroll
            for (int rr = 0; rr < 2; rr++) {
                int m = m0 + mbase + mt * 16 + grp + rr * 8;
                float v0 = c4[rr * 2], v1 = c4[rr * 2 + 1];
                if (bias) { v0 += bias[nc]; v1 += bias[nc + 1]; }
                if (epi == 1) { v0 = gelu_f(v0); v1 = gelu_f(v1); }
                long idx = (long)m * ldc + nc;
                if (epi == 2) {
                    float2 old = *(const float2*)&Cf[idx];
                    v0 += old.x; v1 += old.y;
                }
                if (Cf) *(float2*)&Cf[idx] = make_float2(v0, v1);
                if (Chi) {
                    bf16 h0, l0, h1, l1;
                    split_pair(v0, h0, l0);
                    split_pair(v1, h1, l1);
                    __nv_bfloat162 th = __halves2bfloat162(h0, h1);
                    __nv_bfloat162 tl = __halves2bfloat162(l0, l1);
                    *(uint32_t*)&Chi[idx] = *(uint32_t*)&th;
                    *(uint32_t*)&Clo[idx] = *(uint32_t*)&tl;
                }
            }
        }
    }
}

#define DYN_SMEM_M128 (2 * (2 * 128 * 80 + 2 * 128 * 80))   // 81920
#define DYN_SMEM_M64  (2 * (2 * 64 * 80 + 2 * 128 * 80))    // 61440

// =====================================================================
// Fused flash attention (champion config: K-block 128, 1 CTA/SM).
// =====================================================================
#define FQ_ROWB   144
#define FA_QL     18432
#define FA_ST0    36864
#define FA_ARR    18432
#define FA_STAGE  (4*FA_ARR)
#define FA_SMEM   (FA_ST0 + 2*FA_STAGE)   // 184320

__global__ __launch_bounds__(256, 1)
void flash_attn_kernel(const bf16* __restrict__ qkvh, const bf16* __restrict__ qkvl,
                       bf16* __restrict__ oh, bf16* __restrict__ ol)
{
    const int bh = blockIdx.y;
    const int b  = bh / NHEADS;
    const int h  = bh % NHEADS;
    const int q0 = blockIdx.x * 128;

    const int tid  = threadIdx.x;
    const int warp = tid >> 5;
    const int lane = tid & 31;
    const int qbase = warp * 16;

    const uint32_t dyn = smem_u32(smem_raw);

    const bf16* qh_g = qkvh + ((long)(b * NTOK + q0)) * (3 * CDIM) + h * HEADD;
    const bf16* ql_g = qkvl + ((long)(b * NTOK + q0)) * (3 * CDIM) + h * HEADD;

    #pragma unroll
    for (int i = 0; i < 8; i++) {
        int idx = tid + i * 256;
        int arr = idx >> 10;
        int rem = idx & 1023;
        int row = rem >> 3;
        int c   = rem & 7;
        uint32_t dst = dyn + arr * FA_QL + row * FQ_ROWB + c * 16;
        const bf16* src = (arr ? ql_g : qh_g) + (long)row * (3 * CDIM) + c * 8;
        cp_async16(dst, src, true);
    }

    auto load_kv = [&](int s, int j) {
        const long keybase = (long)(b * NTOK + j * 128);
        const uint32_t sb = dyn + FA_ST0 + s * FA_STAGE;
        #pragma unroll
        for (int i = 0; i < 16; i++) {
            int idx = tid + i * 256;
            int arr = idx >> 10;
            int rem = idx & 1023;
            int row = rem >> 3;
            int c   = rem & 7;
            uint32_t dst = sb + arr * FA_ARR + row * FQ_ROWB + c * 16;
            const bf16* base = ((arr & 1) ? qkvl : qkvh);
            int sect = (arr < 2) ? CDIM : 2 * CDIM;
            const bf16* src = base + (keybase + row) * (3 * CDIM) + sect + h * HEADD + c * 8;
            cp_async16(dst, src, true);
        }
        asm volatile("cp.async.commit_group;\n");
    };

    load_kv(0, 0);

    float o[8][4];
    #pragma unroll
    for (int i = 0; i < 8; i++)
        #pragma unroll
        for (int r = 0; r < 4; r++) o[i][r] = 0.f;
    float m_i[2] = { -1e30f, -1e30f };
    float l_i[2] = { 0.f, 0.f };

    uint32_t qh_f[4][4], ql_f[4][4];
    const int a_row = qbase + (lane & 15);
    const int a_kof = (lane >> 4) << 3;
    const int b_row = ((lane >> 4) << 3) + (lane & 7);
    const int b_kof = ((lane >> 3) & 1) << 3;
    const int v_row = (((lane >> 3) & 1) << 3) + (lane & 7);
    const int v_dof = (lane >> 4) << 3;

    for (int j = 0; j < 8; j++) {
        const int cur = j & 1;
        if (j + 1 < 8) {
            load_kv(cur ^ 1, j + 1);
            asm volatile("cp.async.wait_group 1;\n");
        } else {
            asm volatile("cp.async.wait_group 0;\n");
        }
        __syncthreads();

        if (j == 0) {
            #pragma unroll
            for (int kk = 0; kk < 4; kk++) {
                uint32_t qaddr = dyn + (uint32_t)(a_row * FQ_ROWB + (kk * 16 + a_kof) * 2);
                LDSM4(qh_f[kk][0], qh_f[kk][1], qh_f[kk][2], qh_f[kk][3], qaddr);
                LDSM4(ql_f[kk][0], ql_f[kk][1], ql_f[kk][2], ql_f[kk][3], qaddr + FA_QL);
            }
        }

        const uint32_t kb = dyn + FA_ST0 + cur * FA_STAGE;
        const uint32_t vb = kb + 2 * FA_ARR;

        float s[16][4];
        #pragma unroll
        for (int i = 0; i < 16; i++)
            #pragma unroll
            for (int r = 0; r < 4; r++) s[i][r] = 0.f;

        #pragma unroll
        for (int np = 0; np < 8; np++) {
            #pragma unroll
            for (int kk = 0; kk < 4; kk++) {
                uint32_t kaddr = kb + (uint32_t)((np * 16 + b_row) * FQ_ROWB
                                                 + (kk * 16 + b_kof) * 2);
                uint32_t kh0, kh1, kh2, kh3, kl0, kl1, kl2, kl3;
                LDSM4(kh0, kh1, kh2, kh3, kaddr);
                LDSM4(kl0, kl1, kl2, kl3, kaddr + FA_ARR);
                float* c0 = s[2*np];
                float* c1 = s[2*np+1];
                MMA16816(c0, qh_f[kk][0], qh_f[kk][1], qh_f[kk][2], qh_f[kk][3], kh0, kh1);
                MMA16816(c0, qh_f[kk][0], qh_f[kk][1], qh_f[kk][2], qh_f[kk][3], kl0, kl1);
                MMA16816(c0, ql_f[kk][0], ql_f[kk][1], ql_f[kk][2], ql_f[kk][3], kh0, kh1);
                MMA16816(c1, qh_f[kk][0], qh_f[kk][1], qh_f[kk][2], qh_f[kk][3], kh2, kh3);
                MMA16816(c1, qh_f[kk][0], qh_f[kk][1], qh_f[kk][2], qh_f[kk][3], kl2, kl3);
                MMA16816(c1, ql_f[kk][0], ql_f[kk][1], ql_f[kk][2], ql_f[kk][3], kh2, kh3);
            }
        }

        #pragma unroll
        for (int rr = 0; rr < 2; rr++) {
            float mx = -1e30f;
            #pragma unroll
            for (int nt = 0; nt < 16; nt++)
                mx = fmaxf(mx, fmaxf(s[nt][rr*2], s[nt][rr*2+1]));
            mx = fmaxf(mx, __shfl_xor_sync(~0u, mx, 1));
            mx = fmaxf(mx, __shfl_xor_sync(~0u, mx, 2));
            float m_new = fmaxf(m_i[rr], mx);
            float alpha = __expf(SCALE_F * (m_i[rr] - m_new));
            m_i[rr] = m_new;
            l_i[rr] *= alpha;
            float psum = 0.f;
            #pragma unroll
            for (int nt = 0; nt < 16; nt++) {
                float p0 = __expf(SCALE_F * (s[nt][rr*2]     - m_new));
                float p1 = __expf(SCALE_F * (s[nt][rr*2 + 1] - m_new));
                s[nt][rr*2]     = p0;
                s[nt][rr*2 + 1] = p1;
                psum += p0 + p1;
            }
            l_i[rr] += psum;
            #pragma unroll
            for (int nt = 0; nt < 8; nt++) {
                o[nt][rr*2]     *= alpha;
                o[nt][rr*2 + 1] *= alpha;
            }
        }

        #pragma unroll
        for (int ks = 0; ks < 8; ks++) {
            uint32_t pah[4], pal[4];
            #pragma unroll
            for (int q = 0; q < 4; q++) {
                int nt = 2 * ks + (q >> 1);
                int base = (q & 1) * 2;
                bf16 h0, l0, h1, l1;
                split_pair(s[nt][base],     h0, l0);
                split_pair(s[nt][base + 1], h1, l1);
                __nv_bfloat162 th = __halves2bfloat162(h0, h1);
                __nv_bfloat162 tl = __halves2bfloat162(l0, l1);
                pah[q] = *(uint32_t*)&th;
                pal[q] = *(uint32_t*)&tl;
            }
            #pragma unroll
            for (int np = 0; np < 4; np++) {
                uint32_t vaddr = vb + (uint32_t)((ks * 16 + v_row) * FQ_ROWB
                                                 + (np * 16 + v_dof) * 2);
                uint32_t vh0, vh1, vh2, vh3, vl0, vl1, vl2, vl3;
                LDSM4T(vh0, vh1, vh2, vh3, vaddr);
                LDSM4T(vl0, vl1, vl2, vl3, vaddr + FA_ARR);
                float* c0 = o[2*np];
                float* c1 = o[2*np+1];
                MMA16816(c0, pah[0], pah[1], pah[2], pah[3], vh0, vh1);
                MMA16816(c0, pah[0], pah[1], pah[2], pah[3], vl0, vl1);
                MMA16816(c0, pal[0], pal[1], pal[2], pal[3], vh0, vh1);
                MMA16816(c1, pah[0], pah[1], pah[2], pah[3], vh2, vh3);
                MMA16816(c1, pah[0], pah[1], pah[2], pah[3], vl2, vl3);
                MMA16816(c1, pal[0], pal[1], pal[2], pal[3], vh2, vh3);
            }
        }
        __syncthreads();
    }

    float inv[2];
    #pragma unroll
    for (int rr = 0; rr < 2; rr++) {
        float l = l_i[rr];
        l += __shfl_xor_sync(~0u, l, 1);
        l += __shfl_xor_sync(~0u, l, 2);
        inv[rr] = 1.f / l;
    }

    const int r = lane >> 2;
    const int t = lane & 3;
    #pragma unroll
    for (int nt = 0; nt < 8; nt++) {
        #pragma unroll
        for (int rr = 0; rr < 2; rr++) {
            int qr = q0 + qbase + r + rr * 8;
            float v0 = o[nt][rr*2]     * inv[rr];
            float v1 = o[nt][rr*2 + 1] * inv[rr];
            bf16 h0, l0, h1, l1;
            split_pair(v0, h0, l0);
            split_pair(v1, h1, l1);
            __nv_bfloat162 th = __halves2bfloat162(h0, h1);
            __nv_bfloat162 tl = __halves2bfloat162(l0, l1);
            long idx = ((long)(b * NTOK + qr)) * CDIM + h * HEADD + nt * 8 + 2 * t;
            *(uint32_t*)&oh[idx] = *(uint32_t*)&th;
            *(uint32_t*)&ol[idx] = *(uint32_t*)&tl;
        }
    }
}

// =====================================================================
// f32 -> bf16 hi/lo pair conversion, float4-vectorized
// =====================================================================
__global__ void cvt_pair4_kernel(const float* __restrict__ in,
                                 bf16* __restrict__ hi, bf16* __restrict__ lo, long n4)
{
    long i = (long)blockIdx.x * blockDim.x + threadIdx.x;
    if (i >= n4) return;
    float4 v = ((const float4*)in)[i];
    bf16 h[4], l[4];
    split_pair(v.x, h[0], l[0]); split_pair(v.y, h[1], l[1]);
    split_pair(v.z, h[2], l[2]); split_pair(v.w, h[3], l[3]);
    __nv_bfloat162 h01 = __halves2bfloat162(h[0], h[1]);
    __nv_bfloat162 h23 = __halves2bfloat162(h[2], h[3]);
    __nv_bfloat162 l01 = __halves2bfloat162(l[0], l[1]);
    __nv_bfloat162 l23 = __halves2bfloat162(l[2], l[3]);
    ((uint2*)hi)[i] = make_uint2(*(uint32_t*)&h01, *(uint32_t*)&h23);
    ((uint2*)lo)[i] = make_uint2(*(uint32_t*)&l01, *(uint32_t*)&l23);
}

// =====================================================================
// im2col producing bf16 pairs
// =====================================================================
__global__ void im2col_kernel(const float* __restrict__ x,
                              bf16* __restrict__ ch, bf16* __restrict__ cl)
{
    long idx = (long)blockIdx.x * blockDim.x + threadIdx.x;
    if (idx >= (long)MROWS * CDIM) return;
    int k = (int)(idx % CDIM);
    int m = (int)(idx / CDIM);
    int b  = m >> 10;
    int n  = m & 1023;
    int hp = n >> 5, wp = n & 31;
    int ci = k >> 8;
    int r  = k & 255;
    int ky = r >> 4, kx = r & 15;
    long src = (((long)(b * 3 + ci) * IMG) + hp * PS + ky) * IMG + wp * PS + kx;
    bf16 h, l; split_pair(x[src], h, l);
    ch[idx] = h; cl[idx] = l;
}

// =====================================================================
// LayerNorm producing bf16 pairs.
// COMBINE variant: in = gx + p0 + p1 (K-split partials), writes gx back.
// =====================================================================
template<bool COMBINE>
__global__ void layernorm_kernel(float* __restrict__ gx,
                                 const float* __restrict__ p0,
                                 const float* __restrict__ p1,
                                 bf16* __restrict__ oh, bf16* __restrict__ ol,
                                 const float* __restrict__ s, const float* __restrict__ b)
{
    __shared__ float red[8];
    const long row = blockIdx.x;
    int tid = threadIdx.x, lane = tid & 31, w = tid >> 5;

    float v[3];
    float sum = 0.f;
    #pragma unroll
    for (int j = 0; j < 3; j++) {
        long idx = row * CDIM + tid + j * 256;
        float t = gx[idx];
        if (COMBINE) {
            t += p0[idx] + p1[idx];
            gx[idx] = t;
        }
        v[j] = t; sum += t;
    }
    #pragma unroll
    for (int off = 16; off; off >>= 1) sum += __shfl_xor_sync(~0u, sum, off);
    if (lane == 0) red[w] = sum;
    __syncthreads();
    if (w == 0) {
        float t = (lane < 8) ? red[lane] : 0.f;
        #pragma unroll
        for (int off = 4; off; off >>= 1) t += __shfl_xor_sync(~0u, t, off);
        if (lane == 0) red[0] = t;
    }
    __syncthreads();
    float mu = red[0] * (1.f / CDIM);
    __syncthreads();

    float sq = 0.f;
    #pragma unroll
    for (int j = 0; j < 3; j++) { float d = v[j] - mu; sq += d * d; }
    #pragma unroll
    for (int off = 16; off; off >>= 1) sq += __shfl_xor_sync(~0u, sq, off);
    if (lane == 0) red[w] = sq;
    __syncthreads();
    if (w == 0) {
        float t = (lane < 8) ? red[lane] : 0.f;
        #pragma unroll
        for (int off = 4; off; off >>= 1) t += __shfl_xor_sync(~0u, t, off);
        if (lane == 0) red[0] = t;
    }
    __syncthreads();
    float rstd = rsqrtf(red[0] * (1.f / CDIM) + EPS_F);

    #pragma unroll
    for (int j = 0; j < 3; j++) {
        int c = tid + j * 256;
        float o = (v[j] - mu) * rstd * s[c] + b[c];
        bf16 h, l; split_pair(o, h, l);
        oh[row * CDIM + c] = h; ol[row * CDIM + c] = l;
    }
}

// =====================================================================
// Fused deformable attention: one warp per (b, h, n).
// =====================================================================
__global__ void deform_attn_kernel(const bf16* __restrict__ qkvh,
                                   const bf16* __restrict__ qkvl,
                                   const float* __restrict__ offs4,
                                   const float* __restrict__ offs_b,
                                   bf16* __restrict__ oh, bf16* __restrict__ ol)
{
    int gwarp = (blockIdx.x * blockDim.x + threadIdx.x) >> 5;
    int lane  = threadIdx.x & 31;
    if (gwarp >= BB * NHEADS * NTOK) return;
    int n  = gwarp & (NTOK - 1);
    int bh = gwarp >> 10;
    int h  = bh % NHEADS;
    int b  = bh / NHEADS;
    int hp = n >> 5, wp = n & 31;

    const long rowoff = ((long)(b * NTOK + n)) * (3 * CDIM) + h * HEADD + 2 * lane;
    float2 q = unpack_pair(*(const uint32_t*)&qkvh[rowoff],
                           *(const uint32_t*)&qkvl[rowoff]);

    const long offbase = ((long)(b * NTOK + n)) * 96 + h * NPTS * 2;
    const long CH = (long)MROWS * 96;

    float att[NPTS], sv0[NPTS], sv1[NPTS];

    #pragma unroll
    for (int p = 0; p < NPTS; p++) {
        long oidx = offbase + p * 2;
        float ox = offs4[oidx]            + offs4[oidx + CH]
                 + offs4[oidx + 2 * CH]   + offs4[oidx + 3 * CH]
                 + offs_b[h * NPTS * 2 + p * 2];
        float oy = offs4[oidx + 1]        + offs4[oidx + 1 + CH]
                 + offs4[oidx + 1 + 2*CH] + offs4[oidx + 1 + 3*CH]
                 + offs_b[h * NPTS * 2 + p * 2 + 1];
        float gx = (wp + 0.5f) * (1.f / HP) + ox * (1.f / HP);
        float gy = (hp + 0.5f) * (1.f / HP) + oy * (1.f / HP);
        float px = (2.f * gx) * (HP * 0.5f) - 0.5f;
        float py = (2.f * gy) * (HP * 0.5f) - 0.5f;
        float x0f = floorf(px), y0f = floorf(py);
        float wx = px - x0f, wy = py - y0f;
        int x0 = (int)x0f, y0 = (int)y0f;
        float cw[4] = { (1.f - wx) * (1.f - wy), wx * (1.f - wy),
                        (1.f - wx) * wy,         wx * wy };

        float k0 = 0.f, k1 = 0.f, v0 = 0.f, v1 = 0.f;
        #pragma unroll
        for (int c = 0; c < 4; c++) {
            int yi = y0 + (c >> 1);
            int xi = x0 + (c & 1);
            if (yi >= 0 && yi < HP && xi >= 0 && xi < HP) {
                long base = ((long)(b * NTOK + yi * HP + xi)) * (3 * CDIM)
                          + CDIM + h * HEADD + 2 * lane;
                float2 kv = unpack_pair(*(const uint32_t*)&qkvh[base],
                                        *(const uint32_t*)&qkvl[base]);
                float2 vv = unpack_pair(*(const uint32_t*)&qkvh[base + CDIM],
                                        *(const uint32_t*)&qkvl[base + CDIM]);
                float wc = cw[c];
                k0 += wc * kv.x;  k1 += wc * kv.y;
                v0 += wc * vv.x;  v1 += wc * vv.y;
            }
        }
        sv0[p] = v0; sv1[p] = v1;
        float d = q.x * k0 + q.y * k1;
        #pragma unroll
        for (int off = 16; off; off >>= 1) d += __shfl_xor_sync(~0u, d, off);
        att[p] = d * SCALE_F;
    }

    float mx = fmaxf(fmaxf(att[0], att[1]), fmaxf(att[2], att[3]));
    float e[NPTS], sum = 0.f;
    #pragma unroll
    for (int p = 0; p < NPTS; p++) { e[p] = __expf(att[p] - mx); sum += e[p]; }
    float inv = 1.f / sum;

    float o0 = 0.f, o1 = 0.f;
    #pragma unroll
    for (int p = 0; p < NPTS; p++) {
        float a = e[p] * inv;
        o0 += a * sv0[p];
        o1 += a * sv1[p];
    }
    long base = ((long)(b * NTOK + n)) * CDIM + h * HEADD + 2 * lane;
    bf16 h0, l0, h1, l1;
    split_pair(o0, h0, l0);
    split_pair(o1, h1, l1);
    __nv_bfloat162 th = __halves2bfloat162(h0, h1);
    __nv_bfloat162 tl = __halves2bfloat162(l0, l1);
    *(uint32_t*)&oh[base] = *(uint32_t*)&th;
    *(uint32_t*)&ol[base] = *(uint32_t*)&tl;
}

// =====================================================================
// Output transpose with fc2-partial combine: (B,N,C) -> (B,C,Hp,Wp)
// =====================================================================
__global__ void out_transpose_combine_kernel(const float* __restrict__ x,
                                             const float* __restrict__ p0,
                                             const float* __restrict__ p1,
                                             float* __restrict__ out)
{
    long idx = (long)blockIdx.x * blockDim.x + threadIdx.x;
    if (idx >= (long)MROWS * CDIM) return;
    int n = (int)(idx % NTOK);
    int c = (int)((idx / NTOK) % CDIM);
    int b = (int)(idx / ((long)NTOK * CDIM));
    long src = ((long)(b * NTOK + n)) * CDIM + c;
    out[idx] = x[src] + p0[src] + p1[src];
}

// =====================================================================
// Host launcher
// =====================================================================
extern "C" void kernel_launch(void* const* d_in, const int* in_sizes, int n_in,
                              void* d_out, int out_size)
{
    const float* x       = (const float*)d_in[0];
    const float* patch_w = (const float*)d_in[1];
    const float* patch_b = (const float*)d_in[2];
    const float* ln1_s   = (const float*)d_in[3];
    const float* ln1_b   = (const float*)d_in[4];
    const float* qkv_w   = (const float*)d_in[5];
    const float* offs_w  = (const float*)d_in[6];
    const float* offs_b  = (const float*)d_in[7];
    const float* proj_w  = (const float*)d_in[8];
    const float* proj_b  = (const float*)d_in[9];
    const float* ln2_s   = (const float*)d_in[10];
    const float* ln2_b   = (const float*)d_in[11];
    const float* fc1_w   = (const float*)d_in[12];
    const float* fc1_b   = (const float*)d_in[13];
    const float* fc2_w   = (const float*)d_in[14];
    const float* fc2_b   = (const float*)d_in[15];

    cudaFuncSetAttribute(mma_gemm_kernel<4>,
                         cudaFuncAttributeMaxDynamicSharedMemorySize, DYN_SMEM_M128);
    cudaFuncSetAttribute(mma_gemm_kernel<2>,
                         cudaFuncAttributeMaxDynamicSharedMemorySize, DYN_SMEM_M64);
    cudaFuncSetAttribute(flash_attn_kernel,
                         cudaFuncAttributeMaxDynamicSharedMemorySize, FA_SMEM);

    float *gx, *goffs4, *gf2p;
    bf16 *ghh,*ghl,*gcolh,*gcoll,*gqkvh,*gqkvl,*gaoh,*gaol;
    bf16 *gmlph,*gmlpl;
    bf16 *pwh,*pwl,*qwh,*qwl,*owh,*owl,*jwh,*jwl,*f1h,*f1l,*f2h,*f2l;
    cudaGetSymbolAddress((void**)&gx,     g_x);
    cudaGetSymbolAddress((void**)&goffs4, g_offs4);
    cudaGetSymbolAddress((void**)&gf2p,   g_f2p);
    cudaGetSymbolAddress((void**)&ghh,   g_hh);   cudaGetSymbolAddress((void**)&ghl,   g_hl);
    cudaGetSymbolAddress((void**)&gcolh, g_colh); cudaGetSymbolAddress((void**)&gcoll, g_coll);
    cudaGetSymbolAddress((void**)&gqkvh, g_qkvh); cudaGetSymbolAddress((void**)&gqkvl, g_qkvl);
    cudaGetSymbolAddress((void**)&gaoh,  g_aoh);  cudaGetSymbolAddress((void**)&gaol,  g_aol);
    cudaGetSymbolAddress((void**)&gmlph, g_mlph); cudaGetSymbolAddress((void**)&gmlpl, g_mlpl);
    cudaGetSymbolAddress((void**)&pwh, g_pwh); cudaGetSymbolAddress((void**)&pwl, g_pwl);
    cudaGetSymbolAddress((void**)&qwh, g_qwh); cudaGetSymbolAddress((void**)&qwl, g_qwl);
    cudaGetSymbolAddress((void**)&owh, g_owh); cudaGetSymbolAddress((void**)&owl, g_owl);
    cudaGetSymbolAddress((void**)&jwh, g_jwh); cudaGetSymbolAddress((void**)&jwl, g_jwl);
    cudaGetSymbolAddress((void**)&f1h, g_f1h); cudaGetSymbolAddress((void**)&f1l, g_f1l);
    cudaGetSymbolAddress((void**)&f2h, g_f2h); cudaGetSymbolAddress((void**)&f2l, g_f2l);

    const int M = MROWS;
    float* gf2p1 = gf2p + (long)MROWS * CDIM;

    // ---- weight conversion (vectorized) ----
    {
        long n1 = (long)CDIM * CDIM / 4;
        cvt_pair4_kernel<<<(int)((n1 + 255) / 256), 256>>>(patch_w, pwh, pwl, n1);
        long n2 = 6L * 3 * CDIM * CDIM / 4;
        cvt_pair4_kernel<<<(int)((n2 + 255) / 256), 256>>>(qkv_w, qwh, qwl, n2);
        long n3 = 6L * 96 * CDIM / 4;
        cvt_pair4_kernel<<<(int)((n3 + 255) / 256), 256>>>(offs_w, owh, owl, n3);
        long n4 = 6L * CDIM * CDIM / 4;
        cvt_pair4_kernel<<<(int)((n4 + 255) / 256), 256>>>(proj_w, jwh, jwl, n4);
        long n5 = 6L * 4 * CDIM * CDIM / 4;
        cvt_pair4_kernel<<<(int)((n5 + 255) / 256), 256>>>(fc1_w, f1h, f1l, n5);
        cvt_pair4_kernel<<<(int)((n5 + 255) / 256), 256>>>(fc2_w, f2h, f2l, n5);
    }

    // ---- patch embed (M64: 192 CTAs) ----
    im2col_kernel<<<(M * CDIM + 255) / 256, 256>>>(x, gcolh, gcoll);
    mma_gemm_kernel<2><<<dim3(6, M / 64, 1), 256, DYN_SMEM_M64>>>(
        gcolh, gcoll, pwh, pwl, gx, nullptr, nullptr, patch_b,
        M, CDIM, CDIM, CDIM, CDIM, CDIM,
        0, 0, 0, 0, 0, 0, 1, 0);

    for (int i = 0; i < 6; i++) {
        // LN1: layer 0 reads plain gx; layers >=1 fold in fc2 partials, update gx
        if (i == 0)
            layernorm_kernel<false><<<M, 256>>>(gx, nullptr, nullptr, ghh, ghl,
                                                ln1_s + i * CDIM, ln1_b + i * CDIM);
        else
            layernorm_kernel<true><<<M, 256>>>(gx, gf2p, gf2p1, ghh, ghl,
                                               ln1_s + i * CDIM, ln1_b + i * CDIM);

        // QKV (M128: 288 CTAs)
        mma_gemm_kernel<4><<<dim3(18, M / 128, 1), 256, DYN_SMEM_M128>>>(
            ghh, ghl, qwh + (long)i * 2304 * CDIM, qwl + (long)i * 2304 * CDIM,
            nullptr, gqkvh, gqkvl, nullptr,
            M, 2304, CDIM, CDIM, CDIM, 2304,
            0, 0, 0, 0, 0, 0, 1, 0);

        bool sample = ((i + 1) % 3) != 0;
        if (sample) {
            // offsets: K-split x4 (128 CTAs)
            mma_gemm_kernel<2><<<dim3(1, M / 64, KSPLIT), 256, DYN_SMEM_M64>>>(
                gqkvh, gqkvl, owh + (long)i * 96 * CDIM, owl + (long)i * 96 * CDIM,
                goffs4, nullptr, nullptr, nullptr,
                M, 96, CDIM / KSPLIT, 3 * CDIM, CDIM, 96,
                0, CDIM / KSPLIT,
                0, CDIM / KSPLIT,
                0, (long)MROWS * 96,
                KSPLIT, 0);
            deform_attn_kernel<<<(BB * NHEADS * NTOK * 32) / 256, 256>>>(
                gqkvh, gqkvl, goffs4, offs_b + i * 96, gaoh, gaol);
        } else {
            flash_attn_kernel<<<dim3(NTOK / 128, BB * NHEADS, 1), 256, FA_SMEM>>>(
                gqkvh, gqkvl, gaoh, gaol);
        }

        // proj: K-split x2 (384 CTAs) into partials (bias on chunk 0);
        // combined into gx (residual) by LN2's COMBINE pass
        mma_gemm_kernel<2><<<dim3(6, M / 64, 2), 256, DYN_SMEM_M64>>>(
            gaoh, gaol, jwh + (long)i * CDIM * CDIM, jwl + (long)i * CDIM * CDIM,
            gf2p, nullptr, nullptr, proj_b + i * CDIM,
            M, CDIM, CDIM / 2, CDIM, CDIM, CDIM,
            0, CDIM / 2,
            0, CDIM / 2,
            0, (long)MROWS * CDIM,
            2, 0);

        // LN2: combine proj partials into gx, emit normalized pairs
        layernorm_kernel<true><<<M, 256>>>(gx, gf2p, gf2p1, ghh, ghl,
                                           ln2_s + i * CDIM, ln2_b + i * CDIM);

        // fc1 + gelu (M128: 384 CTAs)
        mma_gemm_kernel<4><<<dim3(24, M / 128, 1), 256, DYN_SMEM_M128>>>(
            ghh, ghl, f1h + (long)i * 3072 * CDIM, f1l + (long)i * 3072 * CDIM,
            nullptr, gmlph, gmlpl, fc1_b + i * 3072,
            M, 3072, CDIM, CDIM, CDIM, 3072,
            0, 0, 0, 0, 0, 0, 1, 1);

        // fc2: K-split x2 (384 CTAs) into partials; bias on chunk 0;
        // combined into gx by next LN1 (or final transpose for layer 5)
        mma_gemm_kernel<2><<<dim3(6, M / 64, 2), 256, DYN_SMEM_M64>>>(
            gmlph, gmlpl, f2h + (long)i * CDIM * 3072, f2l + (long)i * CDIM * 3072,
            gf2p, nullptr, nullptr, fc2_b + i * CDIM,
            M, CDIM, 3072 / 2, 3072, 3072, CDIM,
            0, 3072 / 2,
            0, 3072 / 2,
            0, (long)MROWS * CDIM,
            2, 0);
    }

    out_transpose_combine_kernel<<<(M * CDIM + 255) / 256, 256>>>(
        gx, gf2p, gf2p1, (float*)d_out);
}